// round 13
// baseline (speedup 1.0000x reference)
#include <cuda_runtime.h>
#include <cuda_bf16.h>
#include <cuda_fp16.h>
#include <math.h>

// ---------------------------------------------------------------------------
// Problem constants
// ---------------------------------------------------------------------------
#define BB 2
#define TT 2048
#define DD 1024
#define HH 16
#define DH 64
#define NTOK (BB*TT)            // 4096
#define EE 16
#define KK 2
#define FF 2048
#define CAP 640
#define DP 256
#define NPRIM 512
#define NFLAT (NTOK*KK)         // 8192

// ---------------------------------------------------------------------------
// Scratch (device globals; no allocation allowed)
// ---------------------------------------------------------------------------
__device__ float g_x[NTOK*DD];
__device__ float g_logits[NTOK*EE];
__device__ float g_probs[NTOK*EE];
__device__ int   g_topi[NFLAT];
__device__ float g_topw[NFLAT];
__device__ int   g_slot[NFLAT];
__device__ int   g_keep[NFLAT];
__device__ float g_wcomb[NFLAT];
__device__ int   g_counts[EE];
__device__ float g_pmean[EE];
__device__ float g_yb[EE*CAP*DD];
__device__ float g_tl[NTOK*NPRIM];
__device__ float g_gate[NTOK];
__device__ float g_ropec[TT*32];
__device__ float g_ropes[TT*32];

// fp16 buffers
__device__ __half gh_qkv[NTOK*3*DD];
__device__ __half gh_xn[NTOK*DD];
__device__ __half gh_attn[NTOK*DD];
__device__ __half gh_buf[EE*CAP*DD];
__device__ __half gh_h[EE*CAP*FF];
__device__ __half gh_tq[NTOK*DP];
__device__ __half gh_tk[NPRIM*DP];
__device__ __half gh_tv[NPRIM*DP];
__device__ __half gh_tl[NTOK*NPRIM];
__device__ __half gh_tout[NTOK*DP];
// fp16 weights (converted once per launch)
__device__ __half gh_qkvw[3*DD*DD];
__device__ __half gh_aow[DD*DD];
__device__ __half gh_w1[EE*DD*FF];
__device__ __half gh_w2[EE*FF*DD];
__device__ __half gh_tqw[DP*DD];
__device__ __half gh_tkw[DP*DP];
__device__ __half gh_tvw[DP*DP];
__device__ __half gh_tow[DD*DP];
__device__ __half gh_emb[NPRIM*DP];

// ---------------------------------------------------------------------------
// Streams / events (host resources, created once)
// ---------------------------------------------------------------------------
static cudaStream_t s1, s2;
static cudaEvent_t ev_root, ev_tab, ev_s1, ev_s2, ev_qkvw, ev_aow, ev_top2, ev_pm;
namespace {
struct InitOnce {
    InitOnce() {
        cudaStreamCreateWithFlags(&s1, cudaStreamNonBlocking);
        cudaStreamCreateWithFlags(&s2, cudaStreamNonBlocking);
        cudaEventCreateWithFlags(&ev_root, cudaEventDisableTiming);
        cudaEventCreateWithFlags(&ev_tab,  cudaEventDisableTiming);
        cudaEventCreateWithFlags(&ev_s1,   cudaEventDisableTiming);
        cudaEventCreateWithFlags(&ev_s2,   cudaEventDisableTiming);
        cudaEventCreateWithFlags(&ev_qkvw, cudaEventDisableTiming);
        cudaEventCreateWithFlags(&ev_aow,  cudaEventDisableTiming);
        cudaEventCreateWithFlags(&ev_top2, cudaEventDisableTiming);
        cudaEventCreateWithFlags(&ev_pm,   cudaEventDisableTiming);
    }
};
static InitOnce init_once_;
}

// ---------------------------------------------------------------------------
// MMA / cp.async / ldmatrix helpers
// ---------------------------------------------------------------------------
__device__ __forceinline__ void mma_f16(float c[4], const unsigned a[4], const unsigned b[2])
{
    asm volatile(
        "mma.sync.aligned.m16n8k16.row.col.f32.f16.f16.f32 "
        "{%0,%1,%2,%3},{%4,%5,%6,%7},{%8,%9},{%0,%1,%2,%3};"
        : "+f"(c[0]), "+f"(c[1]), "+f"(c[2]), "+f"(c[3])
        : "r"(a[0]), "r"(a[1]), "r"(a[2]), "r"(a[3]),
          "r"(b[0]), "r"(b[1]));
}

__device__ __forceinline__ void ldsm4(unsigned r[4], unsigned addr)
{
    asm volatile("ldmatrix.sync.aligned.m8n8.x4.shared.b16 {%0,%1,%2,%3}, [%4];"
        : "=r"(r[0]), "=r"(r[1]), "=r"(r[2]), "=r"(r[3]) : "r"(addr));
}
__device__ __forceinline__ void ldsm4t(unsigned r[4], unsigned addr)
{
    asm volatile("ldmatrix.sync.aligned.m8n8.x4.trans.shared.b16 {%0,%1,%2,%3}, [%4];"
        : "=r"(r[0]), "=r"(r[1]), "=r"(r[2]), "=r"(r[3]) : "r"(addr));
}

__device__ __forceinline__ void cp16(void* smem_dst, const void* gptr)
{
    unsigned saddr = (unsigned)__cvta_generic_to_shared(smem_dst);
    asm volatile("cp.async.cg.shared.global [%0], [%1], 16;\n"
                 :: "r"(saddr), "l"(gptr));
}
__device__ __forceinline__ void cp_commit()  { asm volatile("cp.async.commit_group;\n"); }
__device__ __forceinline__ void cp_wait2()   { asm volatile("cp.async.wait_group 2;\n"); }
__device__ __forceinline__ void cp_wait1()   { asm volatile("cp.async.wait_group 1;\n"); }
__device__ __forceinline__ void cp_wait0()   { asm volatile("cp.async.wait_group 0;\n"); }

// ---------------------------------------------------------------------------
// f32 -> f16 conversion (n % 2048 == 0)
// ---------------------------------------------------------------------------
__global__ void f2h_kernel(const float* __restrict__ in, __half* __restrict__ out)
{
    int i = (blockIdx.x*256 + threadIdx.x) * 8;
    float4 v0 = *(const float4*)(in + i);
    float4 v1 = *(const float4*)(in + i + 4);
    __half2* o = (__half2*)(out + i);
    o[0] = __floats2half2_rn(v0.x, v0.y);
    o[1] = __floats2half2_rn(v0.z, v0.w);
    o[2] = __floats2half2_rn(v1.x, v1.y);
    o[3] = __floats2half2_rn(v1.z, v1.w);
}

// ---------------------------------------------------------------------------
// RMSNorm: one block per token; fp16 out
// ---------------------------------------------------------------------------
__global__ void rmsnorm_h(const float* __restrict__ x,
                          const float* __restrict__ w,
                          __half* __restrict__ outh)
{
    int n = blockIdx.x;
    int tid = threadIdx.x;
    const float4* xp = (const float4*)(x + (size_t)n*DD);
    float4 xv = xp[tid];
    float ss = xv.x*xv.x + xv.y*xv.y + xv.z*xv.z + xv.w*xv.w;
    __shared__ float red[256];
    red[tid] = ss;
    __syncthreads();
    for (int s = 128; s; s >>= 1) {
        if (tid < s) red[tid] += red[tid+s];
        __syncthreads();
    }
    float scale = rsqrtf(red[0] / (float)DD + 1e-6f);
    const float4* wp = (const float4*)w;
    float4 wv = wp[tid];
    __half2* oh = (__half2*)(outh + (size_t)n*DD);
    oh[2*tid]   = __floats2half2_rn(xv.x*scale*wv.x, xv.y*scale*wv.y);
    oh[2*tid+1] = __floats2half2_rn(xv.z*scale*wv.z, xv.w*scale*wv.w);
}

// ---------------------------------------------------------------------------
// Fused RMSNorm + router logits: one block per token.
// Writes fp16 xn and 16 fp32 logits (fp32 math throughout).
// ---------------------------------------------------------------------------
__global__ void rmsnorm_router(const float* __restrict__ x,
                               const float* __restrict__ w,
                               __half* __restrict__ outh,
                               const float* __restrict__ rw,
                               float* __restrict__ logits)
{
    int n = blockIdx.x;
    int tid = threadIdx.x;
    int lane = tid & 31, warp = tid >> 5;
    const float4* xp = (const float4*)(x + (size_t)n*DD);
    float4 xv = xp[tid];
    float ss = xv.x*xv.x + xv.y*xv.y + xv.z*xv.z + xv.w*xv.w;
    __shared__ float red[256];
    red[tid] = ss;
    __syncthreads();
    for (int s = 128; s; s >>= 1) {
        if (tid < s) red[tid] += red[tid+s];
        __syncthreads();
    }
    float scale = rsqrtf(red[0] / (float)DD + 1e-6f);
    float4 wv = ((const float4*)w)[tid];
    float a = xv.x*scale*wv.x, b = xv.y*scale*wv.y;
    float c = xv.z*scale*wv.z, d = xv.w*scale*wv.w;
    __half2* oh = (__half2*)(outh + (size_t)n*DD);
    oh[2*tid]   = __floats2half2_rn(a, b);
    oh[2*tid+1] = __floats2half2_rn(c, d);

    __shared__ float part[EE][8];
    #pragma unroll
    for (int e = 0; e < EE; e++) {
        float4 rv = ((const float4*)(rw + (size_t)e*DD))[tid];
        float p = a*rv.x + b*rv.y + c*rv.z + d*rv.w;
        #pragma unroll
        for (int off = 16; off; off >>= 1) p += __shfl_xor_sync(0xffffffffu, p, off);
        if (lane == 0) part[e][warp] = p;
    }
    __syncthreads();
    if (tid < EE) {
        float s = 0.f;
        #pragma unroll
        for (int w8 = 0; w8 < 8; w8++) s += part[tid][w8];
        logits[n*EE + tid] = s;
    }
}

// ---------------------------------------------------------------------------
// Fused gather + RMSNorm3 + gate: one block per token.
// x += expert mix (written back); hxn = rmsnorm(x)*w; gate = sigmoid(xn.gw+gb)
// ---------------------------------------------------------------------------
__global__ void gather_ng(const int* __restrict__ topi,
                          const int* __restrict__ slot,
                          const float* __restrict__ wcomb,
                          const float* __restrict__ yb,
                          float* __restrict__ x,
                          const float* __restrict__ nw,
                          const float* __restrict__ gw,
                          const float* __restrict__ gb,
                          __half* __restrict__ outh,
                          float* __restrict__ gate)
{
    int n = blockIdx.x;
    int tid = threadIdx.x;
    float4* xp = (float4*)(x + (size_t)n*DD);
    float4 a = xp[tid];
    #pragma unroll
    for (int k = 0; k < 2; k++) {
        int i = n*2 + k;
        float w = wcomb[i];
        if (w != 0.f) {
            int e = topi[i], s = slot[i];
            const float4* yp = (const float4*)(yb + ((size_t)e*CAP + s)*DD);
            float4 yv = yp[tid];
            a.x += w*yv.x; a.y += w*yv.y; a.z += w*yv.z; a.w += w*yv.w;
        }
    }
    xp[tid] = a;

    // rmsnorm
    float ss = a.x*a.x + a.y*a.y + a.z*a.z + a.w*a.w;
    __shared__ float red[256];
    red[tid] = ss;
    __syncthreads();
    for (int s = 128; s; s >>= 1) {
        if (tid < s) red[tid] += red[tid+s];
        __syncthreads();
    }
    float scale = rsqrtf(red[0] / (float)DD + 1e-6f);
    float4 wv = ((const float4*)nw)[tid];
    float va = a.x*scale*wv.x, vb = a.y*scale*wv.y;
    float vc = a.z*scale*wv.z, vd = a.w*scale*wv.w;
    __half2* oh = (__half2*)(outh + (size_t)n*DD);
    oh[2*tid]   = __floats2half2_rn(va, vb);
    oh[2*tid+1] = __floats2half2_rn(vc, vd);

    // gate
    float4 gv = ((const float4*)gw)[tid];
    float p = va*gv.x + vb*gv.y + vc*gv.z + vd*gv.w;
    __syncthreads();
    red[tid] = p;
    __syncthreads();
    for (int s = 128; s; s >>= 1) {
        if (tid < s) red[tid] += red[tid+s];
        __syncthreads();
    }
    if (tid == 0) gate[n] = 1.f / (1.f + __expf(-(red[0] + gb[0])));
}

// ---------------------------------------------------------------------------
// FP16 tensor-core GEMM (m16n8k16): 4-stage cp.async, ldmatrix fragments.
// ---------------------------------------------------------------------------
#define AH_STR 40
#define BH_STR 136
#define NSTG 4
#define AH_TILE (128*AH_STR)
#define BH_TILE (32*BH_STR)

template<bool BT, int EPI, bool OUTH>
__global__ __launch_bounds__(256, 2)
void gemm_h(const __half* __restrict__ A, const __half* __restrict__ Bm,
            void* __restrict__ Cv, int M, int N, int K,
            long long sA, long long sB, long long sC,
            const float* __restrict__ gate, const float* __restrict__ Xin)
{
    A  += blockIdx.z * sA;
    Bm += blockIdx.z * sB;

    extern __shared__ __half smem_h[];
    __half* AsP = smem_h;
    __half* BsP = smem_h + NSTG*AH_TILE;
    const unsigned sbase = (unsigned)__cvta_generic_to_shared(smem_h);
    const unsigned bbase = sbase + NSTG*AH_TILE*2;

    const int tid  = threadIdx.x;
    const int lane = tid & 31;
    const int warp = tid >> 5;
    const int lr   = lane >> 2;
    const int lq   = lane & 3;
    const int g    = lane >> 3;
    const int tr   = lane & 7;
    const int wm   = warp & 1, wn = warp >> 1;
    const int m0   = wm * 64, n0 = wn * 32;
    const int row0 = blockIdx.y * 128, col0 = blockIdx.x * 128;

    const int c0i = tid, c1i = tid + 256;
    const int ar0 = c0i >> 2, ac0 = (c0i & 3) * 8;
    const int ar1 = c1i >> 2, ac1 = (c1i & 3) * 8;
    const int fr0 = c0i >> 4, fo0 = (c0i & 15) * 8;
    const int fr1 = c1i >> 4, fo1 = (c1i & 15) * 8;

    const int nIter = K >> 5;

    auto issue = [&](int stg, int k0) {
        cp16(&AsP[stg*AH_TILE + ar0*AH_STR + ac0], A + (size_t)(row0 + ar0) * K + k0 + ac0);
        cp16(&AsP[stg*AH_TILE + ar1*AH_STR + ac1], A + (size_t)(row0 + ar1) * K + k0 + ac1);
        if constexpr (BT) {
            cp16(&BsP[stg*AH_TILE + ar0*AH_STR + ac0], Bm + (size_t)(col0 + ar0) * K + k0 + ac0);
            cp16(&BsP[stg*AH_TILE + ar1*AH_STR + ac1], Bm + (size_t)(col0 + ar1) * K + k0 + ac1);
        } else {
            cp16(&BsP[stg*BH_TILE + fr0*BH_STR + fo0], Bm + (size_t)(k0 + fr0) * N + col0 + fo0);
            cp16(&BsP[stg*BH_TILE + fr1*BH_STR + fo1], Bm + (size_t)(k0 + fr1) * N + col0 + fo1);
        }
        cp_commit();
    };

    issue(0, 0);
    if (nIter > 1) issue(1, 32);
    if (nIter > 2) issue(2, 64);

    float c[4][4][4];
    #pragma unroll
    for (int mt = 0; mt < 4; mt++)
        #pragma unroll
        for (int nt = 0; nt < 4; nt++)
            #pragma unroll
            for (int i = 0; i < 4; i++) c[mt][nt][i] = 0.f;

    const int a_row = (g & 1) * 8 + tr;
    const int a_col = (g >> 1) * 8;
    const int bt_row = (g >> 1) * 8 + tr;
    const int bt_col = (g & 1) * 8;
    const int bf_row = (g & 1) * 8 + tr;
    const int bf_col = (g >> 1) * 8;

    for (int it = 0; it < nIter; it++) {
        if (it + 2 < nIter)      cp_wait2();
        else if (it + 1 < nIter) cp_wait1();
        else                     cp_wait0();
        __syncthreads();

        if (it + 3 < nIter) issue((it + 3) & 3, (it + 3) << 5);

        const int st = it & 3;
        const unsigned abase = sbase + st*AH_TILE*2;
        const unsigned btb   = bbase + (BT ? st*AH_TILE*2 : st*BH_TILE*2);

        #pragma unroll
        for (int ks = 0; ks < 2; ks++) {
            const int kb = ks * 16;
            unsigned a[4][4];
            #pragma unroll
            for (int mt = 0; mt < 4; mt++) {
                unsigned addr = abase + ((m0 + mt*16 + a_row)*AH_STR + kb + a_col)*2;
                ldsm4(a[mt], addr);
            }
            unsigned b[4][2];
            #pragma unroll
            for (int ntp = 0; ntp < 2; ntp++) {
                unsigned r[4];
                if constexpr (BT) {
                    unsigned addr = btb + ((n0 + ntp*16 + bt_row)*AH_STR + kb + bt_col)*2;
                    ldsm4(r, addr);
                } else {
                    unsigned addr = btb + ((kb + bf_row)*BH_STR + n0 + ntp*16 + bf_col)*2;
                    ldsm4t(r, addr);
                }
                b[ntp*2][0]   = r[0]; b[ntp*2][1]   = r[1];
                b[ntp*2+1][0] = r[2]; b[ntp*2+1][1] = r[3];
            }
            #pragma unroll
            for (int mt = 0; mt < 4; mt++)
                #pragma unroll
                for (int nt = 0; nt < 4; nt++)
                    mma_f16(c[mt][nt], a[mt], b[nt]);
        }
    }

    float* Cf = (float*)Cv + (OUTH ? 0 : blockIdx.z * sC);
    __half* Ch = (__half*)Cv + (OUTH ? blockIdx.z * sC : 0);
    #pragma unroll
    for (int mt = 0; mt < 4; mt++) {
        int r0g = row0 + m0 + mt * 16 + lr;
        int r1g = r0g + 8;
        float g0 = (EPI == 5) ? gate[r0g] : 0.f;
        float g1 = (EPI == 5) ? gate[r1g] : 0.f;
        #pragma unroll
        for (int nt = 0; nt < 4; nt++) {
            int cg = col0 + n0 + nt * 8 + 2 * lq;
            size_t i0 = (size_t)r0g * N + cg;
            size_t i1 = (size_t)r1g * N + cg;
            float v0 = c[mt][nt][0], v1 = c[mt][nt][1];
            float v2 = c[mt][nt][2], v3 = c[mt][nt][3];
            if (EPI == 2) {
                v0 = v0 / (1.f + __expf(-v0));
                v1 = v1 / (1.f + __expf(-v1));
                v2 = v2 / (1.f + __expf(-v2));
                v3 = v3 / (1.f + __expf(-v3));
            } else if (EPI == 4) {
                float2 x0 = *(const float2*)&Xin[i0];
                float2 x1 = *(const float2*)&Xin[i1];
                v0 += x0.x; v1 += x0.y; v2 += x1.x; v3 += x1.y;
            } else if (EPI == 5) {
                float2 x0 = *(const float2*)&Xin[i0];
                float2 x1 = *(const float2*)&Xin[i1];
                v0 = x0.x + g0*v0; v1 = x0.y + g0*v1;
                v2 = x1.x + g1*v2; v3 = x1.y + g1*v3;
            }
            if (OUTH) {
                *(__half2*)&Ch[i0] = __floats2half2_rn(v0, v1);
                *(__half2*)&Ch[i1] = __floats2half2_rn(v2, v3);
            } else {
                *(float2*)&Cf[i0] = make_float2(v0, v1);
                *(float2*)&Cf[i1] = make_float2(v2, v3);
            }
        }
    }
}

#define SMEM_HBT ((NSTG*AH_TILE + NSTG*AH_TILE) * 2)
#define SMEM_HKN ((NSTG*AH_TILE + NSTG*BH_TILE) * 2)

// ---------------------------------------------------------------------------
// RoPE table + in-place fp16 apply
// ---------------------------------------------------------------------------
__global__ void rope_table_kernel()
{
    int idx = blockIdx.x * 256 + threadIdx.x;
    int t = idx >> 5, i = idx & 31;
    float inv = powf(10000.f, -(float)i / 32.f);
    float s, c;
    sincosf((float)t * inv, &s, &c);
    g_ropec[idx] = c;
    g_ropes[idx] = s;
}

__global__ void rope_hh(__half* __restrict__ qkvh)
{
    int n = blockIdx.x;
    int t = n & (TT-1);
    for (int p = threadIdx.x; p < 1024; p += 256) {
        int which = p >> 9;
        int rem = p & 511;
        int h = rem >> 5;
        int i = rem & 31;
        float c = g_ropec[t*32 + i];
        float s = g_ropes[t*32 + i];
        size_t base = (size_t)n*3072 + (size_t)which*1024 + h*64 + i;
        float u1 = __half2float(qkvh[base]);
        float u2 = __half2float(qkvh[base+32]);
        qkvh[base]    = __float2half_rn(u1*c - u2*s);
        qkvh[base+32] = __float2half_rn(u2*c + u1*s);
    }
}

// ---------------------------------------------------------------------------
// Flash attention FP16 (unchanged from R9)
// ---------------------------------------------------------------------------
#define QH_STR 72
#define KH_STR 72
#define VH_STR 72
#define PH_STR 40
#define QH_OFF 0
#define KH_OFF (128*QH_STR)
#define VH_OFF (KH_OFF + 3*32*KH_STR)
#define PH_OFF (VH_OFF + 3*32*VH_STR)
#define FLASHH_SMEM ((PH_OFF + 128*PH_STR) * 2)

__global__ __launch_bounds__(256)
void flash_attn_h(const __half* __restrict__ qkv, __half* __restrict__ out)
{
    extern __shared__ __half fsm_h[];
    __half* Qs = fsm_h + QH_OFF;
    __half* Ks = fsm_h + KH_OFF;
    __half* Vs = fsm_h + VH_OFF;
    __half* Ps = fsm_h + PH_OFF;
    const unsigned smem0 = (unsigned)__cvta_generic_to_shared(fsm_h);

    const int qb = blockIdx.x, bh = blockIdx.y;
    const int b = bh >> 4, h = bh & 15;
    const int tid = threadIdx.x, lane = tid & 31, warp = tid >> 5;
    const int lr = lane >> 2, lq = lane & 3;
    const int g = lane >> 3, tr = lane & 7;
    const int m0 = warp * 16;
    const int q0 = qb * 128;
    const int ntiles = 4*qb + 4;

    #pragma unroll
    for (int c = tid; c < 1024; c += 256) {
        int r = c >> 3, off = (c & 7) * 8;
        cp16(&Qs[r*QH_STR + off], qkv + (size_t)(b*TT + q0 + r)*3072 + h*64 + off);
    }

    auto load_tile = [&](int kb, int buf) {
        __half* Kb = Ks + buf*(32*KH_STR);
        __half* Vb = Vs + buf*(32*VH_STR);
        int r = tid >> 3, off = (tid & 7) * 8;
        size_t base = (size_t)(b*TT + kb*32 + r)*3072 + h*64 + off;
        cp16(&Kb[r*KH_STR + off], qkv + base + 1024);
        cp16(&Vb[r*VH_STR + off], qkv + base + 2048);
        cp_commit();
    };

    load_tile(0, 0);
    load_tile(1, 1);

    float mrow0 = -1e30f, mrow1 = -1e30f;
    float lrow0 = 0.f,    lrow1 = 0.f;
    float o[8][4];
    #pragma unroll
    for (int nt = 0; nt < 8; nt++)
        #pragma unroll
        for (int i = 0; i < 4; i++) o[nt][i] = 0.f;

    const int rg0 = q0 + m0 + lr, rg1 = rg0 + 8;

    const int a_row = (g & 1) * 8 + tr;
    const int a_col = (g >> 1) * 8;
    const int bt_row = (g >> 1) * 8 + tr;
    const int bt_col = (g & 1) * 8;
    const int bf_row = (g & 1) * 8 + tr;
    const int bf_col = (g >> 1) * 8;

    for (int kb = 0; kb < ntiles; kb++) {
        if (kb + 1 < ntiles) cp_wait1(); else cp_wait0();
        __syncthreads();
        if (kb + 2 < ntiles) load_tile(kb + 2, (kb + 2) % 3);

        const unsigned kbb = smem0 + (KH_OFF + (kb % 3)*(32*KH_STR))*2;
        const unsigned vbb = smem0 + (VH_OFF + (kb % 3)*(32*VH_STR))*2;
        const unsigned qbb = smem0 + QH_OFF*2;
        const unsigned pbb = smem0 + PH_OFF*2;

        float s[4][4];
        #pragma unroll
        for (int nt = 0; nt < 4; nt++)
            #pragma unroll
            for (int i = 0; i < 4; i++) s[nt][i] = 0.f;
        #pragma unroll
        for (int ks = 0; ks < 4; ks++) {
            const int kk = ks * 16;
            unsigned a[4];
            ldsm4(a, qbb + ((m0 + a_row)*QH_STR + kk + a_col)*2);
            unsigned bfr[2][4];
            ldsm4(bfr[0], kbb + ((bt_row)*KH_STR + kk + bt_col)*2);
            ldsm4(bfr[1], kbb + ((16 + bt_row)*KH_STR + kk + bt_col)*2);
            unsigned bv[4][2];
            bv[0][0]=bfr[0][0]; bv[0][1]=bfr[0][1];
            bv[1][0]=bfr[0][2]; bv[1][1]=bfr[0][3];
            bv[2][0]=bfr[1][0]; bv[2][1]=bfr[1][1];
            bv[3][0]=bfr[1][2]; bv[3][1]=bfr[1][3];
            #pragma unroll
            for (int nt = 0; nt < 4; nt++)
                mma_f16(s[nt], a, bv[nt]);
        }

        #pragma unroll
        for (int nt = 0; nt < 4; nt++)
            #pragma unroll
            for (int i = 0; i < 4; i++) s[nt][i] *= 0.125f;
        if (kb*32 + 31 > q0 + m0) {
            #pragma unroll
            for (int nt = 0; nt < 4; nt++) {
                int c0 = kb*32 + nt*8 + 2*lq;
                if (c0   > rg0) s[nt][0] = -1e30f;
                if (c0+1 > rg0) s[nt][1] = -1e30f;
                if (c0   > rg1) s[nt][2] = -1e30f;
                if (c0+1 > rg1) s[nt][3] = -1e30f;
            }
        }

        float mx0 = -1e30f, mx1 = -1e30f;
        #pragma unroll
        for (int nt = 0; nt < 4; nt++) {
            mx0 = fmaxf(mx0, fmaxf(s[nt][0], s[nt][1]));
            mx1 = fmaxf(mx1, fmaxf(s[nt][2], s[nt][3]));
        }
        mx0 = fmaxf(mx0, __shfl_xor_sync(0xffffffffu, mx0, 1));
        mx0 = fmaxf(mx0, __shfl_xor_sync(0xffffffffu, mx0, 2));
        mx1 = fmaxf(mx1, __shfl_xor_sync(0xffffffffu, mx1, 1));
        mx1 = fmaxf(mx1, __shfl_xor_sync(0xffffffffu, mx1, 2));
        float mn0 = fmaxf(mrow0, mx0), mn1 = fmaxf(mrow1, mx1);
        float corr0 = __expf(mrow0 - mn0), corr1 = __expf(mrow1 - mn1);
        float sum0 = 0.f, sum1 = 0.f;
        #pragma unroll
        for (int nt = 0; nt < 4; nt++) {
            s[nt][0] = __expf(s[nt][0] - mn0);
            s[nt][1] = __expf(s[nt][1] - mn0);
            s[nt][2] = __expf(s[nt][2] - mn1);
            s[nt][3] = __expf(s[nt][3] - mn1);
            sum0 += s[nt][0] + s[nt][1];
            sum1 += s[nt][2] + s[nt][3];
        }
        sum0 += __shfl_xor_sync(0xffffffffu, sum0, 1);
        sum0 += __shfl_xor_sync(0xffffffffu, sum0, 2);
        sum1 += __shfl_xor_sync(0xffffffffu, sum1, 1);
        sum1 += __shfl_xor_sync(0xffffffffu, sum1, 2);
        lrow0 = lrow0*corr0 + sum0;
        lrow1 = lrow1*corr1 + sum1;
        mrow0 = mn0; mrow1 = mn1;
        #pragma unroll
        for (int nt = 0; nt < 8; nt++) {
            o[nt][0] *= corr0; o[nt][1] *= corr0;
            o[nt][2] *= corr1; o[nt][3] *= corr1;
        }

        #pragma unroll
        for (int nt = 0; nt < 4; nt++) {
            *(__half2*)&Ps[(m0+lr)*PH_STR + nt*8+2*lq]   = __floats2half2_rn(s[nt][0], s[nt][1]);
            *(__half2*)&Ps[(m0+lr+8)*PH_STR + nt*8+2*lq] = __floats2half2_rn(s[nt][2], s[nt][3]);
        }
        __syncwarp();

        #pragma unroll
        for (int ks = 0; ks < 2; ks++) {
            const int kk = ks * 16;
            unsigned a[4];
            ldsm4(a, pbb + ((m0 + a_row)*PH_STR + kk + a_col)*2);
            #pragma unroll
            for (int ng = 0; ng < 4; ng++) {
                unsigned r[4];
                ldsm4t(r, vbb + ((kk + bf_row)*VH_STR + ng*16 + bf_col)*2);
                unsigned b0[2] = { r[0], r[1] };
                unsigned b1[2] = { r[2], r[3] };
                mma_f16(o[ng*2],   a, b0);
                mma_f16(o[ng*2+1], a, b1);
            }
        }
    }

    float inv0 = 1.f / lrow0, inv1 = 1.f / lrow1;
    #pragma unroll
    for (int nt = 0; nt < 8; nt++) {
        int cg = h*64 + nt*8 + 2*lq;
        size_t base0 = (size_t)(b*TT + rg0)*DD + cg;
        size_t base1 = (size_t)(b*TT + rg1)*DD + cg;
        ((__half2*)out)[base0>>1] = __floats2half2_rn(o[nt][0]*inv0, o[nt][1]*inv0);
        ((__half2*)out)[base1>>1] = __floats2half2_rn(o[nt][2]*inv1, o[nt][3]*inv1);
    }
}

// ---------------------------------------------------------------------------
// top2 / pmean / assign / scatter / aux / softmax512
// ---------------------------------------------------------------------------
__global__ void top2_kernel(const float* __restrict__ logits,
                            float* __restrict__ probs,
                            int* __restrict__ topi, float* __restrict__ topw)
{
    int n = blockIdx.x*blockDim.x + threadIdx.x;
    if (n >= NTOK) return;
    float l[EE];
    float mx = -1e30f;
    #pragma unroll
    for (int e = 0; e < EE; e++) { l[e] = logits[n*EE+e]; mx = fmaxf(mx, l[e]); }
    float sum = 0.f;
    #pragma unroll
    for (int e = 0; e < EE; e++) { l[e] = __expf(l[e]-mx); sum += l[e]; }
    float inv = 1.f/sum;
    #pragma unroll
    for (int e = 0; e < EE; e++) { l[e] *= inv; probs[n*EE+e] = l[e]; }
    int i0 = 0; float p0 = l[0];
    #pragma unroll
    for (int e = 1; e < EE; e++) if (l[e] > p0) { p0 = l[e]; i0 = e; }
    int i1 = (i0 == 0) ? 1 : 0; float p1 = l[i1];
    #pragma unroll
    for (int e = 0; e < EE; e++) if (e != i0 && l[e] > p1) { p1 = l[e]; i1 = e; }
    float ws = p0 + p1;
    topi[n*2]   = i0; topi[n*2+1] = i1;
    topw[n*2]   = p0/ws; topw[n*2+1] = p1/ws;
}

__global__ void pmean_kernel(const float* __restrict__ probs, float* __restrict__ pmean)
{
    int e = blockIdx.x, tid = threadIdx.x;
    float s = 0.f;
    for (int t = tid; t < NTOK; t += 256) s += probs[t*EE + e];
    __shared__ float red[256];
    red[tid] = s;
    __syncthreads();
    for (int k = 128; k; k >>= 1) {
        if (tid < k) red[tid] += red[tid+k];
        __syncthreads();
    }
    if (tid == 0) pmean[e] = red[0] / (float)NTOK;
}

__global__ void assign_kernel(const int* __restrict__ topi,
                              const float* __restrict__ topw,
                              int* __restrict__ slot, int* __restrict__ keep,
                              float* __restrict__ wcomb, int* __restrict__ counts)
{
    int e = blockIdx.x;
    int tid = threadIdx.x;
    int lane = tid & 31, warp = tid >> 5;
    __shared__ int warpsum[8];
    int running = 0;
    for (int base = 0; base < NFLAT; base += 256) {
        int i = base + tid;
        int match = (topi[i] == e) ? 1 : 0;
        unsigned mask = __ballot_sync(0xffffffffu, match);
        if (lane == 0) warpsum[warp] = __popc(mask);
        __syncthreads();
        int wbase = 0, tot = 0;
        #pragma unroll
        for (int w = 0; w < 8; w++) {
            int c = warpsum[w];
            if (w < warp) wbase += c;
            tot += c;
        }
        if (match) {
            int pos = running + wbase + __popc(mask & ((1u << lane) - 1u));
            int kp = (pos < CAP) ? 1 : 0;
            slot[i]  = (pos < CAP-1) ? pos : (CAP-1);
            keep[i]  = kp;
            wcomb[i] = kp ? topw[i] : 0.f;
        }
        running += tot;
        __syncthreads();
    }
    if (tid == 0) counts[e] = running;
}

__global__ void scatter_kernel(const int* __restrict__ topi,
                               const int* __restrict__ slot,
                               const int* __restrict__ keep,
                               const __half* __restrict__ xn,
                               __half* __restrict__ buf)
{
    int i = blockIdx.x;
    if (!keep[i]) return;
    int e = topi[i], s = slot[i], tok = i >> 1;
    const uint2* src = (const uint2*)(xn + (size_t)tok*DD);
    uint2* dst = (uint2*)(buf + ((size_t)e*CAP + s)*DD);
    dst[threadIdx.x] = src[threadIdx.x];
}

__global__ void aux_kernel(const int* __restrict__ counts,
                           const float* __restrict__ pmean,
                           float* __restrict__ out, int out_size)
{
    if (threadIdx.x == 0 && out_size > NTOK*DD) {
        float s = 0.f;
        for (int e = 0; e < EE; e++)
            s += ((float)counts[e] / (float)NTOK) * pmean[e];
        out[NTOK*DD] = (float)EE * s;
    }
}

__global__ void softmax512_kernel(const float* __restrict__ tl, __half* __restrict__ outh)
{
    int n = blockIdx.x, tid = threadIdx.x;
    const float* row = tl + (size_t)n*NPRIM;
    __half* orow = outh + (size_t)n*NPRIM;
    float v0 = row[tid]       * 0.0625f;
    float v1 = row[tid + 256] * 0.0625f;
    __shared__ float red[256];
    red[tid] = fmaxf(v0, v1);
    __syncthreads();
    for (int s = 128; s; s >>= 1) {
        if (tid < s) red[tid] = fmaxf(red[tid], red[tid+s]);
        __syncthreads();
    }
    float mx = red[0];
    __syncthreads();
    v0 = __expf(v0 - mx); v1 = __expf(v1 - mx);
    red[tid] = v0 + v1;
    __syncthreads();
    for (int s = 128; s; s >>= 1) {
        if (tid < s) red[tid] += red[tid+s];
        __syncthreads();
    }
    float inv = 1.f / red[0];
    orow[tid]       = __float2half_rn(v0*inv);
    orow[tid + 256] = __float2half_rn(v1*inv);
}

// ---------------------------------------------------------------------------
// Host launch
// ---------------------------------------------------------------------------
#define F2H(stream, src, dst, n) f2h_kernel<<<(n)/2048, 256, 0, stream>>>(src, dst)

extern "C" void kernel_launch(void* const* d_in, const int* in_sizes, int n_in,
                              void* d_out, int out_size)
{
    const float* x          = (const float*)d_in[0];
    const float* tou_embeds = (const float*)d_in[1];
    const float* norm1_w    = (const float*)d_in[2];
    const float* qkv_w      = (const float*)d_in[3];
    const float* attn_o_w   = (const float*)d_in[4];
    const float* norm2_w    = (const float*)d_in[5];
    const float* router_w   = (const float*)d_in[6];
    const float* moe_w1     = (const float*)d_in[7];
    const float* moe_w2     = (const float*)d_in[8];
    const float* norm3_w    = (const float*)d_in[9];
    const float* tou_q_w    = (const float*)d_in[10];
    const float* tou_k_w    = (const float*)d_in[11];
    const float* tou_v_w    = (const float*)d_in[12];
    const float* tou_o_w    = (const float*)d_in[13];
    const float* tou_gate_w = (const float*)d_in[14];
    const float* tou_gate_b = (const float*)d_in[15];

    cudaFuncSetAttribute(gemm_h<true,0,false>,  cudaFuncAttributeMaxDynamicSharedMemorySize, SMEM_HBT);
    cudaFuncSetAttribute(gemm_h<true,0,true>,   cudaFuncAttributeMaxDynamicSharedMemorySize, SMEM_HBT);
    cudaFuncSetAttribute(gemm_h<true,4,false>,  cudaFuncAttributeMaxDynamicSharedMemorySize, SMEM_HBT);
    cudaFuncSetAttribute(gemm_h<true,5,false>,  cudaFuncAttributeMaxDynamicSharedMemorySize, SMEM_HBT);
    cudaFuncSetAttribute(gemm_h<false,0,false>, cudaFuncAttributeMaxDynamicSharedMemorySize, SMEM_HKN);
    cudaFuncSetAttribute(gemm_h<false,0,true>,  cudaFuncAttributeMaxDynamicSharedMemorySize, SMEM_HKN);
    cudaFuncSetAttribute(gemm_h<false,2,true>,  cudaFuncAttributeMaxDynamicSharedMemorySize, SMEM_HKN);
    cudaFuncSetAttribute(flash_attn_h,          cudaFuncAttributeMaxDynamicSharedMemorySize, FLASHH_SMEM);

    float *gx, *glogits, *gprobs, *gtopw, *gwcomb, *gpmean, *gyb, *gtl, *ggate;
    int *gtopi, *gslot, *gkeep, *gcounts;
    __half *hqkv, *hxn, *hattn, *hbuf, *hh, *htq, *htk, *htv, *htl, *htout;
    __half *hqkvw, *haow, *hw1, *hw2, *htqw, *htkw, *htvw, *htow, *hemb;
    cudaGetSymbolAddress((void**)&gx, g_x);
    cudaGetSymbolAddress((void**)&glogits, g_logits);
    cudaGetSymbolAddress((void**)&gprobs, g_probs);
    cudaGetSymbolAddress((void**)&gtopi, g_topi);
    cudaGetSymbolAddress((void**)&gtopw, g_topw);
    cudaGetSymbolAddress((void**)&gslot, g_slot);
    cudaGetSymbolAddress((void**)&gkeep, g_keep);
    cudaGetSymbolAddress((void**)&gwcomb, g_wcomb);
    cudaGetSymbolAddress((void**)&gcounts, g_counts);
    cudaGetSymbolAddress((void**)&gpmean, g_pmean);
    cudaGetSymbolAddress((void**)&gyb, g_yb);
    cudaGetSymbolAddress((void**)&gtl, g_tl);
    cudaGetSymbolAddress((void**)&ggate, g_gate);
    cudaGetSymbolAddress((void**)&hqkv, gh_qkv);
    cudaGetSymbolAddress((void**)&hxn, gh_xn);
    cudaGetSymbolAddress((void**)&hattn, gh_attn);
    cudaGetSymbolAddress((void**)&hbuf, gh_buf);
    cudaGetSymbolAddress((void**)&hh, gh_h);
    cudaGetSymbolAddress((void**)&htq, gh_tq);
    cudaGetSymbolAddress((void**)&htk, gh_tk);
    cudaGetSymbolAddress((void**)&htv, gh_tv);
    cudaGetSymbolAddress((void**)&htl, gh_tl);
    cudaGetSymbolAddress((void**)&htout, gh_tout);
    cudaGetSymbolAddress((void**)&hqkvw, gh_qkvw);
    cudaGetSymbolAddress((void**)&haow, gh_aow);
    cudaGetSymbolAddress((void**)&hw1, gh_w1);
    cudaGetSymbolAddress((void**)&hw2, gh_w2);
    cudaGetSymbolAddress((void**)&htqw, gh_tqw);
    cudaGetSymbolAddress((void**)&htkw, gh_tkw);
    cudaGetSymbolAddress((void**)&htvw, gh_tvw);
    cudaGetSymbolAddress((void**)&htow, gh_tow);
    cudaGetSymbolAddress((void**)&hemb, gh_emb);

    cudaEventRecord(ev_root, 0);

    // ---- s1: rope table, ToU weight conversions + tiny GEMMs ----
    cudaStreamWaitEvent(s1, ev_root, 0);
    rope_table_kernel<<<TT*32/256, 256, 0, s1>>>();
    cudaEventRecord(ev_tab, s1);
    F2H(s1, tou_embeds, hemb, NPRIM*DP);
    F2H(s1, tou_k_w, htkw, DP*DP);
    F2H(s1, tou_v_w, htvw, DP*DP);
    F2H(s1, tou_q_w, htqw, DP*DD);
    F2H(s1, tou_o_w, htow, DD*DP);
    gemm_h<true,0,true><<<dim3(DP/128, NPRIM/128, 1), 256, SMEM_HBT, s1>>>(
        hemb, htkw, htk, NPRIM, DP, DP, 0, 0, 0, nullptr, nullptr);
    gemm_h<true,0,true><<<dim3(DP/128, NPRIM/128, 1), 256, SMEM_HBT, s1>>>(
        hemb, htvw, htv, NPRIM, DP, DP, 0, 0, 0, nullptr, nullptr);
    cudaEventRecord(ev_s1, s1);

    // ---- s2: qkv_w + attn_o conversions, gbuf memset, MoE weight conversions ----
    cudaStreamWaitEvent(s2, ev_root, 0);
    F2H(s2, qkv_w, hqkvw, 3*DD*DD);
    cudaEventRecord(ev_qkvw, s2);
    F2H(s2, attn_o_w, haow, DD*DD);
    cudaEventRecord(ev_aow, s2);
    cudaMemsetAsync(hbuf, 0, (size_t)EE*CAP*DD*sizeof(__half), s2);
    F2H(s2, moe_w1, hw1, EE*DD*FF);
    F2H(s2, moe_w2, hw2, EE*FF*DD);
    cudaEventRecord(ev_s2, s2);

    // ---- Block 1 ----
    rmsnorm_h<<<NTOK, 256>>>(x, norm1_w, hxn);
    cudaStreamWaitEvent(0, ev_qkvw, 0);
    gemm_h<true,0,true><<<dim3(3*DD/128, NTOK/128, 1), 256, SMEM_HBT>>>(
        hxn, hqkvw, hqkv, NTOK, 3*DD, DD, 0, 0, 0, nullptr, nullptr);
    cudaStreamWaitEvent(0, ev_tab, 0);
    rope_hh<<<NTOK, 256>>>(hqkv);
    flash_attn_h<<<dim3(TT/128, BB*HH), 256, FLASHH_SMEM>>>(hqkv, hattn);
    cudaStreamWaitEvent(0, ev_aow, 0);
    gemm_h<true,4,false><<<dim3(DD/128, NTOK/128, 1), 256, SMEM_HBT>>>(
        hattn, haow, gx, NTOK, DD, DD, 0, 0, 0, nullptr, x);   // gx = x + proj

    // ---- Block 2: MoE ----
    rmsnorm_router<<<NTOK, 256>>>(gx, norm2_w, hxn, router_w, glogits);
    top2_kernel<<<NTOK/128, 128>>>(glogits, gprobs, gtopi, gtopw);
    cudaEventRecord(ev_top2, 0);
    cudaStreamWaitEvent(s2, ev_top2, 0);
    pmean_kernel<<<EE, 256, 0, s2>>>(gprobs, gpmean);
    cudaEventRecord(ev_pm, s2);
    assign_kernel<<<EE, 256>>>(gtopi, gtopw, gslot, gkeep, gwcomb, gcounts);
    cudaStreamWaitEvent(0, ev_s2, 0);
    scatter_kernel<<<NFLAT, 256>>>(gtopi, gslot, gkeep, hxn, hbuf);
    gemm_h<false,2,true><<<dim3(FF/128, CAP/128, EE), 256, SMEM_HKN>>>(
        hbuf, hw1, hh, CAP, FF, DD,
        (long long)CAP*DD, (long long)DD*FF, (long long)CAP*FF, nullptr, nullptr);
    gemm_h<false,0,false><<<dim3(DD/128, CAP/128, EE), 256, SMEM_HKN>>>(
        hh, hw2, gyb, CAP, DD, FF,
        (long long)CAP*FF, (long long)FF*DD, (long long)CAP*DD, nullptr, nullptr);
    // fused gather + rmsnorm3 + gate
    gather_ng<<<NTOK, 256>>>(gtopi, gslot, gwcomb, gyb, gx,
                             norm3_w, tou_gate_w, tou_gate_b, hxn, ggate);
    cudaStreamWaitEvent(0, ev_pm, 0);
    aux_kernel<<<1, 32>>>(gcounts, gpmean, (float*)d_out, out_size);

    // ---- Block 3: ToU cross-attention ----
    cudaStreamWaitEvent(0, ev_s1, 0);
    gemm_h<true,0,true><<<dim3(DP/128, NTOK/128, 1), 256, SMEM_HBT>>>(
        hxn, htqw, htq, NTOK, DP, DD, 0, 0, 0, nullptr, nullptr);
    gemm_h<true,0,false><<<dim3(NPRIM/128, NTOK/128, 1), 256, SMEM_HBT>>>(
        htq, htk, gtl, NTOK, NPRIM, DP, 0, 0, 0, nullptr, nullptr);
    softmax512_kernel<<<NTOK, 256>>>(gtl, htl);
    gemm_h<false,0,true><<<dim3(DP/128, NTOK/128, 1), 256, SMEM_HKN>>>(
        htl, htv, htout, NTOK, DP, NPRIM, 0, 0, 0, nullptr, nullptr);
    gemm_h<true,5,false><<<dim3(DD/128, NTOK/128, 1), 256, SMEM_HBT>>>(
        htout, htow, (float*)d_out, NTOK, DD, DP, 0, 0, 0, ggate, gx);
}

// round 14
// speedup vs baseline: 1.4682x; 1.4682x over previous
#include <cuda_runtime.h>
#include <cuda_bf16.h>
#include <cuda_fp16.h>
#include <math.h>

// ---------------------------------------------------------------------------
// Problem constants
// ---------------------------------------------------------------------------
#define BB 2
#define TT 2048
#define DD 1024
#define HH 16
#define DH 64
#define NTOK (BB*TT)            // 4096
#define EE 16
#define KK 2
#define FF 2048
#define CAP 640
#define DP 256
#define NPRIM 512
#define NFLAT (NTOK*KK)         // 8192

// ---------------------------------------------------------------------------
// Scratch (device globals; no allocation allowed)
// ---------------------------------------------------------------------------
__device__ float g_x[NTOK*DD];
__device__ float g_xn[NTOK*DD];          // fp32 xn (router)
__device__ float g_logits[NTOK*EE];
__device__ float g_probs[NTOK*EE];
__device__ int   g_topi[NFLAT];
__device__ float g_topw[NFLAT];
__device__ int   g_slot[NFLAT];
__device__ int   g_keep[NFLAT];
__device__ float g_wcomb[NFLAT];
__device__ int   g_counts[EE];
__device__ float g_pmean[EE];
__device__ float g_yb[EE*CAP*DD];
__device__ float g_tl[NTOK*NPRIM];
__device__ float g_gate[NTOK];
__device__ float g_ropec[TT*32];
__device__ float g_ropes[TT*32];

// fp16 buffers
__device__ __half gh_qkv[NTOK*3*DD];
__device__ __half gh_xn[NTOK*DD];
__device__ __half gh_attn[NTOK*DD];
__device__ __half gh_buf[EE*CAP*DD];
__device__ __half gh_h[EE*CAP*FF];
__device__ __half gh_tq[NTOK*DP];
__device__ __half gh_tk[NPRIM*DP];
__device__ __half gh_tv[NPRIM*DP];
__device__ __half gh_tl[NTOK*NPRIM];
__device__ __half gh_tout[NTOK*DP];
// fp16 weights (converted once per launch)
__device__ __half gh_qkvw[3*DD*DD];
__device__ __half gh_aow[DD*DD];
__device__ __half gh_w1[EE*DD*FF];
__device__ __half gh_w2[EE*FF*DD];
__device__ __half gh_tqw[DP*DD];
__device__ __half gh_tkw[DP*DP];
__device__ __half gh_tvw[DP*DP];
__device__ __half gh_tow[DD*DP];
__device__ __half gh_emb[NPRIM*DP];

// ---------------------------------------------------------------------------
// Streams / events (host resources, created once)
// ---------------------------------------------------------------------------
static cudaStream_t s1, s2;
static cudaEvent_t ev_root, ev_tab, ev_s1, ev_s2, ev_qkvw, ev_aow,
                   ev_top2, ev_pm, ev_n3, ev_gate;
namespace {
struct InitOnce {
    InitOnce() {
        cudaStreamCreateWithFlags(&s1, cudaStreamNonBlocking);
        cudaStreamCreateWithFlags(&s2, cudaStreamNonBlocking);
        cudaEventCreateWithFlags(&ev_root, cudaEventDisableTiming);
        cudaEventCreateWithFlags(&ev_tab,  cudaEventDisableTiming);
        cudaEventCreateWithFlags(&ev_s1,   cudaEventDisableTiming);
        cudaEventCreateWithFlags(&ev_s2,   cudaEventDisableTiming);
        cudaEventCreateWithFlags(&ev_qkvw, cudaEventDisableTiming);
        cudaEventCreateWithFlags(&ev_aow,  cudaEventDisableTiming);
        cudaEventCreateWithFlags(&ev_top2, cudaEventDisableTiming);
        cudaEventCreateWithFlags(&ev_pm,   cudaEventDisableTiming);
        cudaEventCreateWithFlags(&ev_n3,   cudaEventDisableTiming);
        cudaEventCreateWithFlags(&ev_gate, cudaEventDisableTiming);
    }
};
static InitOnce init_once_;
}

// ---------------------------------------------------------------------------
// MMA / cp.async / ldmatrix helpers
// ---------------------------------------------------------------------------
__device__ __forceinline__ void mma_f16(float c[4], const unsigned a[4], const unsigned b[2])
{
    asm volatile(
        "mma.sync.aligned.m16n8k16.row.col.f32.f16.f16.f32 "
        "{%0,%1,%2,%3},{%4,%5,%6,%7},{%8,%9},{%0,%1,%2,%3};"
        : "+f"(c[0]), "+f"(c[1]), "+f"(c[2]), "+f"(c[3])
        : "r"(a[0]), "r"(a[1]), "r"(a[2]), "r"(a[3]),
          "r"(b[0]), "r"(b[1]));
}

__device__ __forceinline__ void ldsm4(unsigned r[4], unsigned addr)
{
    asm volatile("ldmatrix.sync.aligned.m8n8.x4.shared.b16 {%0,%1,%2,%3}, [%4];"
        : "=r"(r[0]), "=r"(r[1]), "=r"(r[2]), "=r"(r[3]) : "r"(addr));
}
__device__ __forceinline__ void ldsm4t(unsigned r[4], unsigned addr)
{
    asm volatile("ldmatrix.sync.aligned.m8n8.x4.trans.shared.b16 {%0,%1,%2,%3}, [%4];"
        : "=r"(r[0]), "=r"(r[1]), "=r"(r[2]), "=r"(r[3]) : "r"(addr));
}

__device__ __forceinline__ void cp16(void* smem_dst, const void* gptr)
{
    unsigned saddr = (unsigned)__cvta_generic_to_shared(smem_dst);
    asm volatile("cp.async.cg.shared.global [%0], [%1], 16;\n"
                 :: "r"(saddr), "l"(gptr));
}
__device__ __forceinline__ void cp_commit()  { asm volatile("cp.async.commit_group;\n"); }
__device__ __forceinline__ void cp_wait2()   { asm volatile("cp.async.wait_group 2;\n"); }
__device__ __forceinline__ void cp_wait1()   { asm volatile("cp.async.wait_group 1;\n"); }
__device__ __forceinline__ void cp_wait0()   { asm volatile("cp.async.wait_group 0;\n"); }

// ---------------------------------------------------------------------------
// f32 -> f16 conversion (n % 2048 == 0)
// ---------------------------------------------------------------------------
__global__ void f2h_kernel(const float* __restrict__ in, __half* __restrict__ out)
{
    int i = (blockIdx.x*256 + threadIdx.x) * 8;
    float4 v0 = *(const float4*)(in + i);
    float4 v1 = *(const float4*)(in + i + 4);
    __half2* o = (__half2*)(out + i);
    o[0] = __floats2half2_rn(v0.x, v0.y);
    o[1] = __floats2half2_rn(v0.z, v0.w);
    o[2] = __floats2half2_rn(v1.x, v1.y);
    o[3] = __floats2half2_rn(v1.z, v1.w);
}

// ---------------------------------------------------------------------------
// RMSNorm: one block per token; fp16 out (+optional fp32 out)
// ---------------------------------------------------------------------------
__global__ void rmsnorm_h(const float* __restrict__ x,
                          const float* __restrict__ w,
                          __half* __restrict__ outh,
                          float* __restrict__ outf)
{
    int n = blockIdx.x;
    int tid = threadIdx.x;
    const float4* xp = (const float4*)(x + (size_t)n*DD);
    float4 xv = xp[tid];
    float ss = xv.x*xv.x + xv.y*xv.y + xv.z*xv.z + xv.w*xv.w;
    __shared__ float red[256];
    red[tid] = ss;
    __syncthreads();
    for (int s = 128; s; s >>= 1) {
        if (tid < s) red[tid] += red[tid+s];
        __syncthreads();
    }
    float scale = rsqrtf(red[0] / (float)DD + 1e-6f);
    const float4* wp = (const float4*)w;
    float4 wv = wp[tid];
    float a = xv.x*scale*wv.x, b = xv.y*scale*wv.y;
    float c = xv.z*scale*wv.z, d = xv.w*scale*wv.w;
    __half2* oh = (__half2*)(outh + (size_t)n*DD);
    oh[2*tid]   = __floats2half2_rn(a, b);
    oh[2*tid+1] = __floats2half2_rn(c, d);
    if (outf) ((float4*)(outf + (size_t)n*DD))[tid] = make_float4(a, b, c, d);
}

// ---------------------------------------------------------------------------
// FP16 tensor-core GEMM (m16n8k16): 4-stage cp.async, ldmatrix fragments.
// EPI: 0=store, 2=silu store, 4=C=Xin+v, 5=C=Xin+gate*v;  OUTH: __half out
// ---------------------------------------------------------------------------
#define AH_STR 40
#define BH_STR 136
#define NSTG 4
#define AH_TILE (128*AH_STR)
#define BH_TILE (32*BH_STR)

template<bool BT, int EPI, bool OUTH>
__global__ __launch_bounds__(256, 2)
void gemm_h(const __half* __restrict__ A, const __half* __restrict__ Bm,
            void* __restrict__ Cv, int M, int N, int K,
            long long sA, long long sB, long long sC,
            const float* __restrict__ gate, const float* __restrict__ Xin)
{
    A  += blockIdx.z * sA;
    Bm += blockIdx.z * sB;

    extern __shared__ __half smem_h[];
    __half* AsP = smem_h;
    __half* BsP = smem_h + NSTG*AH_TILE;
    const unsigned sbase = (unsigned)__cvta_generic_to_shared(smem_h);
    const unsigned bbase = sbase + NSTG*AH_TILE*2;

    const int tid  = threadIdx.x;
    const int lane = tid & 31;
    const int warp = tid >> 5;
    const int lr   = lane >> 2;
    const int lq   = lane & 3;
    const int g    = lane >> 3;
    const int tr   = lane & 7;
    const int wm   = warp & 1, wn = warp >> 1;
    const int m0   = wm * 64, n0 = wn * 32;
    const int row0 = blockIdx.y * 128, col0 = blockIdx.x * 128;

    const int c0i = tid, c1i = tid + 256;
    const int ar0 = c0i >> 2, ac0 = (c0i & 3) * 8;
    const int ar1 = c1i >> 2, ac1 = (c1i & 3) * 8;
    const int fr0 = c0i >> 4, fo0 = (c0i & 15) * 8;
    const int fr1 = c1i >> 4, fo1 = (c1i & 15) * 8;

    const int nIter = K >> 5;

    auto issue = [&](int stg, int k0) {
        cp16(&AsP[stg*AH_TILE + ar0*AH_STR + ac0], A + (size_t)(row0 + ar0) * K + k0 + ac0);
        cp16(&AsP[stg*AH_TILE + ar1*AH_STR + ac1], A + (size_t)(row0 + ar1) * K + k0 + ac1);
        if constexpr (BT) {
            cp16(&BsP[stg*AH_TILE + ar0*AH_STR + ac0], Bm + (size_t)(col0 + ar0) * K + k0 + ac0);
            cp16(&BsP[stg*AH_TILE + ar1*AH_STR + ac1], Bm + (size_t)(col0 + ar1) * K + k0 + ac1);
        } else {
            cp16(&BsP[stg*BH_TILE + fr0*BH_STR + fo0], Bm + (size_t)(k0 + fr0) * N + col0 + fo0);
            cp16(&BsP[stg*BH_TILE + fr1*BH_STR + fo1], Bm + (size_t)(k0 + fr1) * N + col0 + fo1);
        }
        cp_commit();
    };

    issue(0, 0);
    if (nIter > 1) issue(1, 32);
    if (nIter > 2) issue(2, 64);

    float c[4][4][4];
    #pragma unroll
    for (int mt = 0; mt < 4; mt++)
        #pragma unroll
        for (int nt = 0; nt < 4; nt++)
            #pragma unroll
            for (int i = 0; i < 4; i++) c[mt][nt][i] = 0.f;

    const int a_row = (g & 1) * 8 + tr;
    const int a_col = (g >> 1) * 8;
    const int bt_row = (g >> 1) * 8 + tr;
    const int bt_col = (g & 1) * 8;
    const int bf_row = (g & 1) * 8 + tr;
    const int bf_col = (g >> 1) * 8;

    for (int it = 0; it < nIter; it++) {
        if (it + 2 < nIter)      cp_wait2();
        else if (it + 1 < nIter) cp_wait1();
        else                     cp_wait0();
        __syncthreads();

        if (it + 3 < nIter) issue((it + 3) & 3, (it + 3) << 5);

        const int st = it & 3;
        const unsigned abase = sbase + st*AH_TILE*2;
        const unsigned btb   = bbase + (BT ? st*AH_TILE*2 : st*BH_TILE*2);

        #pragma unroll
        for (int ks = 0; ks < 2; ks++) {
            const int kb = ks * 16;
            unsigned a[4][4];
            #pragma unroll
            for (int mt = 0; mt < 4; mt++) {
                unsigned addr = abase + ((m0 + mt*16 + a_row)*AH_STR + kb + a_col)*2;
                ldsm4(a[mt], addr);
            }
            unsigned b[4][2];
            #pragma unroll
            for (int ntp = 0; ntp < 2; ntp++) {
                unsigned r[4];
                if constexpr (BT) {
                    unsigned addr = btb + ((n0 + ntp*16 + bt_row)*AH_STR + kb + bt_col)*2;
                    ldsm4(r, addr);
                } else {
                    unsigned addr = btb + ((kb + bf_row)*BH_STR + n0 + ntp*16 + bf_col)*2;
                    ldsm4t(r, addr);
                }
                b[ntp*2][0]   = r[0]; b[ntp*2][1]   = r[1];
                b[ntp*2+1][0] = r[2]; b[ntp*2+1][1] = r[3];
            }
            #pragma unroll
            for (int mt = 0; mt < 4; mt++)
                #pragma unroll
                for (int nt = 0; nt < 4; nt++)
                    mma_f16(c[mt][nt], a[mt], b[nt]);
        }
    }

    float* Cf = (float*)Cv + (OUTH ? 0 : blockIdx.z * sC);
    __half* Ch = (__half*)Cv + (OUTH ? blockIdx.z * sC : 0);
    #pragma unroll
    for (int mt = 0; mt < 4; mt++) {
        int r0g = row0 + m0 + mt * 16 + lr;
        int r1g = r0g + 8;
        float g0 = (EPI == 5) ? gate[r0g] : 0.f;
        float g1 = (EPI == 5) ? gate[r1g] : 0.f;
        #pragma unroll
        for (int nt = 0; nt < 4; nt++) {
            int cg = col0 + n0 + nt * 8 + 2 * lq;
            size_t i0 = (size_t)r0g * N + cg;
            size_t i1 = (size_t)r1g * N + cg;
            float v0 = c[mt][nt][0], v1 = c[mt][nt][1];
            float v2 = c[mt][nt][2], v3 = c[mt][nt][3];
            if (EPI == 2) {
                v0 = v0 / (1.f + __expf(-v0));
                v1 = v1 / (1.f + __expf(-v1));
                v2 = v2 / (1.f + __expf(-v2));
                v3 = v3 / (1.f + __expf(-v3));
            } else if (EPI == 4) {
                float2 x0 = *(const float2*)&Xin[i0];
                float2 x1 = *(const float2*)&Xin[i1];
                v0 += x0.x; v1 += x0.y; v2 += x1.x; v3 += x1.y;
            } else if (EPI == 5) {
                float2 x0 = *(const float2*)&Xin[i0];
                float2 x1 = *(const float2*)&Xin[i1];
                v0 = x0.x + g0*v0; v1 = x0.y + g0*v1;
                v2 = x1.x + g1*v2; v3 = x1.y + g1*v3;
            }
            if (OUTH) {
                *(__half2*)&Ch[i0] = __floats2half2_rn(v0, v1);
                *(__half2*)&Ch[i1] = __floats2half2_rn(v2, v3);
            } else {
                *(float2*)&Cf[i0] = make_float2(v0, v1);
                *(float2*)&Cf[i1] = make_float2(v2, v3);
            }
        }
    }
}

#define SMEM_HBT ((NSTG*AH_TILE + NSTG*AH_TILE) * 2)
#define SMEM_HKN ((NSTG*AH_TILE + NSTG*BH_TILE) * 2)

// ---------------------------------------------------------------------------
// RoPE table + in-place fp16 apply
// ---------------------------------------------------------------------------
__global__ void rope_table_kernel()
{
    int idx = blockIdx.x * 256 + threadIdx.x;
    int t = idx >> 5, i = idx & 31;
    float inv = powf(10000.f, -(float)i / 32.f);
    float s, c;
    sincosf((float)t * inv, &s, &c);
    g_ropec[idx] = c;
    g_ropes[idx] = s;
}

__global__ void rope_hh(__half* __restrict__ qkvh)
{
    int n = blockIdx.x;
    int t = n & (TT-1);
    for (int p = threadIdx.x; p < 1024; p += 256) {
        int which = p >> 9;
        int rem = p & 511;
        int h = rem >> 5;
        int i = rem & 31;
        float c = g_ropec[t*32 + i];
        float s = g_ropes[t*32 + i];
        size_t base = (size_t)n*3072 + (size_t)which*1024 + h*64 + i;
        float u1 = __half2float(qkvh[base]);
        float u2 = __half2float(qkvh[base+32]);
        qkvh[base]    = __float2half_rn(u1*c - u2*s);
        qkvh[base+32] = __float2half_rn(u2*c + u1*s);
    }
}

// ---------------------------------------------------------------------------
// Flash attention FP16 (unchanged champion version)
// ---------------------------------------------------------------------------
#define QH_STR 72
#define KH_STR 72
#define VH_STR 72
#define PH_STR 40
#define QH_OFF 0
#define KH_OFF (128*QH_STR)
#define VH_OFF (KH_OFF + 3*32*KH_STR)
#define PH_OFF (VH_OFF + 3*32*VH_STR)
#define FLASHH_SMEM ((PH_OFF + 128*PH_STR) * 2)

__global__ __launch_bounds__(256)
void flash_attn_h(const __half* __restrict__ qkv, __half* __restrict__ out)
{
    extern __shared__ __half fsm_h[];
    __half* Qs = fsm_h + QH_OFF;
    __half* Ks = fsm_h + KH_OFF;
    __half* Vs = fsm_h + VH_OFF;
    __half* Ps = fsm_h + PH_OFF;
    const unsigned smem0 = (unsigned)__cvta_generic_to_shared(fsm_h);

    const int qb = blockIdx.x, bh = blockIdx.y;
    const int b = bh >> 4, h = bh & 15;
    const int tid = threadIdx.x, lane = tid & 31, warp = tid >> 5;
    const int lr = lane >> 2, lq = lane & 3;
    const int g = lane >> 3, tr = lane & 7;
    const int m0 = warp * 16;
    const int q0 = qb * 128;
    const int ntiles = 4*qb + 4;

    #pragma unroll
    for (int c = tid; c < 1024; c += 256) {
        int r = c >> 3, off = (c & 7) * 8;
        cp16(&Qs[r*QH_STR + off], qkv + (size_t)(b*TT + q0 + r)*3072 + h*64 + off);
    }

    auto load_tile = [&](int kb, int buf) {
        __half* Kb = Ks + buf*(32*KH_STR);
        __half* Vb = Vs + buf*(32*VH_STR);
        int r = tid >> 3, off = (tid & 7) * 8;
        size_t base = (size_t)(b*TT + kb*32 + r)*3072 + h*64 + off;
        cp16(&Kb[r*KH_STR + off], qkv + base + 1024);
        cp16(&Vb[r*VH_STR + off], qkv + base + 2048);
        cp_commit();
    };

    load_tile(0, 0);
    load_tile(1, 1);

    float mrow0 = -1e30f, mrow1 = -1e30f;
    float lrow0 = 0.f,    lrow1 = 0.f;
    float o[8][4];
    #pragma unroll
    for (int nt = 0; nt < 8; nt++)
        #pragma unroll
        for (int i = 0; i < 4; i++) o[nt][i] = 0.f;

    const int rg0 = q0 + m0 + lr, rg1 = rg0 + 8;

    const int a_row = (g & 1) * 8 + tr;
    const int a_col = (g >> 1) * 8;
    const int bt_row = (g >> 1) * 8 + tr;
    const int bt_col = (g & 1) * 8;
    const int bf_row = (g & 1) * 8 + tr;
    const int bf_col = (g >> 1) * 8;

    for (int kb = 0; kb < ntiles; kb++) {
        if (kb + 1 < ntiles) cp_wait1(); else cp_wait0();
        __syncthreads();
        if (kb + 2 < ntiles) load_tile(kb + 2, (kb + 2) % 3);

        const unsigned kbb = smem0 + (KH_OFF + (kb % 3)*(32*KH_STR))*2;
        const unsigned vbb = smem0 + (VH_OFF + (kb % 3)*(32*VH_STR))*2;
        const unsigned qbb = smem0 + QH_OFF*2;
        const unsigned pbb = smem0 + PH_OFF*2;

        float s[4][4];
        #pragma unroll
        for (int nt = 0; nt < 4; nt++)
            #pragma unroll
            for (int i = 0; i < 4; i++) s[nt][i] = 0.f;
        #pragma unroll
        for (int ks = 0; ks < 4; ks++) {
            const int kk = ks * 16;
            unsigned a[4];
            ldsm4(a, qbb + ((m0 + a_row)*QH_STR + kk + a_col)*2);
            unsigned bfr[2][4];
            ldsm4(bfr[0], kbb + ((bt_row)*KH_STR + kk + bt_col)*2);
            ldsm4(bfr[1], kbb + ((16 + bt_row)*KH_STR + kk + bt_col)*2);
            unsigned bv[4][2];
            bv[0][0]=bfr[0][0]; bv[0][1]=bfr[0][1];
            bv[1][0]=bfr[0][2]; bv[1][1]=bfr[0][3];
            bv[2][0]=bfr[1][0]; bv[2][1]=bfr[1][1];
            bv[3][0]=bfr[1][2]; bv[3][1]=bfr[1][3];
            #pragma unroll
            for (int nt = 0; nt < 4; nt++)
                mma_f16(s[nt], a, bv[nt]);
        }

        #pragma unroll
        for (int nt = 0; nt < 4; nt++)
            #pragma unroll
            for (int i = 0; i < 4; i++) s[nt][i] *= 0.125f;
        if (kb*32 + 31 > q0 + m0) {
            #pragma unroll
            for (int nt = 0; nt < 4; nt++) {
                int c0 = kb*32 + nt*8 + 2*lq;
                if (c0   > rg0) s[nt][0] = -1e30f;
                if (c0+1 > rg0) s[nt][1] = -1e30f;
                if (c0   > rg1) s[nt][2] = -1e30f;
                if (c0+1 > rg1) s[nt][3] = -1e30f;
            }
        }

        float mx0 = -1e30f, mx1 = -1e30f;
        #pragma unroll
        for (int nt = 0; nt < 4; nt++) {
            mx0 = fmaxf(mx0, fmaxf(s[nt][0], s[nt][1]));
            mx1 = fmaxf(mx1, fmaxf(s[nt][2], s[nt][3]));
        }
        mx0 = fmaxf(mx0, __shfl_xor_sync(0xffffffffu, mx0, 1));
        mx0 = fmaxf(mx0, __shfl_xor_sync(0xffffffffu, mx0, 2));
        mx1 = fmaxf(mx1, __shfl_xor_sync(0xffffffffu, mx1, 1));
        mx1 = fmaxf(mx1, __shfl_xor_sync(0xffffffffu, mx1, 2));
        float mn0 = fmaxf(mrow0, mx0), mn1 = fmaxf(mrow1, mx1);
        float corr0 = __expf(mrow0 - mn0), corr1 = __expf(mrow1 - mn1);
        float sum0 = 0.f, sum1 = 0.f;
        #pragma unroll
        for (int nt = 0; nt < 4; nt++) {
            s[nt][0] = __expf(s[nt][0] - mn0);
            s[nt][1] = __expf(s[nt][1] - mn0);
            s[nt][2] = __expf(s[nt][2] - mn1);
            s[nt][3] = __expf(s[nt][3] - mn1);
            sum0 += s[nt][0] + s[nt][1];
            sum1 += s[nt][2] + s[nt][3];
        }
        sum0 += __shfl_xor_sync(0xffffffffu, sum0, 1);
        sum0 += __shfl_xor_sync(0xffffffffu, sum0, 2);
        sum1 += __shfl_xor_sync(0xffffffffu, sum1, 1);
        sum1 += __shfl_xor_sync(0xffffffffu, sum1, 2);
        lrow0 = lrow0*corr0 + sum0;
        lrow1 = lrow1*corr1 + sum1;
        mrow0 = mn0; mrow1 = mn1;
        #pragma unroll
        for (int nt = 0; nt < 8; nt++) {
            o[nt][0] *= corr0; o[nt][1] *= corr0;
            o[nt][2] *= corr1; o[nt][3] *= corr1;
        }

        #pragma unroll
        for (int nt = 0; nt < 4; nt++) {
            *(__half2*)&Ps[(m0+lr)*PH_STR + nt*8+2*lq]   = __floats2half2_rn(s[nt][0], s[nt][1]);
            *(__half2*)&Ps[(m0+lr+8)*PH_STR + nt*8+2*lq] = __floats2half2_rn(s[nt][2], s[nt][3]);
        }
        __syncwarp();

        #pragma unroll
        for (int ks = 0; ks < 2; ks++) {
            const int kk = ks * 16;
            unsigned a[4];
            ldsm4(a, pbb + ((m0 + a_row)*PH_STR + kk + a_col)*2);
            #pragma unroll
            for (int ng = 0; ng < 4; ng++) {
                unsigned r[4];
                ldsm4t(r, vbb + ((kk + bf_row)*VH_STR + ng*16 + bf_col)*2);
                unsigned b0[2] = { r[0], r[1] };
                unsigned b1[2] = { r[2], r[3] };
                mma_f16(o[ng*2],   a, b0);
                mma_f16(o[ng*2+1], a, b1);
            }
        }
    }

    float inv0 = 1.f / lrow0, inv1 = 1.f / lrow1;
    #pragma unroll
    for (int nt = 0; nt < 8; nt++) {
        int cg = h*64 + nt*8 + 2*lq;
        size_t base0 = (size_t)(b*TT + rg0)*DD + cg;
        size_t base1 = (size_t)(b*TT + rg1)*DD + cg;
        ((__half2*)out)[base0>>1] = __floats2half2_rn(o[nt][0]*inv0, o[nt][1]*inv0);
        ((__half2*)out)[base1>>1] = __floats2half2_rn(o[nt][2]*inv1, o[nt][3]*inv1);
    }
}

// ---------------------------------------------------------------------------
// Router logits (fp32 xn)
// ---------------------------------------------------------------------------
__global__ void router_kernel(const float* __restrict__ xn,
                              const float* __restrict__ rw,
                              float* __restrict__ logits)
{
    int n = blockIdx.x;
    int warp = threadIdx.x >> 5, lane = threadIdx.x & 31;
    const float* xp = xn + (size_t)n*DD;
    for (int j = 0; j < 4; j++) {
        int e = warp*4 + j;
        const float* wp = rw + (size_t)e*DD;
        float s = 0.f;
        for (int i = lane; i < DD; i += 32) s += xp[i]*wp[i];
        #pragma unroll
        for (int off = 16; off; off >>= 1) s += __shfl_xor_sync(0xffffffffu, s, off);
        if (lane == 0) logits[n*EE + e] = s;
    }
}

__global__ void top2_kernel(const float* __restrict__ logits,
                            float* __restrict__ probs,
                            int* __restrict__ topi, float* __restrict__ topw)
{
    int n = blockIdx.x*blockDim.x + threadIdx.x;
    if (n >= NTOK) return;
    float l[EE];
    float mx = -1e30f;
    #pragma unroll
    for (int e = 0; e < EE; e++) { l[e] = logits[n*EE+e]; mx = fmaxf(mx, l[e]); }
    float sum = 0.f;
    #pragma unroll
    for (int e = 0; e < EE; e++) { l[e] = __expf(l[e]-mx); sum += l[e]; }
    float inv = 1.f/sum;
    #pragma unroll
    for (int e = 0; e < EE; e++) { l[e] *= inv; probs[n*EE+e] = l[e]; }
    int i0 = 0; float p0 = l[0];
    #pragma unroll
    for (int e = 1; e < EE; e++) if (l[e] > p0) { p0 = l[e]; i0 = e; }
    int i1 = (i0 == 0) ? 1 : 0; float p1 = l[i1];
    #pragma unroll
    for (int e = 0; e < EE; e++) if (e != i0 && l[e] > p1) { p1 = l[e]; i1 = e; }
    float ws = p0 + p1;
    topi[n*2]   = i0; topi[n*2+1] = i1;
    topw[n*2]   = p0/ws; topw[n*2+1] = p1/ws;
}

__global__ void pmean_kernel(const float* __restrict__ probs, float* __restrict__ pmean)
{
    int e = blockIdx.x, tid = threadIdx.x;
    float s = 0.f;
    for (int t = tid; t < NTOK; t += 256) s += probs[t*EE + e];
    __shared__ float red[256];
    red[tid] = s;
    __syncthreads();
    for (int k = 128; k; k >>= 1) {
        if (tid < k) red[tid] += red[tid+k];
        __syncthreads();
    }
    if (tid == 0) pmean[e] = red[0] / (float)NTOK;
}

__global__ void assign_kernel(const int* __restrict__ topi,
                              const float* __restrict__ topw,
                              int* __restrict__ slot, int* __restrict__ keep,
                              float* __restrict__ wcomb, int* __restrict__ counts)
{
    int e = blockIdx.x;
    int tid = threadIdx.x;
    int lane = tid & 31, warp = tid >> 5;
    __shared__ int warpsum[8];
    int running = 0;
    for (int base = 0; base < NFLAT; base += 256) {
        int i = base + tid;
        int match = (topi[i] == e) ? 1 : 0;
        unsigned mask = __ballot_sync(0xffffffffu, match);
        if (lane == 0) warpsum[warp] = __popc(mask);
        __syncthreads();
        int wbase = 0, tot = 0;
        #pragma unroll
        for (int w = 0; w < 8; w++) {
            int c = warpsum[w];
            if (w < warp) wbase += c;
            tot += c;
        }
        if (match) {
            int pos = running + wbase + __popc(mask & ((1u << lane) - 1u));
            int kp = (pos < CAP) ? 1 : 0;
            slot[i]  = (pos < CAP-1) ? pos : (CAP-1);
            keep[i]  = kp;
            wcomb[i] = kp ? topw[i] : 0.f;
        }
        running += tot;
        __syncthreads();
    }
    if (tid == 0) counts[e] = running;
}

__global__ void scatter_kernel(const int* __restrict__ topi,
                               const int* __restrict__ slot,
                               const int* __restrict__ keep,
                               const __half* __restrict__ xn,
                               __half* __restrict__ buf)
{
    int i = blockIdx.x;
    if (!keep[i]) return;
    int e = topi[i], s = slot[i], tok = i >> 1;
    const uint2* src = (const uint2*)(xn + (size_t)tok*DD);
    uint2* dst = (uint2*)(buf + ((size_t)e*CAP + s)*DD);
    dst[threadIdx.x] = src[threadIdx.x];
}

__global__ void gather_kernel(const int* __restrict__ topi,
                              const int* __restrict__ slot,
                              const float* __restrict__ wcomb,
                              const float* __restrict__ yb,
                              float* __restrict__ x)
{
    int n = blockIdx.x;
    int t4 = threadIdx.x;
    float4* xp = (float4*)(x + (size_t)n*DD);
    float4 a = xp[t4];
    #pragma unroll
    for (int k = 0; k < 2; k++) {
        int i = n*2 + k;
        float w = wcomb[i];
        if (w != 0.f) {
            int e = topi[i], s = slot[i];
            const float4* yp = (const float4*)(yb + ((size_t)e*CAP + s)*DD);
            float4 yv = yp[t4];
            a.x += w*yv.x; a.y += w*yv.y; a.z += w*yv.z; a.w += w*yv.w;
        }
    }
    xp[t4] = a;
}

__global__ void aux_kernel(const int* __restrict__ counts,
                           const float* __restrict__ pmean,
                           float* __restrict__ out, int out_size)
{
    if (threadIdx.x == 0 && out_size > NTOK*DD) {
        float s = 0.f;
        for (int e = 0; e < EE; e++)
            s += ((float)counts[e] / (float)NTOK) * pmean[e];
        out[NTOK*DD] = (float)EE * s;
    }
}

__global__ void gate_kernel(const __half* __restrict__ xn,
                            const float* __restrict__ gw,
                            const float* __restrict__ gb,
                            float* __restrict__ gate)
{
    int n = blockIdx.x, tid = threadIdx.x;
    const __half2* xp = (const __half2*)(xn + (size_t)n*DD);
    const float4* wp = (const float4*)gw;
    float2 f0 = __half22float2(xp[2*tid]);
    float2 f1 = __half22float2(xp[2*tid+1]);
    float4 wv = wp[tid];
    float s = f0.x*wv.x + f0.y*wv.y + f1.x*wv.z + f1.y*wv.w;
    __shared__ float red[256];
    red[tid] = s;
    __syncthreads();
    for (int k = 128; k; k >>= 1) {
        if (tid < k) red[tid] += red[tid+k];
        __syncthreads();
    }
    if (tid == 0) gate[n] = 1.f / (1.f + __expf(-(red[0] + gb[0])));
}

__global__ void softmax512_kernel(const float* __restrict__ tl, __half* __restrict__ outh)
{
    int n = blockIdx.x, tid = threadIdx.x;
    const float* row = tl + (size_t)n*NPRIM;
    __half* orow = outh + (size_t)n*NPRIM;
    float v0 = row[tid]       * 0.0625f;
    float v1 = row[tid + 256] * 0.0625f;
    __shared__ float red[256];
    red[tid] = fmaxf(v0, v1);
    __syncthreads();
    for (int s = 128; s; s >>= 1) {
        if (tid < s) red[tid] = fmaxf(red[tid], red[tid+s]);
        __syncthreads();
    }
    float mx = red[0];
    __syncthreads();
    v0 = __expf(v0 - mx); v1 = __expf(v1 - mx);
    red[tid] = v0 + v1;
    __syncthreads();
    for (int s = 128; s; s >>= 1) {
        if (tid < s) red[tid] += red[tid+s];
        __syncthreads();
    }
    float inv = 1.f / red[0];
    orow[tid]       = __float2half_rn(v0*inv);
    orow[tid + 256] = __float2half_rn(v1*inv);
}

// ---------------------------------------------------------------------------
// Host launch
// ---------------------------------------------------------------------------
#define F2H(stream, src, dst, n) f2h_kernel<<<(n)/2048, 256, 0, stream>>>(src, dst)

extern "C" void kernel_launch(void* const* d_in, const int* in_sizes, int n_in,
                              void* d_out, int out_size)
{
    const float* x          = (const float*)d_in[0];
    const float* tou_embeds = (const float*)d_in[1];
    const float* norm1_w    = (const float*)d_in[2];
    const float* qkv_w      = (const float*)d_in[3];
    const float* attn_o_w   = (const float*)d_in[4];
    const float* norm2_w    = (const float*)d_in[5];
    const float* router_w   = (const float*)d_in[6];
    const float* moe_w1     = (const float*)d_in[7];
    const float* moe_w2     = (const float*)d_in[8];
    const float* norm3_w    = (const float*)d_in[9];
    const float* tou_q_w    = (const float*)d_in[10];
    const float* tou_k_w    = (const float*)d_in[11];
    const float* tou_v_w    = (const float*)d_in[12];
    const float* tou_o_w    = (const float*)d_in[13];
    const float* tou_gate_w = (const float*)d_in[14];
    const float* tou_gate_b = (const float*)d_in[15];

    cudaFuncSetAttribute(gemm_h<true,0,false>,  cudaFuncAttributeMaxDynamicSharedMemorySize, SMEM_HBT);
    cudaFuncSetAttribute(gemm_h<true,0,true>,   cudaFuncAttributeMaxDynamicSharedMemorySize, SMEM_HBT);
    cudaFuncSetAttribute(gemm_h<true,4,false>,  cudaFuncAttributeMaxDynamicSharedMemorySize, SMEM_HBT);
    cudaFuncSetAttribute(gemm_h<true,5,false>,  cudaFuncAttributeMaxDynamicSharedMemorySize, SMEM_HBT);
    cudaFuncSetAttribute(gemm_h<false,0,false>, cudaFuncAttributeMaxDynamicSharedMemorySize, SMEM_HKN);
    cudaFuncSetAttribute(gemm_h<false,0,true>,  cudaFuncAttributeMaxDynamicSharedMemorySize, SMEM_HKN);
    cudaFuncSetAttribute(gemm_h<false,2,true>,  cudaFuncAttributeMaxDynamicSharedMemorySize, SMEM_HKN);
    cudaFuncSetAttribute(flash_attn_h,          cudaFuncAttributeMaxDynamicSharedMemorySize, FLASHH_SMEM);

    float *gx, *gxn, *glogits, *gprobs, *gtopw, *gwcomb, *gpmean, *gyb, *gtl, *ggate;
    int *gtopi, *gslot, *gkeep, *gcounts;
    __half *hqkv, *hxn, *hattn, *hbuf, *hh, *htq, *htk, *htv, *htl, *htout;
    __half *hqkvw, *haow, *hw1, *hw2, *htqw, *htkw, *htvw, *htow, *hemb;
    cudaGetSymbolAddress((void**)&gx, g_x);
    cudaGetSymbolAddress((void**)&gxn, g_xn);
    cudaGetSymbolAddress((void**)&glogits, g_logits);
    cudaGetSymbolAddress((void**)&gprobs, g_probs);
    cudaGetSymbolAddress((void**)&gtopi, g_topi);
    cudaGetSymbolAddress((void**)&gtopw, g_topw);
    cudaGetSymbolAddress((void**)&gslot, g_slot);
    cudaGetSymbolAddress((void**)&gkeep, g_keep);
    cudaGetSymbolAddress((void**)&gwcomb, g_wcomb);
    cudaGetSymbolAddress((void**)&gcounts, g_counts);
    cudaGetSymbolAddress((void**)&gpmean, g_pmean);
    cudaGetSymbolAddress((void**)&gyb, g_yb);
    cudaGetSymbolAddress((void**)&gtl, g_tl);
    cudaGetSymbolAddress((void**)&ggate, g_gate);
    cudaGetSymbolAddress((void**)&hqkv, gh_qkv);
    cudaGetSymbolAddress((void**)&hxn, gh_xn);
    cudaGetSymbolAddress((void**)&hattn, gh_attn);
    cudaGetSymbolAddress((void**)&hbuf, gh_buf);
    cudaGetSymbolAddress((void**)&hh, gh_h);
    cudaGetSymbolAddress((void**)&htq, gh_tq);
    cudaGetSymbolAddress((void**)&htk, gh_tk);
    cudaGetSymbolAddress((void**)&htv, gh_tv);
    cudaGetSymbolAddress((void**)&htl, gh_tl);
    cudaGetSymbolAddress((void**)&htout, gh_tout);
    cudaGetSymbolAddress((void**)&hqkvw, gh_qkvw);
    cudaGetSymbolAddress((void**)&haow, gh_aow);
    cudaGetSymbolAddress((void**)&hw1, gh_w1);
    cudaGetSymbolAddress((void**)&hw2, gh_w2);
    cudaGetSymbolAddress((void**)&htqw, gh_tqw);
    cudaGetSymbolAddress((void**)&htkw, gh_tkw);
    cudaGetSymbolAddress((void**)&htvw, gh_tvw);
    cudaGetSymbolAddress((void**)&htow, gh_tow);
    cudaGetSymbolAddress((void**)&hemb, gh_emb);

    cudaEventRecord(ev_root, 0);

    // ---- s1: rope table, ToU weight conversions + tiny GEMMs ----
    cudaStreamWaitEvent(s1, ev_root, 0);
    rope_table_kernel<<<TT*32/256, 256, 0, s1>>>();
    cudaEventRecord(ev_tab, s1);
    F2H(s1, tou_embeds, hemb, NPRIM*DP);
    F2H(s1, tou_k_w, htkw, DP*DP);
    F2H(s1, tou_v_w, htvw, DP*DP);
    F2H(s1, tou_q_w, htqw, DP*DD);
    F2H(s1, tou_o_w, htow, DD*DP);
    gemm_h<true,0,true><<<dim3(DP/128, NPRIM/128, 1), 256, SMEM_HBT, s1>>>(
        hemb, htkw, htk, NPRIM, DP, DP, 0, 0, 0, nullptr, nullptr);
    gemm_h<true,0,true><<<dim3(DP/128, NPRIM/128, 1), 256, SMEM_HBT, s1>>>(
        hemb, htvw, htv, NPRIM, DP, DP, 0, 0, 0, nullptr, nullptr);
    cudaEventRecord(ev_s1, s1);

    // ---- s2: qkv_w + attn_o conversions, gbuf memset, MoE weight conversions ----
    cudaStreamWaitEvent(s2, ev_root, 0);
    F2H(s2, qkv_w, hqkvw, 3*DD*DD);
    cudaEventRecord(ev_qkvw, s2);
    F2H(s2, attn_o_w, haow, DD*DD);
    cudaEventRecord(ev_aow, s2);
    cudaMemsetAsync(hbuf, 0, (size_t)EE*CAP*DD*sizeof(__half), s2);
    F2H(s2, moe_w1, hw1, EE*DD*FF);
    F2H(s2, moe_w2, hw2, EE*FF*DD);
    cudaEventRecord(ev_s2, s2);

    // ---- Block 1 ----
    rmsnorm_h<<<NTOK, 256>>>(x, norm1_w, hxn, nullptr);
    cudaStreamWaitEvent(0, ev_qkvw, 0);
    gemm_h<true,0,true><<<dim3(3*DD/128, NTOK/128, 1), 256, SMEM_HBT>>>(
        hxn, hqkvw, hqkv, NTOK, 3*DD, DD, 0, 0, 0, nullptr, nullptr);
    cudaStreamWaitEvent(0, ev_tab, 0);
    rope_hh<<<NTOK, 256>>>(hqkv);
    flash_attn_h<<<dim3(TT/128, BB*HH), 256, FLASHH_SMEM>>>(hqkv, hattn);
    cudaStreamWaitEvent(0, ev_aow, 0);
    gemm_h<true,4,false><<<dim3(DD/128, NTOK/128, 1), 256, SMEM_HBT>>>(
        hattn, haow, gx, NTOK, DD, DD, 0, 0, 0, nullptr, x);   // gx = x + proj

    // ---- Block 2: MoE ----
    rmsnorm_h<<<NTOK, 256>>>(gx, norm2_w, hxn, gxn);
    router_kernel<<<NTOK, 128>>>(gxn, router_w, glogits);
    top2_kernel<<<NTOK/128, 128>>>(glogits, gprobs, gtopi, gtopw);
    cudaEventRecord(ev_top2, 0);
    cudaStreamWaitEvent(s2, ev_top2, 0);
    pmean_kernel<<<EE, 256, 0, s2>>>(gprobs, gpmean);
    cudaEventRecord(ev_pm, s2);
    assign_kernel<<<EE, 256>>>(gtopi, gtopw, gslot, gkeep, gwcomb, gcounts);
    cudaStreamWaitEvent(0, ev_s2, 0);
    scatter_kernel<<<NFLAT, 256>>>(gtopi, gslot, gkeep, hxn, hbuf);
    gemm_h<false,2,true><<<dim3(FF/128, CAP/128, EE), 256, SMEM_HKN>>>(
        hbuf, hw1, hh, CAP, FF, DD,
        (long long)CAP*DD, (long long)DD*FF, (long long)CAP*FF, nullptr, nullptr);
    gemm_h<false,0,false><<<dim3(DD/128, CAP/128, EE), 256, SMEM_HKN>>>(
        hh, hw2, gyb, CAP, DD, FF,
        (long long)CAP*FF, (long long)FF*DD, (long long)CAP*DD, nullptr, nullptr);
    gather_kernel<<<NTOK, 256>>>(gtopi, gslot, gwcomb, gyb, gx);
    cudaStreamWaitEvent(0, ev_pm, 0);
    aux_kernel<<<1, 32>>>(gcounts, gpmean, (float*)d_out, out_size);

    // ---- Block 3: ToU cross-attention ----
    rmsnorm_h<<<NTOK, 256>>>(gx, norm3_w, hxn, nullptr);
    cudaEventRecord(ev_n3, 0);
    cudaStreamWaitEvent(s2, ev_n3, 0);
    gate_kernel<<<NTOK, 256, 0, s2>>>(hxn, tou_gate_w, tou_gate_b, ggate);
    cudaEventRecord(ev_gate, s2);
    cudaStreamWaitEvent(0, ev_s1, 0);
    gemm_h<true,0,true><<<dim3(DP/128, NTOK/128, 1), 256, SMEM_HBT>>>(
        hxn, htqw, htq, NTOK, DP, DD, 0, 0, 0, nullptr, nullptr);
    gemm_h<true,0,false><<<dim3(NPRIM/128, NTOK/128, 1), 256, SMEM_HBT>>>(
        htq, htk, gtl, NTOK, NPRIM, DP, 0, 0, 0, nullptr, nullptr);
    softmax512_kernel<<<NTOK, 256>>>(gtl, htl);
    gemm_h<false,0,true><<<dim3(DP/128, NTOK/128, 1), 256, SMEM_HKN>>>(
        htl, htv, htout, NTOK, DP, NPRIM, 0, 0, 0, nullptr, nullptr);
    cudaStreamWaitEvent(0, ev_gate, 0);
    gemm_h<true,5,false><<<dim3(DD/128, NTOK/128, 1), 256, SMEM_HBT>>>(
        htout, htow, (float*)d_out, NTOK, DD, DP, 0, 0, 0, ggate, gx);
}

// round 15
// speedup vs baseline: 1.5424x; 1.0506x over previous
#include <cuda_runtime.h>
#include <cuda_bf16.h>
#include <cuda_fp16.h>
#include <math.h>

// ---------------------------------------------------------------------------
// Problem constants
// ---------------------------------------------------------------------------
#define BB 2
#define TT 2048
#define DD 1024
#define HH 16
#define DH 64
#define NTOK (BB*TT)            // 4096
#define EE 16
#define KK 2
#define FF 2048
#define CAP 640
#define DP 256
#define NPRIM 512
#define NFLAT (NTOK*KK)         // 8192

// ---------------------------------------------------------------------------
// Scratch (device globals; no allocation allowed)
// ---------------------------------------------------------------------------
__device__ float g_x[NTOK*DD];
__device__ float g_xn[NTOK*DD];          // fp32 xn (router)
__device__ float g_logits[NTOK*EE];
__device__ float g_probs[NTOK*EE];
__device__ int   g_topi[NFLAT];
__device__ float g_topw[NFLAT];
__device__ int   g_slot[NFLAT];
__device__ int   g_keep[NFLAT];
__device__ float g_wcomb[NFLAT];
__device__ int   g_counts[EE];
__device__ float g_pmean[EE];
__device__ float g_yb[EE*CAP*DD];
__device__ float g_tl[NTOK*NPRIM];
__device__ float g_gate[NTOK];
__device__ float g_ropec[TT*32];
__device__ float g_ropes[TT*32];

// fp16 buffers
__device__ __half gh_qkv[NTOK*3*DD];
__device__ __half gh_xn[NTOK*DD];
__device__ __half gh_attn[NTOK*DD];
__device__ __half gh_buf[EE*CAP*DD];
__device__ __half gh_h[EE*CAP*FF];
__device__ __half gh_tq[NTOK*DP];
__device__ __half gh_tk[NPRIM*DP];
__device__ __half gh_tv[NPRIM*DP];
__device__ __half gh_tl[NTOK*NPRIM];
__device__ __half gh_tout[NTOK*DP];
// fp16 weights (converted once per launch)
__device__ __half gh_qkvw[3*DD*DD];
__device__ __half gh_aow[DD*DD];
__device__ __half gh_w1[EE*DD*FF];
__device__ __half gh_w2[EE*FF*DD];
__device__ __half gh_tqw[DP*DD];
__device__ __half gh_tkw[DP*DP];
__device__ __half gh_tvw[DP*DP];
__device__ __half gh_tow[DD*DP];
__device__ __half gh_emb[NPRIM*DP];

// ---------------------------------------------------------------------------
// Streams / events (host resources, created once)
// ---------------------------------------------------------------------------
static cudaStream_t s1, s2;
static cudaEvent_t ev_root, ev_tab, ev_s1, ev_s2, ev_qkvw, ev_aow,
                   ev_top2, ev_asn, ev_n3, ev_gate;
namespace {
struct InitOnce {
    InitOnce() {
        cudaStreamCreateWithFlags(&s1, cudaStreamNonBlocking);
        cudaStreamCreateWithFlags(&s2, cudaStreamNonBlocking);
        cudaEventCreateWithFlags(&ev_root, cudaEventDisableTiming);
        cudaEventCreateWithFlags(&ev_tab,  cudaEventDisableTiming);
        cudaEventCreateWithFlags(&ev_s1,   cudaEventDisableTiming);
        cudaEventCreateWithFlags(&ev_s2,   cudaEventDisableTiming);
        cudaEventCreateWithFlags(&ev_qkvw, cudaEventDisableTiming);
        cudaEventCreateWithFlags(&ev_aow,  cudaEventDisableTiming);
        cudaEventCreateWithFlags(&ev_top2, cudaEventDisableTiming);
        cudaEventCreateWithFlags(&ev_asn,  cudaEventDisableTiming);
        cudaEventCreateWithFlags(&ev_n3,   cudaEventDisableTiming);
        cudaEventCreateWithFlags(&ev_gate, cudaEventDisableTiming);
    }
};
static InitOnce init_once_;
}

// ---------------------------------------------------------------------------
// MMA / cp.async / ldmatrix helpers
// ---------------------------------------------------------------------------
__device__ __forceinline__ void mma_f16(float c[4], const unsigned a[4], const unsigned b[2])
{
    asm volatile(
        "mma.sync.aligned.m16n8k16.row.col.f32.f16.f16.f32 "
        "{%0,%1,%2,%3},{%4,%5,%6,%7},{%8,%9},{%0,%1,%2,%3};"
        : "+f"(c[0]), "+f"(c[1]), "+f"(c[2]), "+f"(c[3])
        : "r"(a[0]), "r"(a[1]), "r"(a[2]), "r"(a[3]),
          "r"(b[0]), "r"(b[1]));
}

__device__ __forceinline__ void ldsm4(unsigned r[4], unsigned addr)
{
    asm volatile("ldmatrix.sync.aligned.m8n8.x4.shared.b16 {%0,%1,%2,%3}, [%4];"
        : "=r"(r[0]), "=r"(r[1]), "=r"(r[2]), "=r"(r[3]) : "r"(addr));
}
__device__ __forceinline__ void ldsm4t(unsigned r[4], unsigned addr)
{
    asm volatile("ldmatrix.sync.aligned.m8n8.x4.trans.shared.b16 {%0,%1,%2,%3}, [%4];"
        : "=r"(r[0]), "=r"(r[1]), "=r"(r[2]), "=r"(r[3]) : "r"(addr));
}

__device__ __forceinline__ void cp16(void* smem_dst, const void* gptr)
{
    unsigned saddr = (unsigned)__cvta_generic_to_shared(smem_dst);
    asm volatile("cp.async.cg.shared.global [%0], [%1], 16;\n"
                 :: "r"(saddr), "l"(gptr));
}
__device__ __forceinline__ void cp_commit()  { asm volatile("cp.async.commit_group;\n"); }
__device__ __forceinline__ void cp_wait2()   { asm volatile("cp.async.wait_group 2;\n"); }
__device__ __forceinline__ void cp_wait1()   { asm volatile("cp.async.wait_group 1;\n"); }
__device__ __forceinline__ void cp_wait0()   { asm volatile("cp.async.wait_group 0;\n"); }

// ---------------------------------------------------------------------------
// f32 -> f16 conversion (n % 2048 == 0)
// ---------------------------------------------------------------------------
__global__ void f2h_kernel(const float* __restrict__ in, __half* __restrict__ out)
{
    int i = (blockIdx.x*256 + threadIdx.x) * 8;
    float4 v0 = *(const float4*)(in + i);
    float4 v1 = *(const float4*)(in + i + 4);
    __half2* o = (__half2*)(out + i);
    o[0] = __floats2half2_rn(v0.x, v0.y);
    o[1] = __floats2half2_rn(v0.z, v0.w);
    o[2] = __floats2half2_rn(v1.x, v1.y);
    o[3] = __floats2half2_rn(v1.z, v1.w);
}

// ---------------------------------------------------------------------------
// RMSNorm: one block per token; fp16 out (+optional fp32 out)
// ---------------------------------------------------------------------------
__global__ void rmsnorm_h(const float* __restrict__ x,
                          const float* __restrict__ w,
                          __half* __restrict__ outh,
                          float* __restrict__ outf)
{
    int n = blockIdx.x;
    int tid = threadIdx.x;
    const float4* xp = (const float4*)(x + (size_t)n*DD);
    float4 xv = xp[tid];
    float ss = xv.x*xv.x + xv.y*xv.y + xv.z*xv.z + xv.w*xv.w;
    __shared__ float red[256];
    red[tid] = ss;
    __syncthreads();
    for (int s = 128; s; s >>= 1) {
        if (tid < s) red[tid] += red[tid+s];
        __syncthreads();
    }
    float scale = rsqrtf(red[0] / (float)DD + 1e-6f);
    const float4* wp = (const float4*)w;
    float4 wv = wp[tid];
    float a = xv.x*scale*wv.x, b = xv.y*scale*wv.y;
    float c = xv.z*scale*wv.z, d = xv.w*scale*wv.w;
    __half2* oh = (__half2*)(outh + (size_t)n*DD);
    oh[2*tid]   = __floats2half2_rn(a, b);
    oh[2*tid+1] = __floats2half2_rn(c, d);
    if (outf) ((float4*)(outf + (size_t)n*DD))[tid] = make_float4(a, b, c, d);
}

// ---------------------------------------------------------------------------
// FP16 tensor-core GEMM (m16n8k16): 4-stage cp.async, ldmatrix fragments.
// EPI: 0=store, 2=silu store, 4=C=Xin+v, 5=C=Xin+gate*v;  OUTH: __half out
// cnt: optional per-z row-count (skip row-blocks >= min(cnt, M))
// ---------------------------------------------------------------------------
#define AH_STR 40
#define BH_STR 136
#define NSTG 4
#define AH_TILE (128*AH_STR)
#define BH_TILE (32*BH_STR)

template<bool BT, int EPI, bool OUTH>
__global__ __launch_bounds__(256, 2)
void gemm_h(const __half* __restrict__ A, const __half* __restrict__ Bm,
            void* __restrict__ Cv, int M, int N, int K,
            long long sA, long long sB, long long sC,
            const float* __restrict__ gate, const float* __restrict__ Xin,
            const int* __restrict__ cnt)
{
    const int row0 = blockIdx.y * 128, col0 = blockIdx.x * 128;
    if (cnt) {
        int c = cnt[blockIdx.z];
        if (c > M) c = M;
        if (row0 >= c) return;        // rows never consumed downstream
    }

    A  += blockIdx.z * sA;
    Bm += blockIdx.z * sB;

    extern __shared__ __half smem_h[];
    __half* AsP = smem_h;
    __half* BsP = smem_h + NSTG*AH_TILE;
    const unsigned sbase = (unsigned)__cvta_generic_to_shared(smem_h);
    const unsigned bbase = sbase + NSTG*AH_TILE*2;

    const int tid  = threadIdx.x;
    const int lane = tid & 31;
    const int warp = tid >> 5;
    const int lr   = lane >> 2;
    const int lq   = lane & 3;
    const int g    = lane >> 3;
    const int tr   = lane & 7;
    const int wm   = warp & 1, wn = warp >> 1;
    const int m0   = wm * 64, n0 = wn * 32;

    const int c0i = tid, c1i = tid + 256;
    const int ar0 = c0i >> 2, ac0 = (c0i & 3) * 8;
    const int ar1 = c1i >> 2, ac1 = (c1i & 3) * 8;
    const int fr0 = c0i >> 4, fo0 = (c0i & 15) * 8;
    const int fr1 = c1i >> 4, fo1 = (c1i & 15) * 8;

    const int nIter = K >> 5;

    auto issue = [&](int stg, int k0) {
        cp16(&AsP[stg*AH_TILE + ar0*AH_STR + ac0], A + (size_t)(row0 + ar0) * K + k0 + ac0);
        cp16(&AsP[stg*AH_TILE + ar1*AH_STR + ac1], A + (size_t)(row0 + ar1) * K + k0 + ac1);
        if constexpr (BT) {
            cp16(&BsP[stg*AH_TILE + ar0*AH_STR + ac0], Bm + (size_t)(col0 + ar0) * K + k0 + ac0);
            cp16(&BsP[stg*AH_TILE + ar1*AH_STR + ac1], Bm + (size_t)(col0 + ar1) * K + k0 + ac1);
        } else {
            cp16(&BsP[stg*BH_TILE + fr0*BH_STR + fo0], Bm + (size_t)(k0 + fr0) * N + col0 + fo0);
            cp16(&BsP[stg*BH_TILE + fr1*BH_STR + fo1], Bm + (size_t)(k0 + fr1) * N + col0 + fo1);
        }
        cp_commit();
    };

    issue(0, 0);
    if (nIter > 1) issue(1, 32);
    if (nIter > 2) issue(2, 64);

    float c[4][4][4];
    #pragma unroll
    for (int mt = 0; mt < 4; mt++)
        #pragma unroll
        for (int nt = 0; nt < 4; nt++)
            #pragma unroll
            for (int i = 0; i < 4; i++) c[mt][nt][i] = 0.f;

    const int a_row = (g & 1) * 8 + tr;
    const int a_col = (g >> 1) * 8;
    const int bt_row = (g >> 1) * 8 + tr;
    const int bt_col = (g & 1) * 8;
    const int bf_row = (g & 1) * 8 + tr;
    const int bf_col = (g >> 1) * 8;

    for (int it = 0; it < nIter; it++) {
        if (it + 2 < nIter)      cp_wait2();
        else if (it + 1 < nIter) cp_wait1();
        else                     cp_wait0();
        __syncthreads();

        if (it + 3 < nIter) issue((it + 3) & 3, (it + 3) << 5);

        const int st = it & 3;
        const unsigned abase = sbase + st*AH_TILE*2;
        const unsigned btb   = bbase + (BT ? st*AH_TILE*2 : st*BH_TILE*2);

        #pragma unroll
        for (int ks = 0; ks < 2; ks++) {
            const int kb = ks * 16;
            unsigned a[4][4];
            #pragma unroll
            for (int mt = 0; mt < 4; mt++) {
                unsigned addr = abase + ((m0 + mt*16 + a_row)*AH_STR + kb + a_col)*2;
                ldsm4(a[mt], addr);
            }
            unsigned b[4][2];
            #pragma unroll
            for (int ntp = 0; ntp < 2; ntp++) {
                unsigned r[4];
                if constexpr (BT) {
                    unsigned addr = btb + ((n0 + ntp*16 + bt_row)*AH_STR + kb + bt_col)*2;
                    ldsm4(r, addr);
                } else {
                    unsigned addr = btb + ((kb + bf_row)*BH_STR + n0 + ntp*16 + bf_col)*2;
                    ldsm4t(r, addr);
                }
                b[ntp*2][0]   = r[0]; b[ntp*2][1]   = r[1];
                b[ntp*2+1][0] = r[2]; b[ntp*2+1][1] = r[3];
            }
            #pragma unroll
            for (int mt = 0; mt < 4; mt++)
                #pragma unroll
                for (int nt = 0; nt < 4; nt++)
                    mma_f16(c[mt][nt], a[mt], b[nt]);
        }
    }

    float* Cf = (float*)Cv + (OUTH ? 0 : blockIdx.z * sC);
    __half* Ch = (__half*)Cv + (OUTH ? blockIdx.z * sC : 0);
    #pragma unroll
    for (int mt = 0; mt < 4; mt++) {
        int r0g = row0 + m0 + mt * 16 + lr;
        int r1g = r0g + 8;
        float g0 = (EPI == 5) ? gate[r0g] : 0.f;
        float g1 = (EPI == 5) ? gate[r1g] : 0.f;
        #pragma unroll
        for (int nt = 0; nt < 4; nt++) {
            int cg = col0 + n0 + nt * 8 + 2 * lq;
            size_t i0 = (size_t)r0g * N + cg;
            size_t i1 = (size_t)r1g * N + cg;
            float v0 = c[mt][nt][0], v1 = c[mt][nt][1];
            float v2 = c[mt][nt][2], v3 = c[mt][nt][3];
            if (EPI == 2) {
                v0 = v0 / (1.f + __expf(-v0));
                v1 = v1 / (1.f + __expf(-v1));
                v2 = v2 / (1.f + __expf(-v2));
                v3 = v3 / (1.f + __expf(-v3));
            } else if (EPI == 4) {
                float2 x0 = *(const float2*)&Xin[i0];
                float2 x1 = *(const float2*)&Xin[i1];
                v0 += x0.x; v1 += x0.y; v2 += x1.x; v3 += x1.y;
            } else if (EPI == 5) {
                float2 x0 = *(const float2*)&Xin[i0];
                float2 x1 = *(const float2*)&Xin[i1];
                v0 = x0.x + g0*v0; v1 = x0.y + g0*v1;
                v2 = x1.x + g1*v2; v3 = x1.y + g1*v3;
            }
            if (OUTH) {
                *(__half2*)&Ch[i0] = __floats2half2_rn(v0, v1);
                *(__half2*)&Ch[i1] = __floats2half2_rn(v2, v3);
            } else {
                *(float2*)&Cf[i0] = make_float2(v0, v1);
                *(float2*)&Cf[i1] = make_float2(v2, v3);
            }
        }
    }
}

#define SMEM_HBT ((NSTG*AH_TILE + NSTG*AH_TILE) * 2)
#define SMEM_HKN ((NSTG*AH_TILE + NSTG*BH_TILE) * 2)

// ---------------------------------------------------------------------------
// RoPE table + in-place fp16 apply
// ---------------------------------------------------------------------------
__global__ void rope_table_kernel()
{
    int idx = blockIdx.x * 256 + threadIdx.x;
    int t = idx >> 5, i = idx & 31;
    float inv = powf(10000.f, -(float)i / 32.f);
    float s, c;
    sincosf((float)t * inv, &s, &c);
    g_ropec[idx] = c;
    g_ropes[idx] = s;
}

__global__ void rope_hh(__half* __restrict__ qkvh)
{
    int n = blockIdx.x;
    int t = n & (TT-1);
    for (int p = threadIdx.x; p < 1024; p += 256) {
        int which = p >> 9;
        int rem = p & 511;
        int h = rem >> 5;
        int i = rem & 31;
        float c = g_ropec[t*32 + i];
        float s = g_ropes[t*32 + i];
        size_t base = (size_t)n*3072 + (size_t)which*1024 + h*64 + i;
        float u1 = __half2float(qkvh[base]);
        float u2 = __half2float(qkvh[base+32]);
        qkvh[base]    = __float2half_rn(u1*c - u2*s);
        qkvh[base+32] = __float2half_rn(u2*c + u1*s);
    }
}

// ---------------------------------------------------------------------------
// Flash attention FP16 (unchanged champion version)
// ---------------------------------------------------------------------------
#define QH_STR 72
#define KH_STR 72
#define VH_STR 72
#define PH_STR 40
#define QH_OFF 0
#define KH_OFF (128*QH_STR)
#define VH_OFF (KH_OFF + 3*32*KH_STR)
#define PH_OFF (VH_OFF + 3*32*VH_STR)
#define FLASHH_SMEM ((PH_OFF + 128*PH_STR) * 2)

__global__ __launch_bounds__(256)
void flash_attn_h(const __half* __restrict__ qkv, __half* __restrict__ out)
{
    extern __shared__ __half fsm_h[];
    __half* Qs = fsm_h + QH_OFF;
    __half* Ks = fsm_h + KH_OFF;
    __half* Vs = fsm_h + VH_OFF;
    __half* Ps = fsm_h + PH_OFF;
    const unsigned smem0 = (unsigned)__cvta_generic_to_shared(fsm_h);

    const int qb = blockIdx.x, bh = blockIdx.y;
    const int b = bh >> 4, h = bh & 15;
    const int tid = threadIdx.x, lane = tid & 31, warp = tid >> 5;
    const int lr = lane >> 2, lq = lane & 3;
    const int g = lane >> 3, tr = lane & 7;
    const int m0 = warp * 16;
    const int q0 = qb * 128;
    const int ntiles = 4*qb + 4;

    #pragma unroll
    for (int c = tid; c < 1024; c += 256) {
        int r = c >> 3, off = (c & 7) * 8;
        cp16(&Qs[r*QH_STR + off], qkv + (size_t)(b*TT + q0 + r)*3072 + h*64 + off);
    }

    auto load_tile = [&](int kb, int buf) {
        __half* Kb = Ks + buf*(32*KH_STR);
        __half* Vb = Vs + buf*(32*VH_STR);
        int r = tid >> 3, off = (tid & 7) * 8;
        size_t base = (size_t)(b*TT + kb*32 + r)*3072 + h*64 + off;
        cp16(&Kb[r*KH_STR + off], qkv + base + 1024);
        cp16(&Vb[r*VH_STR + off], qkv + base + 2048);
        cp_commit();
    };

    load_tile(0, 0);
    load_tile(1, 1);

    float mrow0 = -1e30f, mrow1 = -1e30f;
    float lrow0 = 0.f,    lrow1 = 0.f;
    float o[8][4];
    #pragma unroll
    for (int nt = 0; nt < 8; nt++)
        #pragma unroll
        for (int i = 0; i < 4; i++) o[nt][i] = 0.f;

    const int rg0 = q0 + m0 + lr, rg1 = rg0 + 8;

    const int a_row = (g & 1) * 8 + tr;
    const int a_col = (g >> 1) * 8;
    const int bt_row = (g >> 1) * 8 + tr;
    const int bt_col = (g & 1) * 8;
    const int bf_row = (g & 1) * 8 + tr;
    const int bf_col = (g >> 1) * 8;

    for (int kb = 0; kb < ntiles; kb++) {
        if (kb + 1 < ntiles) cp_wait1(); else cp_wait0();
        __syncthreads();
        if (kb + 2 < ntiles) load_tile(kb + 2, (kb + 2) % 3);

        const unsigned kbb = smem0 + (KH_OFF + (kb % 3)*(32*KH_STR))*2;
        const unsigned vbb = smem0 + (VH_OFF + (kb % 3)*(32*VH_STR))*2;
        const unsigned qbb = smem0 + QH_OFF*2;
        const unsigned pbb = smem0 + PH_OFF*2;

        float s[4][4];
        #pragma unroll
        for (int nt = 0; nt < 4; nt++)
            #pragma unroll
            for (int i = 0; i < 4; i++) s[nt][i] = 0.f;
        #pragma unroll
        for (int ks = 0; ks < 4; ks++) {
            const int kk = ks * 16;
            unsigned a[4];
            ldsm4(a, qbb + ((m0 + a_row)*QH_STR + kk + a_col)*2);
            unsigned bfr[2][4];
            ldsm4(bfr[0], kbb + ((bt_row)*KH_STR + kk + bt_col)*2);
            ldsm4(bfr[1], kbb + ((16 + bt_row)*KH_STR + kk + bt_col)*2);
            unsigned bv[4][2];
            bv[0][0]=bfr[0][0]; bv[0][1]=bfr[0][1];
            bv[1][0]=bfr[0][2]; bv[1][1]=bfr[0][3];
            bv[2][0]=bfr[1][0]; bv[2][1]=bfr[1][1];
            bv[3][0]=bfr[1][2]; bv[3][1]=bfr[1][3];
            #pragma unroll
            for (int nt = 0; nt < 4; nt++)
                mma_f16(s[nt], a, bv[nt]);
        }

        #pragma unroll
        for (int nt = 0; nt < 4; nt++)
            #pragma unroll
            for (int i = 0; i < 4; i++) s[nt][i] *= 0.125f;
        if (kb*32 + 31 > q0 + m0) {
            #pragma unroll
            for (int nt = 0; nt < 4; nt++) {
                int c0 = kb*32 + nt*8 + 2*lq;
                if (c0   > rg0) s[nt][0] = -1e30f;
                if (c0+1 > rg0) s[nt][1] = -1e30f;
                if (c0   > rg1) s[nt][2] = -1e30f;
                if (c0+1 > rg1) s[nt][3] = -1e30f;
            }
        }

        float mx0 = -1e30f, mx1 = -1e30f;
        #pragma unroll
        for (int nt = 0; nt < 4; nt++) {
            mx0 = fmaxf(mx0, fmaxf(s[nt][0], s[nt][1]));
            mx1 = fmaxf(mx1, fmaxf(s[nt][2], s[nt][3]));
        }
        mx0 = fmaxf(mx0, __shfl_xor_sync(0xffffffffu, mx0, 1));
        mx0 = fmaxf(mx0, __shfl_xor_sync(0xffffffffu, mx0, 2));
        mx1 = fmaxf(mx1, __shfl_xor_sync(0xffffffffu, mx1, 1));
        mx1 = fmaxf(mx1, __shfl_xor_sync(0xffffffffu, mx1, 2));
        float mn0 = fmaxf(mrow0, mx0), mn1 = fmaxf(mrow1, mx1);
        float corr0 = __expf(mrow0 - mn0), corr1 = __expf(mrow1 - mn1);
        float sum0 = 0.f, sum1 = 0.f;
        #pragma unroll
        for (int nt = 0; nt < 4; nt++) {
            s[nt][0] = __expf(s[nt][0] - mn0);
            s[nt][1] = __expf(s[nt][1] - mn0);
            s[nt][2] = __expf(s[nt][2] - mn1);
            s[nt][3] = __expf(s[nt][3] - mn1);
            sum0 += s[nt][0] + s[nt][1];
            sum1 += s[nt][2] + s[nt][3];
        }
        sum0 += __shfl_xor_sync(0xffffffffu, sum0, 1);
        sum0 += __shfl_xor_sync(0xffffffffu, sum0, 2);
        sum1 += __shfl_xor_sync(0xffffffffu, sum1, 1);
        sum1 += __shfl_xor_sync(0xffffffffu, sum1, 2);
        lrow0 = lrow0*corr0 + sum0;
        lrow1 = lrow1*corr1 + sum1;
        mrow0 = mn0; mrow1 = mn1;
        #pragma unroll
        for (int nt = 0; nt < 8; nt++) {
            o[nt][0] *= corr0; o[nt][1] *= corr0;
            o[nt][2] *= corr1; o[nt][3] *= corr1;
        }

        #pragma unroll
        for (int nt = 0; nt < 4; nt++) {
            *(__half2*)&Ps[(m0+lr)*PH_STR + nt*8+2*lq]   = __floats2half2_rn(s[nt][0], s[nt][1]);
            *(__half2*)&Ps[(m0+lr+8)*PH_STR + nt*8+2*lq] = __floats2half2_rn(s[nt][2], s[nt][3]);
        }
        __syncwarp();

        #pragma unroll
        for (int ks = 0; ks < 2; ks++) {
            const int kk = ks * 16;
            unsigned a[4];
            ldsm4(a, pbb + ((m0 + a_row)*PH_STR + kk + a_col)*2);
            #pragma unroll
            for (int ng = 0; ng < 4; ng++) {
                unsigned r[4];
                ldsm4t(r, vbb + ((kk + bf_row)*VH_STR + ng*16 + bf_col)*2);
                unsigned b0[2] = { r[0], r[1] };
                unsigned b1[2] = { r[2], r[3] };
                mma_f16(o[ng*2],   a, b0);
                mma_f16(o[ng*2+1], a, b1);
            }
        }
    }

    float inv0 = 1.f / lrow0, inv1 = 1.f / lrow1;
    #pragma unroll
    for (int nt = 0; nt < 8; nt++) {
        int cg = h*64 + nt*8 + 2*lq;
        size_t base0 = (size_t)(b*TT + rg0)*DD + cg;
        size_t base1 = (size_t)(b*TT + rg1)*DD + cg;
        ((__half2*)out)[base0>>1] = __floats2half2_rn(o[nt][0]*inv0, o[nt][1]*inv0);
        ((__half2*)out)[base1>>1] = __floats2half2_rn(o[nt][2]*inv1, o[nt][3]*inv1);
    }
}

// ---------------------------------------------------------------------------
// Router logits (fp32 xn)
// ---------------------------------------------------------------------------
__global__ void router_kernel(const float* __restrict__ xn,
                              const float* __restrict__ rw,
                              float* __restrict__ logits)
{
    int n = blockIdx.x;
    int warp = threadIdx.x >> 5, lane = threadIdx.x & 31;
    const float* xp = xn + (size_t)n*DD;
    for (int j = 0; j < 4; j++) {
        int e = warp*4 + j;
        const float* wp = rw + (size_t)e*DD;
        float s = 0.f;
        for (int i = lane; i < DD; i += 32) s += xp[i]*wp[i];
        #pragma unroll
        for (int off = 16; off; off >>= 1) s += __shfl_xor_sync(0xffffffffu, s, off);
        if (lane == 0) logits[n*EE + e] = s;
    }
}

__global__ void top2_kernel(const float* __restrict__ logits,
                            float* __restrict__ probs,
                            int* __restrict__ topi, float* __restrict__ topw)
{
    int n = blockIdx.x*blockDim.x + threadIdx.x;
    if (n >= NTOK) return;
    float l[EE];
    float mx = -1e30f;
    #pragma unroll
    for (int e = 0; e < EE; e++) { l[e] = logits[n*EE+e]; mx = fmaxf(mx, l[e]); }
    float sum = 0.f;
    #pragma unroll
    for (int e = 0; e < EE; e++) { l[e] = __expf(l[e]-mx); sum += l[e]; }
    float inv = 1.f/sum;
    #pragma unroll
    for (int e = 0; e < EE; e++) { l[e] *= inv; probs[n*EE+e] = l[e]; }
    int i0 = 0; float p0 = l[0];
    #pragma unroll
    for (int e = 1; e < EE; e++) if (l[e] > p0) { p0 = l[e]; i0 = e; }
    int i1 = (i0 == 0) ? 1 : 0; float p1 = l[i1];
    #pragma unroll
    for (int e = 0; e < EE; e++) if (e != i0 && l[e] > p1) { p1 = l[e]; i1 = e; }
    float ws = p0 + p1;
    topi[n*2]   = i0; topi[n*2+1] = i1;
    topw[n*2]   = p0/ws; topw[n*2+1] = p1/ws;
}

__global__ void pmean_kernel(const float* __restrict__ probs, float* __restrict__ pmean)
{
    int e = blockIdx.x, tid = threadIdx.x;
    float s = 0.f;
    for (int t = tid; t < NTOK; t += 256) s += probs[t*EE + e];
    __shared__ float red[256];
    red[tid] = s;
    __syncthreads();
    for (int k = 128; k; k >>= 1) {
        if (tid < k) red[tid] += red[tid+k];
        __syncthreads();
    }
    if (tid == 0) pmean[e] = red[0] / (float)NTOK;
}

__global__ void assign_kernel(const int* __restrict__ topi,
                              const float* __restrict__ topw,
                              int* __restrict__ slot, int* __restrict__ keep,
                              float* __restrict__ wcomb, int* __restrict__ counts)
{
    int e = blockIdx.x;
    int tid = threadIdx.x;
    int lane = tid & 31, warp = tid >> 5;
    __shared__ int warpsum[8];
    int running = 0;
    for (int base = 0; base < NFLAT; base += 256) {
        int i = base + tid;
        int match = (topi[i] == e) ? 1 : 0;
        unsigned mask = __ballot_sync(0xffffffffu, match);
        if (lane == 0) warpsum[warp] = __popc(mask);
        __syncthreads();
        int wbase = 0, tot = 0;
        #pragma unroll
        for (int w = 0; w < 8; w++) {
            int c = warpsum[w];
            if (w < warp) wbase += c;
            tot += c;
        }
        if (match) {
            int pos = running + wbase + __popc(mask & ((1u << lane) - 1u));
            int kp = (pos < CAP) ? 1 : 0;
            slot[i]  = (pos < CAP-1) ? pos : (CAP-1);
            keep[i]  = kp;
            wcomb[i] = kp ? topw[i] : 0.f;
        }
        running += tot;
        __syncthreads();
    }
    if (tid == 0) counts[e] = running;
}

__global__ void scatter_kernel(const int* __restrict__ topi,
                               const int* __restrict__ slot,
                               const int* __restrict__ keep,
                               const __half* __restrict__ xn,
                               __half* __restrict__ buf)
{
    int i = blockIdx.x;
    if (!keep[i]) return;
    int e = topi[i], s = slot[i], tok = i >> 1;
    const uint2* src = (const uint2*)(xn + (size_t)tok*DD);
    uint2* dst = (uint2*)(buf + ((size_t)e*CAP + s)*DD);
    dst[threadIdx.x] = src[threadIdx.x];
}

__global__ void gather_kernel(const int* __restrict__ topi,
                              const int* __restrict__ slot,
                              const float* __restrict__ wcomb,
                              const float* __restrict__ yb,
                              float* __restrict__ x)
{
    int n = blockIdx.x;
    int t4 = threadIdx.x;
    float4* xp = (float4*)(x + (size_t)n*DD);
    float4 a = xp[t4];
    #pragma unroll
    for (int k = 0; k < 2; k++) {
        int i = n*2 + k;
        float w = wcomb[i];
        if (w != 0.f) {
            int e = topi[i], s = slot[i];
            const float4* yp = (const float4*)(yb + ((size_t)e*CAP + s)*DD);
            float4 yv = yp[t4];
            a.x += w*yv.x; a.y += w*yv.y; a.z += w*yv.z; a.w += w*yv.w;
        }
    }
    xp[t4] = a;
}

__global__ void aux_kernel(const int* __restrict__ counts,
                           const float* __restrict__ pmean,
                           float* __restrict__ out, int out_size)
{
    if (threadIdx.x == 0 && out_size > NTOK*DD) {
        float s = 0.f;
        for (int e = 0; e < EE; e++)
            s += ((float)counts[e] / (float)NTOK) * pmean[e];
        out[NTOK*DD] = (float)EE * s;
    }
}

__global__ void gate_kernel(const __half* __restrict__ xn,
                            const float* __restrict__ gw,
                            const float* __restrict__ gb,
                            float* __restrict__ gate)
{
    int n = blockIdx.x, tid = threadIdx.x;
    const __half2* xp = (const __half2*)(xn + (size_t)n*DD);
    const float4* wp = (const float4*)gw;
    float2 f0 = __half22float2(xp[2*tid]);
    float2 f1 = __half22float2(xp[2*tid+1]);
    float4 wv = wp[tid];
    float s = f0.x*wv.x + f0.y*wv.y + f1.x*wv.z + f1.y*wv.w;
    __shared__ float red[256];
    red[tid] = s;
    __syncthreads();
    for (int k = 128; k; k >>= 1) {
        if (tid < k) red[tid] += red[tid+k];
        __syncthreads();
    }
    if (tid == 0) gate[n] = 1.f / (1.f + __expf(-(red[0] + gb[0])));
}

__global__ void softmax512_kernel(const float* __restrict__ tl, __half* __restrict__ outh)
{
    int n = blockIdx.x, tid = threadIdx.x;
    const float* row = tl + (size_t)n*NPRIM;
    __half* orow = outh + (size_t)n*NPRIM;
    float v0 = row[tid]       * 0.0625f;
    float v1 = row[tid + 256] * 0.0625f;
    __shared__ float red[256];
    red[tid] = fmaxf(v0, v1);
    __syncthreads();
    for (int s = 128; s; s >>= 1) {
        if (tid < s) red[tid] = fmaxf(red[tid], red[tid+s]);
        __syncthreads();
    }
    float mx = red[0];
    __syncthreads();
    v0 = __expf(v0 - mx); v1 = __expf(v1 - mx);
    red[tid] = v0 + v1;
    __syncthreads();
    for (int s = 128; s; s >>= 1) {
        if (tid < s) red[tid] += red[tid+s];
        __syncthreads();
    }
    float inv = 1.f / red[0];
    orow[tid]       = __float2half_rn(v0*inv);
    orow[tid + 256] = __float2half_rn(v1*inv);
}

// ---------------------------------------------------------------------------
// Host launch
// ---------------------------------------------------------------------------
#define F2H(stream, src, dst, n) f2h_kernel<<<(n)/2048, 256, 0, stream>>>(src, dst)

extern "C" void kernel_launch(void* const* d_in, const int* in_sizes, int n_in,
                              void* d_out, int out_size)
{
    const float* x          = (const float*)d_in[0];
    const float* tou_embeds = (const float*)d_in[1];
    const float* norm1_w    = (const float*)d_in[2];
    const float* qkv_w      = (const float*)d_in[3];
    const float* attn_o_w   = (const float*)d_in[4];
    const float* norm2_w    = (const float*)d_in[5];
    const float* router_w   = (const float*)d_in[6];
    const float* moe_w1     = (const float*)d_in[7];
    const float* moe_w2     = (const float*)d_in[8];
    const float* norm3_w    = (const float*)d_in[9];
    const float* tou_q_w    = (const float*)d_in[10];
    const float* tou_k_w    = (const float*)d_in[11];
    const float* tou_v_w    = (const float*)d_in[12];
    const float* tou_o_w    = (const float*)d_in[13];
    const float* tou_gate_w = (const float*)d_in[14];
    const float* tou_gate_b = (const float*)d_in[15];

    cudaFuncSetAttribute(gemm_h<true,0,false>,  cudaFuncAttributeMaxDynamicSharedMemorySize, SMEM_HBT);
    cudaFuncSetAttribute(gemm_h<true,0,true>,   cudaFuncAttributeMaxDynamicSharedMemorySize, SMEM_HBT);
    cudaFuncSetAttribute(gemm_h<true,4,false>,  cudaFuncAttributeMaxDynamicSharedMemorySize, SMEM_HBT);
    cudaFuncSetAttribute(gemm_h<true,5,false>,  cudaFuncAttributeMaxDynamicSharedMemorySize, SMEM_HBT);
    cudaFuncSetAttribute(gemm_h<false,0,false>, cudaFuncAttributeMaxDynamicSharedMemorySize, SMEM_HKN);
    cudaFuncSetAttribute(gemm_h<false,0,true>,  cudaFuncAttributeMaxDynamicSharedMemorySize, SMEM_HKN);
    cudaFuncSetAttribute(gemm_h<false,2,true>,  cudaFuncAttributeMaxDynamicSharedMemorySize, SMEM_HKN);
    cudaFuncSetAttribute(flash_attn_h,          cudaFuncAttributeMaxDynamicSharedMemorySize, FLASHH_SMEM);

    float *gx, *gxn, *glogits, *gprobs, *gtopw, *gwcomb, *gpmean, *gyb, *gtl, *ggate;
    int *gtopi, *gslot, *gkeep, *gcounts;
    __half *hqkv, *hxn, *hattn, *hbuf, *hh, *htq, *htk, *htv, *htl, *htout;
    __half *hqkvw, *haow, *hw1, *hw2, *htqw, *htkw, *htvw, *htow, *hemb;
    cudaGetSymbolAddress((void**)&gx, g_x);
    cudaGetSymbolAddress((void**)&gxn, g_xn);
    cudaGetSymbolAddress((void**)&glogits, g_logits);
    cudaGetSymbolAddress((void**)&gprobs, g_probs);
    cudaGetSymbolAddress((void**)&gtopi, g_topi);
    cudaGetSymbolAddress((void**)&gtopw, g_topw);
    cudaGetSymbolAddress((void**)&gslot, g_slot);
    cudaGetSymbolAddress((void**)&gkeep, g_keep);
    cudaGetSymbolAddress((void**)&gwcomb, g_wcomb);
    cudaGetSymbolAddress((void**)&gcounts, g_counts);
    cudaGetSymbolAddress((void**)&gpmean, g_pmean);
    cudaGetSymbolAddress((void**)&gyb, g_yb);
    cudaGetSymbolAddress((void**)&gtl, g_tl);
    cudaGetSymbolAddress((void**)&ggate, g_gate);
    cudaGetSymbolAddress((void**)&hqkv, gh_qkv);
    cudaGetSymbolAddress((void**)&hxn, gh_xn);
    cudaGetSymbolAddress((void**)&hattn, gh_attn);
    cudaGetSymbolAddress((void**)&hbuf, gh_buf);
    cudaGetSymbolAddress((void**)&hh, gh_h);
    cudaGetSymbolAddress((void**)&htq, gh_tq);
    cudaGetSymbolAddress((void**)&htk, gh_tk);
    cudaGetSymbolAddress((void**)&htv, gh_tv);
    cudaGetSymbolAddress((void**)&htl, gh_tl);
    cudaGetSymbolAddress((void**)&htout, gh_tout);
    cudaGetSymbolAddress((void**)&hqkvw, gh_qkvw);
    cudaGetSymbolAddress((void**)&haow, gh_aow);
    cudaGetSymbolAddress((void**)&hw1, gh_w1);
    cudaGetSymbolAddress((void**)&hw2, gh_w2);
    cudaGetSymbolAddress((void**)&htqw, gh_tqw);
    cudaGetSymbolAddress((void**)&htkw, gh_tkw);
    cudaGetSymbolAddress((void**)&htvw, gh_tvw);
    cudaGetSymbolAddress((void**)&htow, gh_tow);
    cudaGetSymbolAddress((void**)&hemb, gh_emb);

    cudaEventRecord(ev_root, 0);

    // ---- s1: rope table, ToU weight conversions + tiny GEMMs ----
    cudaStreamWaitEvent(s1, ev_root, 0);
    rope_table_kernel<<<TT*32/256, 256, 0, s1>>>();
    cudaEventRecord(ev_tab, s1);
    F2H(s1, tou_embeds, hemb, NPRIM*DP);
    F2H(s1, tou_k_w, htkw, DP*DP);
    F2H(s1, tou_v_w, htvw, DP*DP);
    F2H(s1, tou_q_w, htqw, DP*DD);
    F2H(s1, tou_o_w, htow, DD*DP);
    gemm_h<true,0,true><<<dim3(DP/128, NPRIM/128, 1), 256, SMEM_HBT, s1>>>(
        hemb, htkw, htk, NPRIM, DP, DP, 0, 0, 0, nullptr, nullptr, nullptr);
    gemm_h<true,0,true><<<dim3(DP/128, NPRIM/128, 1), 256, SMEM_HBT, s1>>>(
        hemb, htvw, htv, NPRIM, DP, DP, 0, 0, 0, nullptr, nullptr, nullptr);
    cudaEventRecord(ev_s1, s1);

    // ---- s2: qkv_w + attn_o conversions, gbuf memset, MoE weight conversions ----
    cudaStreamWaitEvent(s2, ev_root, 0);
    F2H(s2, qkv_w, hqkvw, 3*DD*DD);
    cudaEventRecord(ev_qkvw, s2);
    F2H(s2, attn_o_w, haow, DD*DD);
    cudaEventRecord(ev_aow, s2);
    cudaMemsetAsync(hbuf, 0, (size_t)EE*CAP*DD*sizeof(__half), s2);
    F2H(s2, moe_w1, hw1, EE*DD*FF);
    F2H(s2, moe_w2, hw2, EE*FF*DD);
    cudaEventRecord(ev_s2, s2);

    // ---- Block 1 ----
    rmsnorm_h<<<NTOK, 256>>>(x, norm1_w, hxn, nullptr);
    cudaStreamWaitEvent(0, ev_qkvw, 0);
    gemm_h<true,0,true><<<dim3(3*DD/128, NTOK/128, 1), 256, SMEM_HBT>>>(
        hxn, hqkvw, hqkv, NTOK, 3*DD, DD, 0, 0, 0, nullptr, nullptr, nullptr);
    cudaStreamWaitEvent(0, ev_tab, 0);
    rope_hh<<<NTOK, 256>>>(hqkv);
    flash_attn_h<<<dim3(TT/128, BB*HH), 256, FLASHH_SMEM>>>(hqkv, hattn);
    cudaStreamWaitEvent(0, ev_aow, 0);
    gemm_h<true,4,false><<<dim3(DD/128, NTOK/128, 1), 256, SMEM_HBT>>>(
        hattn, haow, gx, NTOK, DD, DD, 0, 0, 0, nullptr, x, nullptr);   // gx = x + proj

    // ---- Block 2: MoE ----
    rmsnorm_h<<<NTOK, 256>>>(gx, norm2_w, hxn, gxn);
    router_kernel<<<NTOK, 128>>>(gxn, router_w, glogits);
    top2_kernel<<<NTOK/128, 128>>>(glogits, gprobs, gtopi, gtopw);
    cudaEventRecord(ev_top2, 0);
    cudaStreamWaitEvent(s2, ev_top2, 0);
    pmean_kernel<<<EE, 256, 0, s2>>>(gprobs, gpmean);
    assign_kernel<<<EE, 256>>>(gtopi, gtopw, gslot, gkeep, gwcomb, gcounts);
    cudaEventRecord(ev_asn, 0);
    cudaStreamWaitEvent(s2, ev_asn, 0);
    aux_kernel<<<1, 32, 0, s2>>>(gcounts, gpmean, (float*)d_out, out_size);
    cudaStreamWaitEvent(0, ev_s2, 0);
    scatter_kernel<<<NFLAT, 256>>>(gtopi, gslot, gkeep, hxn, hbuf);
    gemm_h<false,2,true><<<dim3(FF/128, CAP/128, EE), 256, SMEM_HKN>>>(
        hbuf, hw1, hh, CAP, FF, DD,
        (long long)CAP*DD, (long long)DD*FF, (long long)CAP*FF, nullptr, nullptr, gcounts);
    gemm_h<false,0,false><<<dim3(DD/128, CAP/128, EE), 256, SMEM_HKN>>>(
        hh, hw2, gyb, CAP, DD, FF,
        (long long)CAP*FF, (long long)FF*DD, (long long)CAP*DD, nullptr, nullptr, gcounts);
    gather_kernel<<<NTOK, 256>>>(gtopi, gslot, gwcomb, gyb, gx);

    // ---- Block 3: ToU cross-attention ----
    rmsnorm_h<<<NTOK, 256>>>(gx, norm3_w, hxn, nullptr);
    cudaEventRecord(ev_n3, 0);
    cudaStreamWaitEvent(s2, ev_n3, 0);
    gate_kernel<<<NTOK, 256, 0, s2>>>(hxn, tou_gate_w, tou_gate_b, ggate);
    cudaEventRecord(ev_gate, s2);
    cudaStreamWaitEvent(0, ev_s1, 0);
    gemm_h<true,0,true><<<dim3(DP/128, NTOK/128, 1), 256, SMEM_HBT>>>(
        hxn, htqw, htq, NTOK, DP, DD, 0, 0, 0, nullptr, nullptr, nullptr);
    gemm_h<true,0,false><<<dim3(NPRIM/128, NTOK/128, 1), 256, SMEM_HBT>>>(
        htq, htk, gtl, NTOK, NPRIM, DP, 0, 0, 0, nullptr, nullptr, nullptr);
    softmax512_kernel<<<NTOK, 256>>>(gtl, htl);
    gemm_h<false,0,true><<<dim3(DP/128, NTOK/128, 1), 256, SMEM_HKN>>>(
        htl, htv, htout, NTOK, DP, NPRIM, 0, 0, 0, nullptr, nullptr, nullptr);
    cudaStreamWaitEvent(0, ev_gate, 0);
    gemm_h<true,5,false><<<dim3(DD/128, NTOK/128, 1), 256, SMEM_HBT>>>(
        htout, htow, (float*)d_out, NTOK, DD, DP, 0, 0, 0, ggate, gx, nullptr);
}

// round 16
// speedup vs baseline: 1.5644x; 1.0142x over previous
#include <cuda_runtime.h>
#include <cuda_bf16.h>
#include <cuda_fp16.h>
#include <math.h>

// ---------------------------------------------------------------------------
// Problem constants
// ---------------------------------------------------------------------------
#define BB 2
#define TT 2048
#define DD 1024
#define HH 16
#define DH 64
#define NTOK (BB*TT)            // 4096
#define EE 16
#define KK 2
#define FF 2048
#define CAP 640
#define DP 256
#define NPRIM 512
#define NFLAT (NTOK*KK)         // 8192

// ---------------------------------------------------------------------------
// Scratch (device globals; no allocation allowed)
// ---------------------------------------------------------------------------
__device__ float g_x[NTOK*DD];
__device__ float g_xn[NTOK*DD];          // fp32 xn (router)
__device__ float g_logits[NTOK*EE];
__device__ float g_probs[NTOK*EE];
__device__ int   g_topi[NFLAT];
__device__ float g_topw[NFLAT];
__device__ int   g_slot[NFLAT];
__device__ int   g_keep[NFLAT];
__device__ float g_wcomb[NFLAT];
__device__ int   g_counts[EE];
__device__ float g_pmean[EE];
__device__ float g_tl[NTOK*NPRIM];
__device__ float g_gate[NTOK];
__device__ float g_ropec[TT*32];
__device__ float g_ropes[TT*32];

// fp16 buffers
__device__ __half gh_qkv[NTOK*3*DD];
__device__ __half gh_xn[NTOK*DD];
__device__ __half gh_attn[NTOK*DD];
__device__ __half gh_buf[EE*CAP*DD];
__device__ __half gh_h[EE*CAP*FF];
__device__ __half gh_yb[EE*CAP*DD];
__device__ __half gh_tq[NTOK*DP];
__device__ __half gh_tk[NPRIM*DP];
__device__ __half gh_tv[NPRIM*DP];
__device__ __half gh_tl[NTOK*NPRIM];
__device__ __half gh_tout[NTOK*DP];
// fp16 weights (converted once per launch)
__device__ __half gh_qkvw[3*DD*DD];
__device__ __half gh_aow[DD*DD];
__device__ __half gh_w1[EE*DD*FF];
__device__ __half gh_w2[EE*FF*DD];
__device__ __half gh_tqw[DP*DD];
__device__ __half gh_tkw[DP*DP];
__device__ __half gh_tvw[DP*DP];
__device__ __half gh_tow[DD*DP];
__device__ __half gh_emb[NPRIM*DP];

// ---------------------------------------------------------------------------
// Streams / events (host resources, created once)
// ---------------------------------------------------------------------------
static cudaStream_t s1, s2;
static cudaEvent_t ev_root, ev_tab, ev_s1, ev_s2, ev_qkvw, ev_aow,
                   ev_top2, ev_asn, ev_n3, ev_gate;
namespace {
struct InitOnce {
    InitOnce() {
        cudaStreamCreateWithFlags(&s1, cudaStreamNonBlocking);
        cudaStreamCreateWithFlags(&s2, cudaStreamNonBlocking);
        cudaEventCreateWithFlags(&ev_root, cudaEventDisableTiming);
        cudaEventCreateWithFlags(&ev_tab,  cudaEventDisableTiming);
        cudaEventCreateWithFlags(&ev_s1,   cudaEventDisableTiming);
        cudaEventCreateWithFlags(&ev_s2,   cudaEventDisableTiming);
        cudaEventCreateWithFlags(&ev_qkvw, cudaEventDisableTiming);
        cudaEventCreateWithFlags(&ev_aow,  cudaEventDisableTiming);
        cudaEventCreateWithFlags(&ev_top2, cudaEventDisableTiming);
        cudaEventCreateWithFlags(&ev_asn,  cudaEventDisableTiming);
        cudaEventCreateWithFlags(&ev_n3,   cudaEventDisableTiming);
        cudaEventCreateWithFlags(&ev_gate, cudaEventDisableTiming);
    }
};
static InitOnce init_once_;
}

// ---------------------------------------------------------------------------
// MMA / cp.async / ldmatrix helpers
// ---------------------------------------------------------------------------
__device__ __forceinline__ void mma_f16(float c[4], const unsigned a[4], const unsigned b[2])
{
    asm volatile(
        "mma.sync.aligned.m16n8k16.row.col.f32.f16.f16.f32 "
        "{%0,%1,%2,%3},{%4,%5,%6,%7},{%8,%9},{%0,%1,%2,%3};"
        : "+f"(c[0]), "+f"(c[1]), "+f"(c[2]), "+f"(c[3])
        : "r"(a[0]), "r"(a[1]), "r"(a[2]), "r"(a[3]),
          "r"(b[0]), "r"(b[1]));
}

__device__ __forceinline__ void ldsm4(unsigned r[4], unsigned addr)
{
    asm volatile("ldmatrix.sync.aligned.m8n8.x4.shared.b16 {%0,%1,%2,%3}, [%4];"
        : "=r"(r[0]), "=r"(r[1]), "=r"(r[2]), "=r"(r[3]) : "r"(addr));
}
__device__ __forceinline__ void ldsm4t(unsigned r[4], unsigned addr)
{
    asm volatile("ldmatrix.sync.aligned.m8n8.x4.trans.shared.b16 {%0,%1,%2,%3}, [%4];"
        : "=r"(r[0]), "=r"(r[1]), "=r"(r[2]), "=r"(r[3]) : "r"(addr));
}

__device__ __forceinline__ void cp16(void* smem_dst, const void* gptr)
{
    unsigned saddr = (unsigned)__cvta_generic_to_shared(smem_dst);
    asm volatile("cp.async.cg.shared.global [%0], [%1], 16;\n"
                 :: "r"(saddr), "l"(gptr));
}
__device__ __forceinline__ void cp_commit()  { asm volatile("cp.async.commit_group;\n"); }
__device__ __forceinline__ void cp_wait2()   { asm volatile("cp.async.wait_group 2;\n"); }
__device__ __forceinline__ void cp_wait1()   { asm volatile("cp.async.wait_group 1;\n"); }
__device__ __forceinline__ void cp_wait0()   { asm volatile("cp.async.wait_group 0;\n"); }

// ---------------------------------------------------------------------------
// f32 -> f16 conversion (n % 2048 == 0)
// ---------------------------------------------------------------------------
__global__ void f2h_kernel(const float* __restrict__ in, __half* __restrict__ out)
{
    int i = (blockIdx.x*256 + threadIdx.x) * 8;
    float4 v0 = *(const float4*)(in + i);
    float4 v1 = *(const float4*)(in + i + 4);
    __half2* o = (__half2*)(out + i);
    o[0] = __floats2half2_rn(v0.x, v0.y);
    o[1] = __floats2half2_rn(v0.z, v0.w);
    o[2] = __floats2half2_rn(v1.x, v1.y);
    o[3] = __floats2half2_rn(v1.z, v1.w);
}

// ---------------------------------------------------------------------------
// RMSNorm: one block per token; fp16 out (+optional fp32 out)
// ---------------------------------------------------------------------------
__global__ void rmsnorm_h(const float* __restrict__ x,
                          const float* __restrict__ w,
                          __half* __restrict__ outh,
                          float* __restrict__ outf)
{
    int n = blockIdx.x;
    int tid = threadIdx.x;
    const float4* xp = (const float4*)(x + (size_t)n*DD);
    float4 xv = xp[tid];
    float ss = xv.x*xv.x + xv.y*xv.y + xv.z*xv.z + xv.w*xv.w;
    __shared__ float red[256];
    red[tid] = ss;
    __syncthreads();
    for (int s = 128; s; s >>= 1) {
        if (tid < s) red[tid] += red[tid+s];
        __syncthreads();
    }
    float scale = rsqrtf(red[0] / (float)DD + 1e-6f);
    const float4* wp = (const float4*)w;
    float4 wv = wp[tid];
    float a = xv.x*scale*wv.x, b = xv.y*scale*wv.y;
    float c = xv.z*scale*wv.z, d = xv.w*scale*wv.w;
    __half2* oh = (__half2*)(outh + (size_t)n*DD);
    oh[2*tid]   = __floats2half2_rn(a, b);
    oh[2*tid+1] = __floats2half2_rn(c, d);
    if (outf) ((float4*)(outf + (size_t)n*DD))[tid] = make_float4(a, b, c, d);
}

// ---------------------------------------------------------------------------
// FP16 tensor-core GEMM (m16n8k16): 4-stage cp.async, ldmatrix fragments.
// EPI: 0=store, 2=silu store, 4=C=Xin+v, 5=C=Xin+gate*v;  OUTH: __half out
// cnt: optional per-z row-count (skip row-blocks >= min(cnt, M))
// ---------------------------------------------------------------------------
#define AH_STR 40
#define BH_STR 136
#define NSTG 4
#define AH_TILE (128*AH_STR)
#define BH_TILE (32*BH_STR)

template<bool BT, int EPI, bool OUTH>
__global__ __launch_bounds__(256, 2)
void gemm_h(const __half* __restrict__ A, const __half* __restrict__ Bm,
            void* __restrict__ Cv, int M, int N, int K,
            long long sA, long long sB, long long sC,
            const float* __restrict__ gate, const float* __restrict__ Xin,
            const int* __restrict__ cnt)
{
    const int row0 = blockIdx.y * 128, col0 = blockIdx.x * 128;
    if (cnt) {
        int c = cnt[blockIdx.z];
        if (c > M) c = M;
        if (row0 >= c) return;        // rows never consumed downstream
    }

    A  += blockIdx.z * sA;
    Bm += blockIdx.z * sB;

    extern __shared__ __half smem_h[];
    __half* AsP = smem_h;
    __half* BsP = smem_h + NSTG*AH_TILE;
    const unsigned sbase = (unsigned)__cvta_generic_to_shared(smem_h);
    const unsigned bbase = sbase + NSTG*AH_TILE*2;

    const int tid  = threadIdx.x;
    const int lane = tid & 31;
    const int warp = tid >> 5;
    const int lr   = lane >> 2;
    const int lq   = lane & 3;
    const int g    = lane >> 3;
    const int tr   = lane & 7;
    const int wm   = warp & 1, wn = warp >> 1;
    const int m0   = wm * 64, n0 = wn * 32;

    const int c0i = tid, c1i = tid + 256;
    const int ar0 = c0i >> 2, ac0 = (c0i & 3) * 8;
    const int ar1 = c1i >> 2, ac1 = (c1i & 3) * 8;
    const int fr0 = c0i >> 4, fo0 = (c0i & 15) * 8;
    const int fr1 = c1i >> 4, fo1 = (c1i & 15) * 8;

    const int nIter = K >> 5;

    auto issue = [&](int stg, int k0) {
        cp16(&AsP[stg*AH_TILE + ar0*AH_STR + ac0], A + (size_t)(row0 + ar0) * K + k0 + ac0);
        cp16(&AsP[stg*AH_TILE + ar1*AH_STR + ac1], A + (size_t)(row0 + ar1) * K + k0 + ac1);
        if constexpr (BT) {
            cp16(&BsP[stg*AH_TILE + ar0*AH_STR + ac0], Bm + (size_t)(col0 + ar0) * K + k0 + ac0);
            cp16(&BsP[stg*AH_TILE + ar1*AH_STR + ac1], Bm + (size_t)(col0 + ar1) * K + k0 + ac1);
        } else {
            cp16(&BsP[stg*BH_TILE + fr0*BH_STR + fo0], Bm + (size_t)(k0 + fr0) * N + col0 + fo0);
            cp16(&BsP[stg*BH_TILE + fr1*BH_STR + fo1], Bm + (size_t)(k0 + fr1) * N + col0 + fo1);
        }
        cp_commit();
    };

    issue(0, 0);
    if (nIter > 1) issue(1, 32);
    if (nIter > 2) issue(2, 64);

    float c[4][4][4];
    #pragma unroll
    for (int mt = 0; mt < 4; mt++)
        #pragma unroll
        for (int nt = 0; nt < 4; nt++)
            #pragma unroll
            for (int i = 0; i < 4; i++) c[mt][nt][i] = 0.f;

    const int a_row = (g & 1) * 8 + tr;
    const int a_col = (g >> 1) * 8;
    const int bt_row = (g >> 1) * 8 + tr;
    const int bt_col = (g & 1) * 8;
    const int bf_row = (g & 1) * 8 + tr;
    const int bf_col = (g >> 1) * 8;

    for (int it = 0; it < nIter; it++) {
        if (it + 2 < nIter)      cp_wait2();
        else if (it + 1 < nIter) cp_wait1();
        else                     cp_wait0();
        __syncthreads();

        if (it + 3 < nIter) issue((it + 3) & 3, (it + 3) << 5);

        const int st = it & 3;
        const unsigned abase = sbase + st*AH_TILE*2;
        const unsigned btb   = bbase + (BT ? st*AH_TILE*2 : st*BH_TILE*2);

        #pragma unroll
        for (int ks = 0; ks < 2; ks++) {
            const int kb = ks * 16;
            unsigned a[4][4];
            #pragma unroll
            for (int mt = 0; mt < 4; mt++) {
                unsigned addr = abase + ((m0 + mt*16 + a_row)*AH_STR + kb + a_col)*2;
                ldsm4(a[mt], addr);
            }
            unsigned b[4][2];
            #pragma unroll
            for (int ntp = 0; ntp < 2; ntp++) {
                unsigned r[4];
                if constexpr (BT) {
                    unsigned addr = btb + ((n0 + ntp*16 + bt_row)*AH_STR + kb + bt_col)*2;
                    ldsm4(r, addr);
                } else {
                    unsigned addr = btb + ((kb + bf_row)*BH_STR + n0 + ntp*16 + bf_col)*2;
                    ldsm4t(r, addr);
                }
                b[ntp*2][0]   = r[0]; b[ntp*2][1]   = r[1];
                b[ntp*2+1][0] = r[2]; b[ntp*2+1][1] = r[3];
            }
            #pragma unroll
            for (int mt = 0; mt < 4; mt++)
                #pragma unroll
                for (int nt = 0; nt < 4; nt++)
                    mma_f16(c[mt][nt], a[mt], b[nt]);
        }
    }

    float* Cf = (float*)Cv + (OUTH ? 0 : blockIdx.z * sC);
    __half* Ch = (__half*)Cv + (OUTH ? blockIdx.z * sC : 0);
    #pragma unroll
    for (int mt = 0; mt < 4; mt++) {
        int r0g = row0 + m0 + mt * 16 + lr;
        int r1g = r0g + 8;
        float g0 = (EPI == 5) ? gate[r0g] : 0.f;
        float g1 = (EPI == 5) ? gate[r1g] : 0.f;
        #pragma unroll
        for (int nt = 0; nt < 4; nt++) {
            int cg = col0 + n0 + nt * 8 + 2 * lq;
            size_t i0 = (size_t)r0g * N + cg;
            size_t i1 = (size_t)r1g * N + cg;
            float v0 = c[mt][nt][0], v1 = c[mt][nt][1];
            float v2 = c[mt][nt][2], v3 = c[mt][nt][3];
            if (EPI == 2) {
                v0 = v0 / (1.f + __expf(-v0));
                v1 = v1 / (1.f + __expf(-v1));
                v2 = v2 / (1.f + __expf(-v2));
                v3 = v3 / (1.f + __expf(-v3));
            } else if (EPI == 4) {
                float2 x0 = *(const float2*)&Xin[i0];
                float2 x1 = *(const float2*)&Xin[i1];
                v0 += x0.x; v1 += x0.y; v2 += x1.x; v3 += x1.y;
            } else if (EPI == 5) {
                float2 x0 = *(const float2*)&Xin[i0];
                float2 x1 = *(const float2*)&Xin[i1];
                v0 = x0.x + g0*v0; v1 = x0.y + g0*v1;
                v2 = x1.x + g1*v2; v3 = x1.y + g1*v3;
            }
            if (OUTH) {
                *(__half2*)&Ch[i0] = __floats2half2_rn(v0, v1);
                *(__half2*)&Ch[i1] = __floats2half2_rn(v2, v3);
            } else {
                *(float2*)&Cf[i0] = make_float2(v0, v1);
                *(float2*)&Cf[i1] = make_float2(v2, v3);
            }
        }
    }
}

#define SMEM_HBT ((NSTG*AH_TILE + NSTG*AH_TILE) * 2)
#define SMEM_HKN ((NSTG*AH_TILE + NSTG*BH_TILE) * 2)

// ---------------------------------------------------------------------------
// RoPE table + in-place fp16 apply
// ---------------------------------------------------------------------------
__global__ void rope_table_kernel()
{
    int idx = blockIdx.x * 256 + threadIdx.x;
    int t = idx >> 5, i = idx & 31;
    float inv = powf(10000.f, -(float)i / 32.f);
    float s, c;
    sincosf((float)t * inv, &s, &c);
    g_ropec[idx] = c;
    g_ropes[idx] = s;
}

__global__ void rope_hh(__half* __restrict__ qkvh)
{
    int n = blockIdx.x;
    int t = n & (TT-1);
    for (int p = threadIdx.x; p < 1024; p += 256) {
        int which = p >> 9;
        int rem = p & 511;
        int h = rem >> 5;
        int i = rem & 31;
        float c = g_ropec[t*32 + i];
        float s = g_ropes[t*32 + i];
        size_t base = (size_t)n*3072 + (size_t)which*1024 + h*64 + i;
        float u1 = __half2float(qkvh[base]);
        float u2 = __half2float(qkvh[base+32]);
        qkvh[base]    = __float2half_rn(u1*c - u2*s);
        qkvh[base+32] = __float2half_rn(u2*c + u1*s);
    }
}

// ---------------------------------------------------------------------------
// Flash attention FP16, BK=64: BQ=128, 8 warps, triple-buffered K/V tiles of
// 64 keys, ldmatrix fragments, fp32 online softmax.
// ---------------------------------------------------------------------------
#define QH_STR 72
#define KH_STR 72
#define VH_STR 72
#define PH_STR 72
#define KH_TILE (64*KH_STR)
#define QH_OFF 0
#define KH_OFF (128*QH_STR)                 // 9216
#define VH_OFF (KH_OFF + 3*KH_TILE)         // 23040
#define PH_OFF (VH_OFF + 3*KH_TILE)         // 36864
#define FLASHH_SMEM ((PH_OFF + 128*PH_STR) * 2)   // 92160 B

__global__ __launch_bounds__(256, 2)
void flash_attn_h(const __half* __restrict__ qkv, __half* __restrict__ out)
{
    extern __shared__ __half fsm_h[];
    __half* Qs = fsm_h + QH_OFF;
    __half* Ks = fsm_h + KH_OFF;
    __half* Vs = fsm_h + VH_OFF;
    __half* Ps = fsm_h + PH_OFF;
    const unsigned smem0 = (unsigned)__cvta_generic_to_shared(fsm_h);

    const int qb = blockIdx.x, bh = blockIdx.y;
    const int b = bh >> 4, h = bh & 15;
    const int tid = threadIdx.x, lane = tid & 31, warp = tid >> 5;
    const int lr = lane >> 2, lq = lane & 3;
    const int g = lane >> 3, tr = lane & 7;
    const int m0 = warp * 16;
    const int q0 = qb * 128;
    const int ntiles = 2*qb + 2;            // tiles of 64 keys

    // Q: 128 rows x 8 chunks (16B) = 1024 chunks
    #pragma unroll
    for (int c = tid; c < 1024; c += 256) {
        int r = c >> 3, off = (c & 7) * 8;
        cp16(&Qs[r*QH_STR + off], qkv + (size_t)(b*TT + q0 + r)*3072 + h*64 + off);
    }

    auto load_tile = [&](int kb, int buf) {
        __half* Kb = Ks + buf*KH_TILE;
        __half* Vb = Vs + buf*KH_TILE;
        // 512 chunks each for K and V (64 rows x 8 chunks); 2 per thread per op
        #pragma unroll
        for (int c = tid; c < 512; c += 256) {
            int r = c >> 3, off = (c & 7) * 8;
            size_t base = (size_t)(b*TT + kb*64 + r)*3072 + h*64 + off;
            cp16(&Kb[r*KH_STR + off], qkv + base + 1024);
            cp16(&Vb[r*VH_STR + off], qkv + base + 2048);
        }
        cp_commit();
    };

    load_tile(0, 0);
    load_tile(1, 1);

    float mrow0 = -1e30f, mrow1 = -1e30f;
    float lrow0 = 0.f,    lrow1 = 0.f;
    float o[8][4];
    #pragma unroll
    for (int nt = 0; nt < 8; nt++)
        #pragma unroll
        for (int i = 0; i < 4; i++) o[nt][i] = 0.f;

    const int rg0 = q0 + m0 + lr, rg1 = rg0 + 8;

    const int a_row = (g & 1) * 8 + tr;
    const int a_col = (g >> 1) * 8;
    const int bt_row = (g >> 1) * 8 + tr;
    const int bt_col = (g & 1) * 8;
    const int bf_row = (g & 1) * 8 + tr;
    const int bf_col = (g >> 1) * 8;

    for (int kb = 0; kb < ntiles; kb++) {
        if (kb + 1 < ntiles) cp_wait1(); else cp_wait0();
        __syncthreads();
        if (kb + 2 < ntiles) load_tile(kb + 2, (kb + 2) % 3);

        const unsigned kbb = smem0 + (KH_OFF + (kb % 3)*KH_TILE)*2;
        const unsigned vbb = smem0 + (VH_OFF + (kb % 3)*KH_TILE)*2;
        const unsigned qbb = smem0 + QH_OFF*2;
        const unsigned pbb = smem0 + PH_OFF*2;

        // ---- S = Q K^T  (4 k16-steps over dh=64; 64 keys => 8 n8 frags) ----
        float s[8][4];
        #pragma unroll
        for (int nt = 0; nt < 8; nt++)
            #pragma unroll
            for (int i = 0; i < 4; i++) s[nt][i] = 0.f;
        #pragma unroll
        for (int ks = 0; ks < 4; ks++) {
            const int kk = ks * 16;
            unsigned a[4];
            ldsm4(a, qbb + ((m0 + a_row)*QH_STR + kk + a_col)*2);
            #pragma unroll
            for (int kg = 0; kg < 4; kg++) {
                unsigned r[4];
                ldsm4(r, kbb + ((kg*16 + bt_row)*KH_STR + kk + bt_col)*2);
                unsigned b0[2] = { r[0], r[1] };
                unsigned b1[2] = { r[2], r[3] };
                mma_f16(s[kg*2],   a, b0);
                mma_f16(s[kg*2+1], a, b1);
            }
        }

        // ---- scale + causal mask ----
        #pragma unroll
        for (int nt = 0; nt < 8; nt++)
            #pragma unroll
            for (int i = 0; i < 4; i++) s[nt][i] *= 0.125f;
        if (kb*64 + 63 > q0 + m0) {
            #pragma unroll
            for (int nt = 0; nt < 8; nt++) {
                int c0 = kb*64 + nt*8 + 2*lq;
                if (c0   > rg0) s[nt][0] = -1e30f;
                if (c0+1 > rg0) s[nt][1] = -1e30f;
                if (c0   > rg1) s[nt][2] = -1e30f;
                if (c0+1 > rg1) s[nt][3] = -1e30f;
            }
        }

        // ---- online softmax ----
        float mx0 = -1e30f, mx1 = -1e30f;
        #pragma unroll
        for (int nt = 0; nt < 8; nt++) {
            mx0 = fmaxf(mx0, fmaxf(s[nt][0], s[nt][1]));
            mx1 = fmaxf(mx1, fmaxf(s[nt][2], s[nt][3]));
        }
        mx0 = fmaxf(mx0, __shfl_xor_sync(0xffffffffu, mx0, 1));
        mx0 = fmaxf(mx0, __shfl_xor_sync(0xffffffffu, mx0, 2));
        mx1 = fmaxf(mx1, __shfl_xor_sync(0xffffffffu, mx1, 1));
        mx1 = fmaxf(mx1, __shfl_xor_sync(0xffffffffu, mx1, 2));
        float mn0 = fmaxf(mrow0, mx0), mn1 = fmaxf(mrow1, mx1);
        float corr0 = __expf(mrow0 - mn0), corr1 = __expf(mrow1 - mn1);
        float sum0 = 0.f, sum1 = 0.f;
        #pragma unroll
        for (int nt = 0; nt < 8; nt++) {
            s[nt][0] = __expf(s[nt][0] - mn0);
            s[nt][1] = __expf(s[nt][1] - mn0);
            s[nt][2] = __expf(s[nt][2] - mn1);
            s[nt][3] = __expf(s[nt][3] - mn1);
            sum0 += s[nt][0] + s[nt][1];
            sum1 += s[nt][2] + s[nt][3];
        }
        sum0 += __shfl_xor_sync(0xffffffffu, sum0, 1);
        sum0 += __shfl_xor_sync(0xffffffffu, sum0, 2);
        sum1 += __shfl_xor_sync(0xffffffffu, sum1, 1);
        sum1 += __shfl_xor_sync(0xffffffffu, sum1, 2);
        lrow0 = lrow0*corr0 + sum0;
        lrow1 = lrow1*corr1 + sum1;
        mrow0 = mn0; mrow1 = mn1;
        #pragma unroll
        for (int nt = 0; nt < 8; nt++) {
            o[nt][0] *= corr0; o[nt][1] *= corr0;
            o[nt][2] *= corr1; o[nt][3] *= corr1;
        }

        // ---- P -> smem as fp16 (warp-private rows) ----
        #pragma unroll
        for (int nt = 0; nt < 8; nt++) {
            *(__half2*)&Ps[(m0+lr)*PH_STR + nt*8+2*lq]   = __floats2half2_rn(s[nt][0], s[nt][1]);
            *(__half2*)&Ps[(m0+lr+8)*PH_STR + nt*8+2*lq] = __floats2half2_rn(s[nt][2], s[nt][3]);
        }
        __syncwarp();

        // ---- O += P V  (4 k16-steps over 64 keys; V [key][dh] trans) ----
        #pragma unroll
        for (int ks = 0; ks < 4; ks++) {
            const int kk = ks * 16;
            unsigned a[4];
            ldsm4(a, pbb + ((m0 + a_row)*PH_STR + kk + a_col)*2);
            #pragma unroll
            for (int ng = 0; ng < 4; ng++) {
                unsigned r[4];
                ldsm4t(r, vbb + ((kk + bf_row)*VH_STR + ng*16 + bf_col)*2);
                unsigned b0[2] = { r[0], r[1] };
                unsigned b1[2] = { r[2], r[3] };
                mma_f16(o[ng*2],   a, b0);
                mma_f16(o[ng*2+1], a, b1);
            }
        }
    }

    float inv0 = 1.f / lrow0, inv1 = 1.f / lrow1;
    #pragma unroll
    for (int nt = 0; nt < 8; nt++) {
        int cg = h*64 + nt*8 + 2*lq;
        size_t base0 = (size_t)(b*TT + rg0)*DD + cg;
        size_t base1 = (size_t)(b*TT + rg1)*DD + cg;
        ((__half2*)out)[base0>>1] = __floats2half2_rn(o[nt][0]*inv0, o[nt][1]*inv0);
        ((__half2*)out)[base1>>1] = __floats2half2_rn(o[nt][2]*inv1, o[nt][3]*inv1);
    }
}

// ---------------------------------------------------------------------------
// Router logits (fp32 xn)
// ---------------------------------------------------------------------------
__global__ void router_kernel(const float* __restrict__ xn,
                              const float* __restrict__ rw,
                              float* __restrict__ logits)
{
    int n = blockIdx.x;
    int warp = threadIdx.x >> 5, lane = threadIdx.x & 31;
    const float* xp = xn + (size_t)n*DD;
    for (int j = 0; j < 4; j++) {
        int e = warp*4 + j;
        const float* wp = rw + (size_t)e*DD;
        float s = 0.f;
        for (int i = lane; i < DD; i += 32) s += xp[i]*wp[i];
        #pragma unroll
        for (int off = 16; off; off >>= 1) s += __shfl_xor_sync(0xffffffffu, s, off);
        if (lane == 0) logits[n*EE + e] = s;
    }
}

__global__ void top2_kernel(const float* __restrict__ logits,
                            float* __restrict__ probs,
                            int* __restrict__ topi, float* __restrict__ topw)
{
    int n = blockIdx.x*blockDim.x + threadIdx.x;
    if (n >= NTOK) return;
    float l[EE];
    float mx = -1e30f;
    #pragma unroll
    for (int e = 0; e < EE; e++) { l[e] = logits[n*EE+e]; mx = fmaxf(mx, l[e]); }
    float sum = 0.f;
    #pragma unroll
    for (int e = 0; e < EE; e++) { l[e] = __expf(l[e]-mx); sum += l[e]; }
    float inv = 1.f/sum;
    #pragma unroll
    for (int e = 0; e < EE; e++) { l[e] *= inv; probs[n*EE+e] = l[e]; }
    int i0 = 0; float p0 = l[0];
    #pragma unroll
    for (int e = 1; e < EE; e++) if (l[e] > p0) { p0 = l[e]; i0 = e; }
    int i1 = (i0 == 0) ? 1 : 0; float p1 = l[i1];
    #pragma unroll
    for (int e = 0; e < EE; e++) if (e != i0 && l[e] > p1) { p1 = l[e]; i1 = e; }
    float ws = p0 + p1;
    topi[n*2]   = i0; topi[n*2+1] = i1;
    topw[n*2]   = p0/ws; topw[n*2+1] = p1/ws;
}

__global__ void pmean_kernel(const float* __restrict__ probs, float* __restrict__ pmean)
{
    int e = blockIdx.x, tid = threadIdx.x;
    float s = 0.f;
    for (int t = tid; t < NTOK; t += 256) s += probs[t*EE + e];
    __shared__ float red[256];
    red[tid] = s;
    __syncthreads();
    for (int k = 128; k; k >>= 1) {
        if (tid < k) red[tid] += red[tid+k];
        __syncthreads();
    }
    if (tid == 0) pmean[e] = red[0] / (float)NTOK;
}

__global__ void assign_kernel(const int* __restrict__ topi,
                              const float* __restrict__ topw,
                              int* __restrict__ slot, int* __restrict__ keep,
                              float* __restrict__ wcomb, int* __restrict__ counts)
{
    int e = blockIdx.x;
    int tid = threadIdx.x;
    int lane = tid & 31, warp = tid >> 5;
    __shared__ int warpsum[8];
    int running = 0;
    for (int base = 0; base < NFLAT; base += 256) {
        int i = base + tid;
        int match = (topi[i] == e) ? 1 : 0;
        unsigned mask = __ballot_sync(0xffffffffu, match);
        if (lane == 0) warpsum[warp] = __popc(mask);
        __syncthreads();
        int wbase = 0, tot = 0;
        #pragma unroll
        for (int w = 0; w < 8; w++) {
            int c = warpsum[w];
            if (w < warp) wbase += c;
            tot += c;
        }
        if (match) {
            int pos = running + wbase + __popc(mask & ((1u << lane) - 1u));
            int kp = (pos < CAP) ? 1 : 0;
            slot[i]  = (pos < CAP-1) ? pos : (CAP-1);
            keep[i]  = kp;
            wcomb[i] = kp ? topw[i] : 0.f;
        }
        running += tot;
        __syncthreads();
    }
    if (tid == 0) counts[e] = running;
}

__global__ void scatter_kernel(const int* __restrict__ topi,
                               const int* __restrict__ slot,
                               const int* __restrict__ keep,
                               const __half* __restrict__ xn,
                               __half* __restrict__ buf)
{
    int i = blockIdx.x;
    if (!keep[i]) return;
    int e = topi[i], s = slot[i], tok = i >> 1;
    const uint2* src = (const uint2*)(xn + (size_t)tok*DD);
    uint2* dst = (uint2*)(buf + ((size_t)e*CAP + s)*DD);
    dst[threadIdx.x] = src[threadIdx.x];
}

__global__ void gather_kernel(const int* __restrict__ topi,
                              const int* __restrict__ slot,
                              const float* __restrict__ wcomb,
                              const __half* __restrict__ yb,
                              float* __restrict__ x)
{
    int n = blockIdx.x;
    int t4 = threadIdx.x;
    float4* xp = (float4*)(x + (size_t)n*DD);
    float4 a = xp[t4];
    #pragma unroll
    for (int k = 0; k < 2; k++) {
        int i = n*2 + k;
        float w = wcomb[i];
        if (w != 0.f) {
            int e = topi[i], s = slot[i];
            const __half2* yp = (const __half2*)(yb + ((size_t)e*CAP + s)*DD);
            float2 y0 = __half22float2(yp[2*t4]);
            float2 y1 = __half22float2(yp[2*t4+1]);
            a.x += w*y0.x; a.y += w*y0.y; a.z += w*y1.x; a.w += w*y1.y;
        }
    }
    xp[t4] = a;
}

__global__ void aux_kernel(const int* __restrict__ counts,
                           const float* __restrict__ pmean,
                           float* __restrict__ out, int out_size)
{
    if (threadIdx.x == 0 && out_size > NTOK*DD) {
        float s = 0.f;
        for (int e = 0; e < EE; e++)
            s += ((float)counts[e] / (float)NTOK) * pmean[e];
        out[NTOK*DD] = (float)EE * s;
    }
}

__global__ void gate_kernel(const __half* __restrict__ xn,
                            const float* __restrict__ gw,
                            const float* __restrict__ gb,
                            float* __restrict__ gate)
{
    int n = blockIdx.x, tid = threadIdx.x;
    const __half2* xp = (const __half2*)(xn + (size_t)n*DD);
    const float4* wp = (const float4*)gw;
    float2 f0 = __half22float2(xp[2*tid]);
    float2 f1 = __half22float2(xp[2*tid+1]);
    float4 wv = wp[tid];
    float s = f0.x*wv.x + f0.y*wv.y + f1.x*wv.z + f1.y*wv.w;
    __shared__ float red[256];
    red[tid] = s;
    __syncthreads();
    for (int k = 128; k; k >>= 1) {
        if (tid < k) red[tid] += red[tid+k];
        __syncthreads();
    }
    if (tid == 0) gate[n] = 1.f / (1.f + __expf(-(red[0] + gb[0])));
}

__global__ void softmax512_kernel(const float* __restrict__ tl, __half* __restrict__ outh)
{
    int n = blockIdx.x, tid = threadIdx.x;
    const float* row = tl + (size_t)n*NPRIM;
    __half* orow = outh + (size_t)n*NPRIM;
    float v0 = row[tid]       * 0.0625f;
    float v1 = row[tid + 256] * 0.0625f;
    __shared__ float red[256];
    red[tid] = fmaxf(v0, v1);
    __syncthreads();
    for (int s = 128; s; s >>= 1) {
        if (tid < s) red[tid] = fmaxf(red[tid], red[tid+s]);
        __syncthreads();
    }
    float mx = red[0];
    __syncthreads();
    v0 = __expf(v0 - mx); v1 = __expf(v1 - mx);
    red[tid] = v0 + v1;
    __syncthreads();
    for (int s = 128; s; s >>= 1) {
        if (tid < s) red[tid] += red[tid+s];
        __syncthreads();
    }
    float inv = 1.f / red[0];
    orow[tid]       = __float2half_rn(v0*inv);
    orow[tid + 256] = __float2half_rn(v1*inv);
}

// ---------------------------------------------------------------------------
// Host launch
// ---------------------------------------------------------------------------
#define F2H(stream, src, dst, n) f2h_kernel<<<(n)/2048, 256, 0, stream>>>(src, dst)

extern "C" void kernel_launch(void* const* d_in, const int* in_sizes, int n_in,
                              void* d_out, int out_size)
{
    const float* x          = (const float*)d_in[0];
    const float* tou_embeds = (const float*)d_in[1];
    const float* norm1_w    = (const float*)d_in[2];
    const float* qkv_w      = (const float*)d_in[3];
    const float* attn_o_w   = (const float*)d_in[4];
    const float* norm2_w    = (const float*)d_in[5];
    const float* router_w   = (const float*)d_in[6];
    const float* moe_w1     = (const float*)d_in[7];
    const float* moe_w2     = (const float*)d_in[8];
    const float* norm3_w    = (const float*)d_in[9];
    const float* tou_q_w    = (const float*)d_in[10];
    const float* tou_k_w    = (const float*)d_in[11];
    const float* tou_v_w    = (const float*)d_in[12];
    const float* tou_o_w    = (const float*)d_in[13];
    const float* tou_gate_w = (const float*)d_in[14];
    const float* tou_gate_b = (const float*)d_in[15];

    cudaFuncSetAttribute(gemm_h<true,0,false>,  cudaFuncAttributeMaxDynamicSharedMemorySize, SMEM_HBT);
    cudaFuncSetAttribute(gemm_h<true,0,true>,   cudaFuncAttributeMaxDynamicSharedMemorySize, SMEM_HBT);
    cudaFuncSetAttribute(gemm_h<true,4,false>,  cudaFuncAttributeMaxDynamicSharedMemorySize, SMEM_HBT);
    cudaFuncSetAttribute(gemm_h<true,5,false>,  cudaFuncAttributeMaxDynamicSharedMemorySize, SMEM_HBT);
    cudaFuncSetAttribute(gemm_h<false,0,true>,  cudaFuncAttributeMaxDynamicSharedMemorySize, SMEM_HKN);
    cudaFuncSetAttribute(gemm_h<false,2,true>,  cudaFuncAttributeMaxDynamicSharedMemorySize, SMEM_HKN);
    cudaFuncSetAttribute(flash_attn_h,          cudaFuncAttributeMaxDynamicSharedMemorySize, FLASHH_SMEM);

    float *gx, *gxn, *glogits, *gprobs, *gtopw, *gwcomb, *gpmean, *gtl, *ggate;
    int *gtopi, *gslot, *gkeep, *gcounts;
    __half *hqkv, *hxn, *hattn, *hbuf, *hh, *hyb, *htq, *htk, *htv, *htl, *htout;
    __half *hqkvw, *haow, *hw1, *hw2, *htqw, *htkw, *htvw, *htow, *hemb;
    cudaGetSymbolAddress((void**)&gx, g_x);
    cudaGetSymbolAddress((void**)&gxn, g_xn);
    cudaGetSymbolAddress((void**)&glogits, g_logits);
    cudaGetSymbolAddress((void**)&gprobs, g_probs);
    cudaGetSymbolAddress((void**)&gtopi, g_topi);
    cudaGetSymbolAddress((void**)&gtopw, g_topw);
    cudaGetSymbolAddress((void**)&gslot, g_slot);
    cudaGetSymbolAddress((void**)&gkeep, g_keep);
    cudaGetSymbolAddress((void**)&gwcomb, g_wcomb);
    cudaGetSymbolAddress((void**)&gcounts, g_counts);
    cudaGetSymbolAddress((void**)&gpmean, g_pmean);
    cudaGetSymbolAddress((void**)&gtl, g_tl);
    cudaGetSymbolAddress((void**)&ggate, g_gate);
    cudaGetSymbolAddress((void**)&hqkv, gh_qkv);
    cudaGetSymbolAddress((void**)&hxn, gh_xn);
    cudaGetSymbolAddress((void**)&hattn, gh_attn);
    cudaGetSymbolAddress((void**)&hbuf, gh_buf);
    cudaGetSymbolAddress((void**)&hh, gh_h);
    cudaGetSymbolAddress((void**)&hyb, gh_yb);
    cudaGetSymbolAddress((void**)&htq, gh_tq);
    cudaGetSymbolAddress((void**)&htk, gh_tk);
    cudaGetSymbolAddress((void**)&htv, gh_tv);
    cudaGetSymbolAddress((void**)&htl, gh_tl);
    cudaGetSymbolAddress((void**)&htout, gh_tout);
    cudaGetSymbolAddress((void**)&hqkvw, gh_qkvw);
    cudaGetSymbolAddress((void**)&haow, gh_aow);
    cudaGetSymbolAddress((void**)&hw1, gh_w1);
    cudaGetSymbolAddress((void**)&hw2, gh_w2);
    cudaGetSymbolAddress((void**)&htqw, gh_tqw);
    cudaGetSymbolAddress((void**)&htkw, gh_tkw);
    cudaGetSymbolAddress((void**)&htvw, gh_tvw);
    cudaGetSymbolAddress((void**)&htow, gh_tow);
    cudaGetSymbolAddress((void**)&hemb, gh_emb);

    cudaEventRecord(ev_root, 0);

    // ---- s1: rope table, ToU weight conversions + tiny GEMMs ----
    cudaStreamWaitEvent(s1, ev_root, 0);
    rope_table_kernel<<<TT*32/256, 256, 0, s1>>>();
    cudaEventRecord(ev_tab, s1);
    F2H(s1, tou_embeds, hemb, NPRIM*DP);
    F2H(s1, tou_k_w, htkw, DP*DP);
    F2H(s1, tou_v_w, htvw, DP*DP);
    F2H(s1, tou_q_w, htqw, DP*DD);
    F2H(s1, tou_o_w, htow, DD*DP);
    gemm_h<true,0,true><<<dim3(DP/128, NPRIM/128, 1), 256, SMEM_HBT, s1>>>(
        hemb, htkw, htk, NPRIM, DP, DP, 0, 0, 0, nullptr, nullptr, nullptr);
    gemm_h<true,0,true><<<dim3(DP/128, NPRIM/128, 1), 256, SMEM_HBT, s1>>>(
        hemb, htvw, htv, NPRIM, DP, DP, 0, 0, 0, nullptr, nullptr, nullptr);
    cudaEventRecord(ev_s1, s1);

    // ---- s2: qkv_w + attn_o conversions, gbuf memset, MoE weight conversions ----
    cudaStreamWaitEvent(s2, ev_root, 0);
    F2H(s2, qkv_w, hqkvw, 3*DD*DD);
    cudaEventRecord(ev_qkvw, s2);
    F2H(s2, attn_o_w, haow, DD*DD);
    cudaEventRecord(ev_aow, s2);
    cudaMemsetAsync(hbuf, 0, (size_t)EE*CAP*DD*sizeof(__half), s2);
    F2H(s2, moe_w1, hw1, EE*DD*FF);
    F2H(s2, moe_w2, hw2, EE*FF*DD);
    cudaEventRecord(ev_s2, s2);

    // ---- Block 1 ----
    rmsnorm_h<<<NTOK, 256>>>(x, norm1_w, hxn, nullptr);
    cudaStreamWaitEvent(0, ev_qkvw, 0);
    gemm_h<true,0,true><<<dim3(3*DD/128, NTOK/128, 1), 256, SMEM_HBT>>>(
        hxn, hqkvw, hqkv, NTOK, 3*DD, DD, 0, 0, 0, nullptr, nullptr, nullptr);
    cudaStreamWaitEvent(0, ev_tab, 0);
    rope_hh<<<NTOK, 256>>>(hqkv);
    flash_attn_h<<<dim3(TT/128, BB*HH), 256, FLASHH_SMEM>>>(hqkv, hattn);
    cudaStreamWaitEvent(0, ev_aow, 0);
    gemm_h<true,4,false><<<dim3(DD/128, NTOK/128, 1), 256, SMEM_HBT>>>(
        hattn, haow, gx, NTOK, DD, DD, 0, 0, 0, nullptr, x, nullptr);   // gx = x + proj

    // ---- Block 2: MoE ----
    rmsnorm_h<<<NTOK, 256>>>(gx, norm2_w, hxn, gxn);
    router_kernel<<<NTOK, 128>>>(gxn, router_w, glogits);
    top2_kernel<<<NTOK/128, 128>>>(glogits, gprobs, gtopi, gtopw);
    cudaEventRecord(ev_top2, 0);
    cudaStreamWaitEvent(s2, ev_top2, 0);
    pmean_kernel<<<EE, 256, 0, s2>>>(gprobs, gpmean);
    assign_kernel<<<EE, 256>>>(gtopi, gtopw, gslot, gkeep, gwcomb, gcounts);
    cudaEventRecord(ev_asn, 0);
    cudaStreamWaitEvent(s2, ev_asn, 0);
    aux_kernel<<<1, 32, 0, s2>>>(gcounts, gpmean, (float*)d_out, out_size);
    cudaStreamWaitEvent(0, ev_s2, 0);
    scatter_kernel<<<NFLAT, 256>>>(gtopi, gslot, gkeep, hxn, hbuf);
    gemm_h<false,2,true><<<dim3(FF/128, CAP/128, EE), 256, SMEM_HKN>>>(
        hbuf, hw1, hh, CAP, FF, DD,
        (long long)CAP*DD, (long long)DD*FF, (long long)CAP*FF, nullptr, nullptr, gcounts);
    gemm_h<false,0,true><<<dim3(DD/128, CAP/128, EE), 256, SMEM_HKN>>>(
        hh, hw2, hyb, CAP, DD, FF,
        (long long)CAP*FF, (long long)FF*DD, (long long)CAP*DD, nullptr, nullptr, gcounts);
    gather_kernel<<<NTOK, 256>>>(gtopi, gslot, gwcomb, hyb, gx);

    // ---- Block 3: ToU cross-attention ----
    rmsnorm_h<<<NTOK, 256>>>(gx, norm3_w, hxn, nullptr);
    cudaEventRecord(ev_n3, 0);
    cudaStreamWaitEvent(s2, ev_n3, 0);
    gate_kernel<<<NTOK, 256, 0, s2>>>(hxn, tou_gate_w, tou_gate_b, ggate);
    cudaEventRecord(ev_gate, s2);
    cudaStreamWaitEvent(0, ev_s1, 0);
    gemm_h<true,0,true><<<dim3(DP/128, NTOK/128, 1), 256, SMEM_HBT>>>(
        hxn, htqw, htq, NTOK, DP, DD, 0, 0, 0, nullptr, nullptr, nullptr);
    gemm_h<true,0,false><<<dim3(NPRIM/128, NTOK/128, 1), 256, SMEM_HBT>>>(
        htq, htk, gtl, NTOK, NPRIM, DP, 0, 0, 0, nullptr, nullptr, nullptr);
    softmax512_kernel<<<NTOK, 256>>>(gtl, htl);
    gemm_h<false,0,true><<<dim3(DP/128, NTOK/128, 1), 256, SMEM_HKN>>>(
        htl, htv, htout, NTOK, DP, NPRIM, 0, 0, 0, nullptr, nullptr, nullptr);
    cudaStreamWaitEvent(0, ev_gate, 0);
    gemm_h<true,5,false><<<dim3(DD/128, NTOK/128, 1), 256, SMEM_HBT>>>(
        htout, htow, (float*)d_out, NTOK, DD, DP, 0, 0, 0, ggate, gx, nullptr);
}

// round 17
// speedup vs baseline: 1.5962x; 1.0203x over previous
#include <cuda_runtime.h>
#include <cuda_bf16.h>
#include <cuda_fp16.h>
#include <math.h>

// ---------------------------------------------------------------------------
// Problem constants
// ---------------------------------------------------------------------------
#define BB 2
#define TT 2048
#define DD 1024
#define HH 16
#define DH 64
#define NTOK (BB*TT)            // 4096
#define EE 16
#define KK 2
#define FF 2048
#define CAP 640
#define DP 256
#define NPRIM 512
#define NFLAT (NTOK*KK)         // 8192

// ---------------------------------------------------------------------------
// Scratch (device globals; no allocation allowed)
// ---------------------------------------------------------------------------
__device__ float g_x[NTOK*DD];
__device__ float g_xn[NTOK*DD];          // fp32 xn (router)
__device__ float g_logits[NTOK*EE];
__device__ float g_probs[NTOK*EE];
__device__ int   g_topi[NFLAT];
__device__ float g_topw[NFLAT];
__device__ int   g_slot[NFLAT];
__device__ int   g_keep[NFLAT];
__device__ float g_wcomb[NFLAT];
__device__ int   g_counts[EE];
__device__ float g_pmean[EE];
__device__ float g_tl[NTOK*NPRIM];
__device__ float g_gate[NTOK];
__device__ float g_ropec[TT*32];
__device__ float g_ropes[TT*32];

// fp16 buffers
__device__ __half gh_qkv[NTOK*3*DD];
__device__ __half gh_xn[NTOK*DD];
__device__ __half gh_attn[NTOK*DD];
__device__ __half gh_buf[EE*CAP*DD];
__device__ __half gh_h[EE*CAP*FF];
__device__ __half gh_yb[EE*CAP*DD];
__device__ __half gh_tq[NTOK*DP];
__device__ __half gh_tk[NPRIM*DP];
__device__ __half gh_tv[NPRIM*DP];
__device__ __half gh_tl[NTOK*NPRIM];
__device__ __half gh_tout[NTOK*DP];
// fp16 weights (converted once per launch)
__device__ __half gh_qkvw[3*DD*DD];
__device__ __half gh_aow[DD*DD];
__device__ __half gh_w1[EE*DD*FF];
__device__ __half gh_w2[EE*FF*DD];
__device__ __half gh_tqw[DP*DD];
__device__ __half gh_tkw[DP*DP];
__device__ __half gh_tvw[DP*DP];
__device__ __half gh_tow[DD*DP];
__device__ __half gh_emb[NPRIM*DP];

// ---------------------------------------------------------------------------
// Streams / events (host resources, created once)
// ---------------------------------------------------------------------------
static cudaStream_t s1, s2;
static cudaEvent_t ev_root, ev_tab, ev_s1, ev_s2, ev_qkvw, ev_aow,
                   ev_top2, ev_asn, ev_n3, ev_gate;
namespace {
struct InitOnce {
    InitOnce() {
        cudaStreamCreateWithFlags(&s1, cudaStreamNonBlocking);
        cudaStreamCreateWithFlags(&s2, cudaStreamNonBlocking);
        cudaEventCreateWithFlags(&ev_root, cudaEventDisableTiming);
        cudaEventCreateWithFlags(&ev_tab,  cudaEventDisableTiming);
        cudaEventCreateWithFlags(&ev_s1,   cudaEventDisableTiming);
        cudaEventCreateWithFlags(&ev_s2,   cudaEventDisableTiming);
        cudaEventCreateWithFlags(&ev_qkvw, cudaEventDisableTiming);
        cudaEventCreateWithFlags(&ev_aow,  cudaEventDisableTiming);
        cudaEventCreateWithFlags(&ev_top2, cudaEventDisableTiming);
        cudaEventCreateWithFlags(&ev_asn,  cudaEventDisableTiming);
        cudaEventCreateWithFlags(&ev_n3,   cudaEventDisableTiming);
        cudaEventCreateWithFlags(&ev_gate, cudaEventDisableTiming);
    }
};
static InitOnce init_once_;
}

// ---------------------------------------------------------------------------
// MMA / cp.async / ldmatrix helpers
// ---------------------------------------------------------------------------
__device__ __forceinline__ void mma_f16(float c[4], const unsigned a[4], const unsigned b[2])
{
    asm volatile(
        "mma.sync.aligned.m16n8k16.row.col.f32.f16.f16.f32 "
        "{%0,%1,%2,%3},{%4,%5,%6,%7},{%8,%9},{%0,%1,%2,%3};"
        : "+f"(c[0]), "+f"(c[1]), "+f"(c[2]), "+f"(c[3])
        : "r"(a[0]), "r"(a[1]), "r"(a[2]), "r"(a[3]),
          "r"(b[0]), "r"(b[1]));
}

__device__ __forceinline__ void ldsm4(unsigned r[4], unsigned addr)
{
    asm volatile("ldmatrix.sync.aligned.m8n8.x4.shared.b16 {%0,%1,%2,%3}, [%4];"
        : "=r"(r[0]), "=r"(r[1]), "=r"(r[2]), "=r"(r[3]) : "r"(addr));
}
__device__ __forceinline__ void ldsm4t(unsigned r[4], unsigned addr)
{
    asm volatile("ldmatrix.sync.aligned.m8n8.x4.trans.shared.b16 {%0,%1,%2,%3}, [%4];"
        : "=r"(r[0]), "=r"(r[1]), "=r"(r[2]), "=r"(r[3]) : "r"(addr));
}

__device__ __forceinline__ void cp16(void* smem_dst, const void* gptr)
{
    unsigned saddr = (unsigned)__cvta_generic_to_shared(smem_dst);
    asm volatile("cp.async.cg.shared.global [%0], [%1], 16;\n"
                 :: "r"(saddr), "l"(gptr));
}
__device__ __forceinline__ void cp_commit()  { asm volatile("cp.async.commit_group;\n"); }
__device__ __forceinline__ void cp_wait2()   { asm volatile("cp.async.wait_group 2;\n"); }
__device__ __forceinline__ void cp_wait1()   { asm volatile("cp.async.wait_group 1;\n"); }
__device__ __forceinline__ void cp_wait0()   { asm volatile("cp.async.wait_group 0;\n"); }

// ---------------------------------------------------------------------------
// f32 -> f16 conversion (n % 2048 == 0)
// ---------------------------------------------------------------------------
__global__ void f2h_kernel(const float* __restrict__ in, __half* __restrict__ out)
{
    int i = (blockIdx.x*256 + threadIdx.x) * 8;
    float4 v0 = *(const float4*)(in + i);
    float4 v1 = *(const float4*)(in + i + 4);
    __half2* o = (__half2*)(out + i);
    o[0] = __floats2half2_rn(v0.x, v0.y);
    o[1] = __floats2half2_rn(v0.z, v0.w);
    o[2] = __floats2half2_rn(v1.x, v1.y);
    o[3] = __floats2half2_rn(v1.z, v1.w);
}

// ---------------------------------------------------------------------------
// RMSNorm: one block per token; fp16 out (+optional fp32 out)
// ---------------------------------------------------------------------------
__global__ void rmsnorm_h(const float* __restrict__ x,
                          const float* __restrict__ w,
                          __half* __restrict__ outh,
                          float* __restrict__ outf)
{
    int n = blockIdx.x;
    int tid = threadIdx.x;
    const float4* xp = (const float4*)(x + (size_t)n*DD);
    float4 xv = xp[tid];
    float ss = xv.x*xv.x + xv.y*xv.y + xv.z*xv.z + xv.w*xv.w;
    __shared__ float red[256];
    red[tid] = ss;
    __syncthreads();
    for (int s = 128; s; s >>= 1) {
        if (tid < s) red[tid] += red[tid+s];
        __syncthreads();
    }
    float scale = rsqrtf(red[0] / (float)DD + 1e-6f);
    const float4* wp = (const float4*)w;
    float4 wv = wp[tid];
    float a = xv.x*scale*wv.x, b = xv.y*scale*wv.y;
    float c = xv.z*scale*wv.z, d = xv.w*scale*wv.w;
    __half2* oh = (__half2*)(outh + (size_t)n*DD);
    oh[2*tid]   = __floats2half2_rn(a, b);
    oh[2*tid+1] = __floats2half2_rn(c, d);
    if (outf) ((float4*)(outf + (size_t)n*DD))[tid] = make_float4(a, b, c, d);
}

// ---------------------------------------------------------------------------
// FP16 tensor-core GEMM (m16n8k16): 4-stage cp.async, ldmatrix fragments.
// MT: M-tile (128 or 64). N-tile fixed 128.
// EPI: 0=store, 2=silu store, 4=C=Xin+v, 5=C=Xin+gate*v;  OUTH: __half out
// cnt: optional per-z row-count (skip row-blocks >= min(cnt, M))
// ---------------------------------------------------------------------------
#define AH_STR 40
#define BH_STR 136
#define NSTG 4
#define BH_TILE (32*BH_STR)

template<int MT, bool BT, int EPI, bool OUTH>
__global__ __launch_bounds__(256, 2)
void gemm_h(const __half* __restrict__ A, const __half* __restrict__ Bm,
            void* __restrict__ Cv, int M, int N, int K,
            long long sA, long long sB, long long sC,
            const float* __restrict__ gate, const float* __restrict__ Xin,
            const int* __restrict__ cnt)
{
    constexpr int A_TILE = MT * AH_STR;        // halfs per A stage
    constexpr int MTW = MT / 32;               // warp m-frag count

    const int row0 = blockIdx.y * MT, col0 = blockIdx.x * 128;
    if (cnt) {
        int c = cnt[blockIdx.z];
        if (c > M) c = M;
        if (row0 >= c) return;
    }

    A  += blockIdx.z * sA;
    Bm += blockIdx.z * sB;

    extern __shared__ __half smem_h[];
    __half* AsP = smem_h;
    __half* BsP = smem_h + NSTG*A_TILE;
    const unsigned sbase = (unsigned)__cvta_generic_to_shared(smem_h);
    const unsigned bbase = sbase + NSTG*A_TILE*2;

    const int tid  = threadIdx.x;
    const int lane = tid & 31;
    const int warp = tid >> 5;
    const int lr   = lane >> 2;
    const int lq   = lane & 3;
    const int g    = lane >> 3;
    const int tr   = lane & 7;
    const int wm   = warp & 1, wn = warp >> 1;
    const int m0   = wm * (MT/2), n0 = wn * 32;

    const int c0i = tid, c1i = tid + 256;
    const int ar0 = c0i >> 2, ac0 = (c0i & 3) * 8;
    const int ar1 = c1i >> 2, ac1 = (c1i & 3) * 8;
    const int fr0 = c0i >> 4, fo0 = (c0i & 15) * 8;
    const int fr1 = c1i >> 4, fo1 = (c1i & 15) * 8;

    const int nIter = K >> 5;

    auto issue = [&](int stg, int k0) {
        cp16(&AsP[stg*A_TILE + ar0*AH_STR + ac0], A + (size_t)(row0 + ar0) * K + k0 + ac0);
        if constexpr (MT == 128)
            cp16(&AsP[stg*A_TILE + ar1*AH_STR + ac1], A + (size_t)(row0 + ar1) * K + k0 + ac1);
        if constexpr (BT) {
            cp16(&BsP[stg*(128*AH_STR) + ar0*AH_STR + ac0], Bm + (size_t)(col0 + ar0) * K + k0 + ac0);
            cp16(&BsP[stg*(128*AH_STR) + ar1*AH_STR + ac1], Bm + (size_t)(col0 + ar1) * K + k0 + ac1);
        } else {
            cp16(&BsP[stg*BH_TILE + fr0*BH_STR + fo0], Bm + (size_t)(k0 + fr0) * N + col0 + fo0);
            cp16(&BsP[stg*BH_TILE + fr1*BH_STR + fo1], Bm + (size_t)(k0 + fr1) * N + col0 + fo1);
        }
        cp_commit();
    };

    issue(0, 0);
    if (nIter > 1) issue(1, 32);
    if (nIter > 2) issue(2, 64);

    float c[MTW][4][4];
    #pragma unroll
    for (int mt = 0; mt < MTW; mt++)
        #pragma unroll
        for (int nt = 0; nt < 4; nt++)
            #pragma unroll
            for (int i = 0; i < 4; i++) c[mt][nt][i] = 0.f;

    const int a_row = (g & 1) * 8 + tr;
    const int a_col = (g >> 1) * 8;
    const int bt_row = (g >> 1) * 8 + tr;
    const int bt_col = (g & 1) * 8;
    const int bf_row = (g & 1) * 8 + tr;
    const int bf_col = (g >> 1) * 8;

    for (int it = 0; it < nIter; it++) {
        if (it + 2 < nIter)      cp_wait2();
        else if (it + 1 < nIter) cp_wait1();
        else                     cp_wait0();
        __syncthreads();

        if (it + 3 < nIter) issue((it + 3) & 3, (it + 3) << 5);

        const int st = it & 3;
        const unsigned abase = sbase + st*A_TILE*2;
        const unsigned btb   = bbase + (BT ? st*(128*AH_STR)*2 : st*BH_TILE*2);

        #pragma unroll
        for (int ks = 0; ks < 2; ks++) {
            const int kb = ks * 16;
            unsigned a[MTW][4];
            #pragma unroll
            for (int mt = 0; mt < MTW; mt++) {
                unsigned addr = abase + ((m0 + mt*16 + a_row)*AH_STR + kb + a_col)*2;
                ldsm4(a[mt], addr);
            }
            unsigned b[4][2];
            #pragma unroll
            for (int ntp = 0; ntp < 2; ntp++) {
                unsigned r[4];
                if constexpr (BT) {
                    unsigned addr = btb + ((n0 + ntp*16 + bt_row)*AH_STR + kb + bt_col)*2;
                    ldsm4(r, addr);
                } else {
                    unsigned addr = btb + ((kb + bf_row)*BH_STR + n0 + ntp*16 + bf_col)*2;
                    ldsm4t(r, addr);
                }
                b[ntp*2][0]   = r[0]; b[ntp*2][1]   = r[1];
                b[ntp*2+1][0] = r[2]; b[ntp*2+1][1] = r[3];
            }
            #pragma unroll
            for (int mt = 0; mt < MTW; mt++)
                #pragma unroll
                for (int nt = 0; nt < 4; nt++)
                    mma_f16(c[mt][nt], a[mt], b[nt]);
        }
    }

    float* Cf = (float*)Cv + (OUTH ? 0 : blockIdx.z * sC);
    __half* Ch = (__half*)Cv + (OUTH ? blockIdx.z * sC : 0);
    #pragma unroll
    for (int mt = 0; mt < MTW; mt++) {
        int r0g = row0 + m0 + mt * 16 + lr;
        int r1g = r0g + 8;
        float g0 = (EPI == 5) ? gate[r0g] : 0.f;
        float g1 = (EPI == 5) ? gate[r1g] : 0.f;
        #pragma unroll
        for (int nt = 0; nt < 4; nt++) {
            int cg = col0 + n0 + nt * 8 + 2 * lq;
            size_t i0 = (size_t)r0g * N + cg;
            size_t i1 = (size_t)r1g * N + cg;
            float v0 = c[mt][nt][0], v1 = c[mt][nt][1];
            float v2 = c[mt][nt][2], v3 = c[mt][nt][3];
            if (EPI == 2) {
                v0 = v0 / (1.f + __expf(-v0));
                v1 = v1 / (1.f + __expf(-v1));
                v2 = v2 / (1.f + __expf(-v2));
                v3 = v3 / (1.f + __expf(-v3));
            } else if (EPI == 4) {
                float2 x0 = *(const float2*)&Xin[i0];
                float2 x1 = *(const float2*)&Xin[i1];
                v0 += x0.x; v1 += x0.y; v2 += x1.x; v3 += x1.y;
            } else if (EPI == 5) {
                float2 x0 = *(const float2*)&Xin[i0];
                float2 x1 = *(const float2*)&Xin[i1];
                v0 = x0.x + g0*v0; v1 = x0.y + g0*v1;
                v2 = x1.x + g1*v2; v3 = x1.y + g1*v3;
            }
            if (OUTH) {
                *(__half2*)&Ch[i0] = __floats2half2_rn(v0, v1);
                *(__half2*)&Ch[i1] = __floats2half2_rn(v2, v3);
            } else {
                *(float2*)&Cf[i0] = make_float2(v0, v1);
                *(float2*)&Cf[i1] = make_float2(v2, v3);
            }
        }
    }
}

#define SMEM_HBT128 ((NSTG*(128*AH_STR) + NSTG*(128*AH_STR)) * 2)
#define SMEM_HBT64  ((NSTG*(64*AH_STR)  + NSTG*(128*AH_STR)) * 2)
#define SMEM_HKN128 ((NSTG*(128*AH_STR) + NSTG*BH_TILE) * 2)
#define SMEM_HKN64  ((NSTG*(64*AH_STR)  + NSTG*BH_TILE) * 2)

// ---------------------------------------------------------------------------
// RoPE table + in-place fp16 apply
// ---------------------------------------------------------------------------
__global__ void rope_table_kernel()
{
    int idx = blockIdx.x * 256 + threadIdx.x;
    int t = idx >> 5, i = idx & 31;
    float inv = powf(10000.f, -(float)i / 32.f);
    float s, c;
    sincosf((float)t * inv, &s, &c);
    g_ropec[idx] = c;
    g_ropes[idx] = s;
}

__global__ void rope_hh(__half* __restrict__ qkvh)
{
    int n = blockIdx.x;
    int t = n & (TT-1);
    for (int p = threadIdx.x; p < 1024; p += 256) {
        int which = p >> 9;
        int rem = p & 511;
        int h = rem >> 5;
        int i = rem & 31;
        float c = g_ropec[t*32 + i];
        float s = g_ropes[t*32 + i];
        size_t base = (size_t)n*3072 + (size_t)which*1024 + h*64 + i;
        float u1 = __half2float(qkvh[base]);
        float u2 = __half2float(qkvh[base+32]);
        qkvh[base]    = __float2half_rn(u1*c - u2*s);
        qkvh[base+32] = __float2half_rn(u2*c + u1*s);
    }
}

// ---------------------------------------------------------------------------
// Flash attention FP16, BK=64 (unchanged from R15)
// ---------------------------------------------------------------------------
#define QH_STR 72
#define KH_STR 72
#define VH_STR 72
#define PH_STR 72
#define KH_TILE (64*KH_STR)
#define QH_OFF 0
#define KH_OFF (128*QH_STR)
#define VH_OFF (KH_OFF + 3*KH_TILE)
#define PH_OFF (VH_OFF + 3*KH_TILE)
#define FLASHH_SMEM ((PH_OFF + 128*PH_STR) * 2)

__global__ __launch_bounds__(256, 2)
void flash_attn_h(const __half* __restrict__ qkv, __half* __restrict__ out)
{
    extern __shared__ __half fsm_h[];
    __half* Qs = fsm_h + QH_OFF;
    __half* Ks = fsm_h + KH_OFF;
    __half* Vs = fsm_h + VH_OFF;
    __half* Ps = fsm_h + PH_OFF;
    const unsigned smem0 = (unsigned)__cvta_generic_to_shared(fsm_h);

    const int qb = blockIdx.x, bh = blockIdx.y;
    const int b = bh >> 4, h = bh & 15;
    const int tid = threadIdx.x, lane = tid & 31, warp = tid >> 5;
    const int lr = lane >> 2, lq = lane & 3;
    const int g = lane >> 3, tr = lane & 7;
    const int m0 = warp * 16;
    const int q0 = qb * 128;
    const int ntiles = 2*qb + 2;

    #pragma unroll
    for (int c = tid; c < 1024; c += 256) {
        int r = c >> 3, off = (c & 7) * 8;
        cp16(&Qs[r*QH_STR + off], qkv + (size_t)(b*TT + q0 + r)*3072 + h*64 + off);
    }

    auto load_tile = [&](int kb, int buf) {
        __half* Kb = Ks + buf*KH_TILE;
        __half* Vb = Vs + buf*KH_TILE;
        #pragma unroll
        for (int c = tid; c < 512; c += 256) {
            int r = c >> 3, off = (c & 7) * 8;
            size_t base = (size_t)(b*TT + kb*64 + r)*3072 + h*64 + off;
            cp16(&Kb[r*KH_STR + off], qkv + base + 1024);
            cp16(&Vb[r*VH_STR + off], qkv + base + 2048);
        }
        cp_commit();
    };

    load_tile(0, 0);
    load_tile(1, 1);

    float mrow0 = -1e30f, mrow1 = -1e30f;
    float lrow0 = 0.f,    lrow1 = 0.f;
    float o[8][4];
    #pragma unroll
    for (int nt = 0; nt < 8; nt++)
        #pragma unroll
        for (int i = 0; i < 4; i++) o[nt][i] = 0.f;

    const int rg0 = q0 + m0 + lr, rg1 = rg0 + 8;

    const int a_row = (g & 1) * 8 + tr;
    const int a_col = (g >> 1) * 8;
    const int bt_row = (g >> 1) * 8 + tr;
    const int bt_col = (g & 1) * 8;
    const int bf_row = (g & 1) * 8 + tr;
    const int bf_col = (g >> 1) * 8;

    for (int kb = 0; kb < ntiles; kb++) {
        if (kb + 1 < ntiles) cp_wait1(); else cp_wait0();
        __syncthreads();
        if (kb + 2 < ntiles) load_tile(kb + 2, (kb + 2) % 3);

        const unsigned kbb = smem0 + (KH_OFF + (kb % 3)*KH_TILE)*2;
        const unsigned vbb = smem0 + (VH_OFF + (kb % 3)*KH_TILE)*2;
        const unsigned qbb = smem0 + QH_OFF*2;
        const unsigned pbb = smem0 + PH_OFF*2;

        float s[8][4];
        #pragma unroll
        for (int nt = 0; nt < 8; nt++)
            #pragma unroll
            for (int i = 0; i < 4; i++) s[nt][i] = 0.f;
        #pragma unroll
        for (int ks = 0; ks < 4; ks++) {
            const int kk = ks * 16;
            unsigned a[4];
            ldsm4(a, qbb + ((m0 + a_row)*QH_STR + kk + a_col)*2);
            #pragma unroll
            for (int kg = 0; kg < 4; kg++) {
                unsigned r[4];
                ldsm4(r, kbb + ((kg*16 + bt_row)*KH_STR + kk + bt_col)*2);
                unsigned b0[2] = { r[0], r[1] };
                unsigned b1[2] = { r[2], r[3] };
                mma_f16(s[kg*2],   a, b0);
                mma_f16(s[kg*2+1], a, b1);
            }
        }

        #pragma unroll
        for (int nt = 0; nt < 8; nt++)
            #pragma unroll
            for (int i = 0; i < 4; i++) s[nt][i] *= 0.125f;
        if (kb*64 + 63 > q0 + m0) {
            #pragma unroll
            for (int nt = 0; nt < 8; nt++) {
                int c0 = kb*64 + nt*8 + 2*lq;
                if (c0   > rg0) s[nt][0] = -1e30f;
                if (c0+1 > rg0) s[nt][1] = -1e30f;
                if (c0   > rg1) s[nt][2] = -1e30f;
                if (c0+1 > rg1) s[nt][3] = -1e30f;
            }
        }

        float mx0 = -1e30f, mx1 = -1e30f;
        #pragma unroll
        for (int nt = 0; nt < 8; nt++) {
            mx0 = fmaxf(mx0, fmaxf(s[nt][0], s[nt][1]));
            mx1 = fmaxf(mx1, fmaxf(s[nt][2], s[nt][3]));
        }
        mx0 = fmaxf(mx0, __shfl_xor_sync(0xffffffffu, mx0, 1));
        mx0 = fmaxf(mx0, __shfl_xor_sync(0xffffffffu, mx0, 2));
        mx1 = fmaxf(mx1, __shfl_xor_sync(0xffffffffu, mx1, 1));
        mx1 = fmaxf(mx1, __shfl_xor_sync(0xffffffffu, mx1, 2));
        float mn0 = fmaxf(mrow0, mx0), mn1 = fmaxf(mrow1, mx1);
        float corr0 = __expf(mrow0 - mn0), corr1 = __expf(mrow1 - mn1);
        float sum0 = 0.f, sum1 = 0.f;
        #pragma unroll
        for (int nt = 0; nt < 8; nt++) {
            s[nt][0] = __expf(s[nt][0] - mn0);
            s[nt][1] = __expf(s[nt][1] - mn0);
            s[nt][2] = __expf(s[nt][2] - mn1);
            s[nt][3] = __expf(s[nt][3] - mn1);
            sum0 += s[nt][0] + s[nt][1];
            sum1 += s[nt][2] + s[nt][3];
        }
        sum0 += __shfl_xor_sync(0xffffffffu, sum0, 1);
        sum0 += __shfl_xor_sync(0xffffffffu, sum0, 2);
        sum1 += __shfl_xor_sync(0xffffffffu, sum1, 1);
        sum1 += __shfl_xor_sync(0xffffffffu, sum1, 2);
        lrow0 = lrow0*corr0 + sum0;
        lrow1 = lrow1*corr1 + sum1;
        mrow0 = mn0; mrow1 = mn1;
        #pragma unroll
        for (int nt = 0; nt < 8; nt++) {
            o[nt][0] *= corr0; o[nt][1] *= corr0;
            o[nt][2] *= corr1; o[nt][3] *= corr1;
        }

        #pragma unroll
        for (int nt = 0; nt < 8; nt++) {
            *(__half2*)&Ps[(m0+lr)*PH_STR + nt*8+2*lq]   = __floats2half2_rn(s[nt][0], s[nt][1]);
            *(__half2*)&Ps[(m0+lr+8)*PH_STR + nt*8+2*lq] = __floats2half2_rn(s[nt][2], s[nt][3]);
        }
        __syncwarp();

        #pragma unroll
        for (int ks = 0; ks < 4; ks++) {
            const int kk = ks * 16;
            unsigned a[4];
            ldsm4(a, pbb + ((m0 + a_row)*PH_STR + kk + a_col)*2);
            #pragma unroll
            for (int ng = 0; ng < 4; ng++) {
                unsigned r[4];
                ldsm4t(r, vbb + ((kk + bf_row)*VH_STR + ng*16 + bf_col)*2);
                unsigned b0[2] = { r[0], r[1] };
                unsigned b1[2] = { r[2], r[3] };
                mma_f16(o[ng*2],   a, b0);
                mma_f16(o[ng*2+1], a, b1);
            }
        }
    }

    float inv0 = 1.f / lrow0, inv1 = 1.f / lrow1;
    #pragma unroll
    for (int nt = 0; nt < 8; nt++) {
        int cg = h*64 + nt*8 + 2*lq;
        size_t base0 = (size_t)(b*TT + rg0)*DD + cg;
        size_t base1 = (size_t)(b*TT + rg1)*DD + cg;
        ((__half2*)out)[base0>>1] = __floats2half2_rn(o[nt][0]*inv0, o[nt][1]*inv0);
        ((__half2*)out)[base1>>1] = __floats2half2_rn(o[nt][2]*inv1, o[nt][3]*inv1);
    }
}

// ---------------------------------------------------------------------------
// Router logits (fp32 xn)
// ---------------------------------------------------------------------------
__global__ void router_kernel(const float* __restrict__ xn,
                              const float* __restrict__ rw,
                              float* __restrict__ logits)
{
    int n = blockIdx.x;
    int warp = threadIdx.x >> 5, lane = threadIdx.x & 31;
    const float* xp = xn + (size_t)n*DD;
    for (int j = 0; j < 4; j++) {
        int e = warp*4 + j;
        const float* wp = rw + (size_t)e*DD;
        float s = 0.f;
        for (int i = lane; i < DD; i += 32) s += xp[i]*wp[i];
        #pragma unroll
        for (int off = 16; off; off >>= 1) s += __shfl_xor_sync(0xffffffffu, s, off);
        if (lane == 0) logits[n*EE + e] = s;
    }
}

__global__ void top2_kernel(const float* __restrict__ logits,
                            float* __restrict__ probs,
                            int* __restrict__ topi, float* __restrict__ topw)
{
    int n = blockIdx.x*blockDim.x + threadIdx.x;
    if (n >= NTOK) return;
    float l[EE];
    float mx = -1e30f;
    #pragma unroll
    for (int e = 0; e < EE; e++) { l[e] = logits[n*EE+e]; mx = fmaxf(mx, l[e]); }
    float sum = 0.f;
    #pragma unroll
    for (int e = 0; e < EE; e++) { l[e] = __expf(l[e]-mx); sum += l[e]; }
    float inv = 1.f/sum;
    #pragma unroll
    for (int e = 0; e < EE; e++) { l[e] *= inv; probs[n*EE+e] = l[e]; }
    int i0 = 0; float p0 = l[0];
    #pragma unroll
    for (int e = 1; e < EE; e++) if (l[e] > p0) { p0 = l[e]; i0 = e; }
    int i1 = (i0 == 0) ? 1 : 0; float p1 = l[i1];
    #pragma unroll
    for (int e = 0; e < EE; e++) if (e != i0 && l[e] > p1) { p1 = l[e]; i1 = e; }
    float ws = p0 + p1;
    topi[n*2]   = i0; topi[n*2+1] = i1;
    topw[n*2]   = p0/ws; topw[n*2+1] = p1/ws;
}

__global__ void pmean_kernel(const float* __restrict__ probs, float* __restrict__ pmean)
{
    int e = blockIdx.x, tid = threadIdx.x;
    float s = 0.f;
    for (int t = tid; t < NTOK; t += 256) s += probs[t*EE + e];
    __shared__ float red[256];
    red[tid] = s;
    __syncthreads();
    for (int k = 128; k; k >>= 1) {
        if (tid < k) red[tid] += red[tid+k];
        __syncthreads();
    }
    if (tid == 0) pmean[e] = red[0] / (float)NTOK;
}

__global__ void assign_kernel(const int* __restrict__ topi,
                              const float* __restrict__ topw,
                              int* __restrict__ slot, int* __restrict__ keep,
                              float* __restrict__ wcomb, int* __restrict__ counts)
{
    int e = blockIdx.x;
    int tid = threadIdx.x;
    int lane = tid & 31, warp = tid >> 5;
    __shared__ int warpsum[8];
    int running = 0;
    for (int base = 0; base < NFLAT; base += 256) {
        int i = base + tid;
        int match = (topi[i] == e) ? 1 : 0;
        unsigned mask = __ballot_sync(0xffffffffu, match);
        if (lane == 0) warpsum[warp] = __popc(mask);
        __syncthreads();
        int wbase = 0, tot = 0;
        #pragma unroll
        for (int w = 0; w < 8; w++) {
            int c = warpsum[w];
            if (w < warp) wbase += c;
            tot += c;
        }
        if (match) {
            int pos = running + wbase + __popc(mask & ((1u << lane) - 1u));
            int kp = (pos < CAP) ? 1 : 0;
            slot[i]  = (pos < CAP-1) ? pos : (CAP-1);
            keep[i]  = kp;
            wcomb[i] = kp ? topw[i] : 0.f;
        }
        running += tot;
        __syncthreads();
    }
    if (tid == 0) counts[e] = running;
}

__global__ void scatter_kernel(const int* __restrict__ topi,
                               const int* __restrict__ slot,
                               const int* __restrict__ keep,
                               const __half* __restrict__ xn,
                               __half* __restrict__ buf)
{
    int i = blockIdx.x;
    if (!keep[i]) return;
    int e = topi[i], s = slot[i], tok = i >> 1;
    const uint2* src = (const uint2*)(xn + (size_t)tok*DD);
    uint2* dst = (uint2*)(buf + ((size_t)e*CAP + s)*DD);
    dst[threadIdx.x] = src[threadIdx.x];
}

__global__ void gather_kernel(const int* __restrict__ topi,
                              const int* __restrict__ slot,
                              const float* __restrict__ wcomb,
                              const __half* __restrict__ yb,
                              float* __restrict__ x)
{
    int n = blockIdx.x;
    int t4 = threadIdx.x;
    float4* xp = (float4*)(x + (size_t)n*DD);
    float4 a = xp[t4];
    #pragma unroll
    for (int k = 0; k < 2; k++) {
        int i = n*2 + k;
        float w = wcomb[i];
        if (w != 0.f) {
            int e = topi[i], s = slot[i];
            const __half2* yp = (const __half2*)(yb + ((size_t)e*CAP + s)*DD);
            float2 y0 = __half22float2(yp[2*t4]);
            float2 y1 = __half22float2(yp[2*t4+1]);
            a.x += w*y0.x; a.y += w*y0.y; a.z += w*y1.x; a.w += w*y1.y;
        }
    }
    xp[t4] = a;
}

__global__ void aux_kernel(const int* __restrict__ counts,
                           const float* __restrict__ pmean,
                           float* __restrict__ out, int out_size)
{
    if (threadIdx.x == 0 && out_size > NTOK*DD) {
        float s = 0.f;
        for (int e = 0; e < EE; e++)
            s += ((float)counts[e] / (float)NTOK) * pmean[e];
        out[NTOK*DD] = (float)EE * s;
    }
}

__global__ void gate_kernel(const __half* __restrict__ xn,
                            const float* __restrict__ gw,
                            const float* __restrict__ gb,
                            float* __restrict__ gate)
{
    int n = blockIdx.x, tid = threadIdx.x;
    const __half2* xp = (const __half2*)(xn + (size_t)n*DD);
    const float4* wp = (const float4*)gw;
    float2 f0 = __half22float2(xp[2*tid]);
    float2 f1 = __half22float2(xp[2*tid+1]);
    float4 wv = wp[tid];
    float s = f0.x*wv.x + f0.y*wv.y + f1.x*wv.z + f1.y*wv.w;
    __shared__ float red[256];
    red[tid] = s;
    __syncthreads();
    for (int k = 128; k; k >>= 1) {
        if (tid < k) red[tid] += red[tid+k];
        __syncthreads();
    }
    if (tid == 0) gate[n] = 1.f / (1.f + __expf(-(red[0] + gb[0])));
}

__global__ void softmax512_kernel(const float* __restrict__ tl, __half* __restrict__ outh)
{
    int n = blockIdx.x, tid = threadIdx.x;
    const float* row = tl + (size_t)n*NPRIM;
    __half* orow = outh + (size_t)n*NPRIM;
    float v0 = row[tid]       * 0.0625f;
    float v1 = row[tid + 256] * 0.0625f;
    __shared__ float red[256];
    red[tid] = fmaxf(v0, v1);
    __syncthreads();
    for (int s = 128; s; s >>= 1) {
        if (tid < s) red[tid] = fmaxf(red[tid], red[tid+s]);
        __syncthreads();
    }
    float mx = red[0];
    __syncthreads();
    v0 = __expf(v0 - mx); v1 = __expf(v1 - mx);
    red[tid] = v0 + v1;
    __syncthreads();
    for (int s = 128; s; s >>= 1) {
        if (tid < s) red[tid] += red[tid+s];
        __syncthreads();
    }
    float inv = 1.f / red[0];
    orow[tid]       = __float2half_rn(v0*inv);
    orow[tid + 256] = __float2half_rn(v1*inv);
}

// ---------------------------------------------------------------------------
// Host launch
// ---------------------------------------------------------------------------
#define F2H(stream, src, dst, n) f2h_kernel<<<(n)/2048, 256, 0, stream>>>(src, dst)

extern "C" void kernel_launch(void* const* d_in, const int* in_sizes, int n_in,
                              void* d_out, int out_size)
{
    const float* x          = (const float*)d_in[0];
    const float* tou_embeds = (const float*)d_in[1];
    const float* norm1_w    = (const float*)d_in[2];
    const float* qkv_w      = (const float*)d_in[3];
    const float* attn_o_w   = (const float*)d_in[4];
    const float* norm2_w    = (const float*)d_in[5];
    const float* router_w   = (const float*)d_in[6];
    const float* moe_w1     = (const float*)d_in[7];
    const float* moe_w2     = (const float*)d_in[8];
    const float* norm3_w    = (const float*)d_in[9];
    const float* tou_q_w    = (const float*)d_in[10];
    const float* tou_k_w    = (const float*)d_in[11];
    const float* tou_v_w    = (const float*)d_in[12];
    const float* tou_o_w    = (const float*)d_in[13];
    const float* tou_gate_w = (const float*)d_in[14];
    const float* tou_gate_b = (const float*)d_in[15];

    cudaFuncSetAttribute(gemm_h<128,true,0,true>,   cudaFuncAttributeMaxDynamicSharedMemorySize, SMEM_HBT128);
    cudaFuncSetAttribute(gemm_h<128,true,4,false>,  cudaFuncAttributeMaxDynamicSharedMemorySize, SMEM_HBT128);
    cudaFuncSetAttribute(gemm_h<128,true,5,false>,  cudaFuncAttributeMaxDynamicSharedMemorySize, SMEM_HBT128);
    cudaFuncSetAttribute(gemm_h<128,false,0,true>,  cudaFuncAttributeMaxDynamicSharedMemorySize, SMEM_HKN128);
    cudaFuncSetAttribute(gemm_h<128,false,2,true>,  cudaFuncAttributeMaxDynamicSharedMemorySize, SMEM_HKN128);
    cudaFuncSetAttribute(gemm_h<64,true,0,true>,    cudaFuncAttributeMaxDynamicSharedMemorySize, SMEM_HBT64);
    cudaFuncSetAttribute(gemm_h<64,true,0,false>,   cudaFuncAttributeMaxDynamicSharedMemorySize, SMEM_HBT64);
    cudaFuncSetAttribute(gemm_h<64,false,0,true>,   cudaFuncAttributeMaxDynamicSharedMemorySize, SMEM_HKN64);
    cudaFuncSetAttribute(flash_attn_h,              cudaFuncAttributeMaxDynamicSharedMemorySize, FLASHH_SMEM);

    float *gx, *gxn, *glogits, *gprobs, *gtopw, *gwcomb, *gpmean, *gtl, *ggate;
    int *gtopi, *gslot, *gkeep, *gcounts;
    __half *hqkv, *hxn, *hattn, *hbuf, *hh, *hyb, *htq, *htk, *htv, *htl, *htout;
    __half *hqkvw, *haow, *hw1, *hw2, *htqw, *htkw, *htvw, *htow, *hemb;
    cudaGetSymbolAddress((void**)&gx, g_x);
    cudaGetSymbolAddress((void**)&gxn, g_xn);
    cudaGetSymbolAddress((void**)&glogits, g_logits);
    cudaGetSymbolAddress((void**)&gprobs, g_probs);
    cudaGetSymbolAddress((void**)&gtopi, g_topi);
    cudaGetSymbolAddress((void**)&gtopw, g_topw);
    cudaGetSymbolAddress((void**)&gslot, g_slot);
    cudaGetSymbolAddress((void**)&gkeep, g_keep);
    cudaGetSymbolAddress((void**)&gwcomb, g_wcomb);
    cudaGetSymbolAddress((void**)&gcounts, g_counts);
    cudaGetSymbolAddress((void**)&gpmean, g_pmean);
    cudaGetSymbolAddress((void**)&gtl, g_tl);
    cudaGetSymbolAddress((void**)&ggate, g_gate);
    cudaGetSymbolAddress((void**)&hqkv, gh_qkv);
    cudaGetSymbolAddress((void**)&hxn, gh_xn);
    cudaGetSymbolAddress((void**)&hattn, gh_attn);
    cudaGetSymbolAddress((void**)&hbuf, gh_buf);
    cudaGetSymbolAddress((void**)&hh, gh_h);
    cudaGetSymbolAddress((void**)&hyb, gh_yb);
    cudaGetSymbolAddress((void**)&htq, gh_tq);
    cudaGetSymbolAddress((void**)&htk, gh_tk);
    cudaGetSymbolAddress((void**)&htv, gh_tv);
    cudaGetSymbolAddress((void**)&htl, gh_tl);
    cudaGetSymbolAddress((void**)&htout, gh_tout);
    cudaGetSymbolAddress((void**)&hqkvw, gh_qkvw);
    cudaGetSymbolAddress((void**)&haow, gh_aow);
    cudaGetSymbolAddress((void**)&hw1, gh_w1);
    cudaGetSymbolAddress((void**)&hw2, gh_w2);
    cudaGetSymbolAddress((void**)&htqw, gh_tqw);
    cudaGetSymbolAddress((void**)&htkw, gh_tkw);
    cudaGetSymbolAddress((void**)&htvw, gh_tvw);
    cudaGetSymbolAddress((void**)&htow, gh_tow);
    cudaGetSymbolAddress((void**)&hemb, gh_emb);

    cudaEventRecord(ev_root, 0);

    // ---- s1: rope table, ToU weight conversions + tiny GEMMs ----
    cudaStreamWaitEvent(s1, ev_root, 0);
    rope_table_kernel<<<TT*32/256, 256, 0, s1>>>();
    cudaEventRecord(ev_tab, s1);
    F2H(s1, tou_embeds, hemb, NPRIM*DP);
    F2H(s1, tou_k_w, htkw, DP*DP);
    F2H(s1, tou_v_w, htvw, DP*DP);
    F2H(s1, tou_q_w, htqw, DP*DD);
    F2H(s1, tou_o_w, htow, DD*DP);
    gemm_h<64,true,0,true><<<dim3(DP/128, NPRIM/64, 1), 256, SMEM_HBT64, s1>>>(
        hemb, htkw, htk, NPRIM, DP, DP, 0, 0, 0, nullptr, nullptr, nullptr);
    gemm_h<64,true,0,true><<<dim3(DP/128, NPRIM/64, 1), 256, SMEM_HBT64, s1>>>(
        hemb, htvw, htv, NPRIM, DP, DP, 0, 0, 0, nullptr, nullptr, nullptr);
    cudaEventRecord(ev_s1, s1);

    // ---- s2: qkv_w + attn_o conversions, gbuf memset, MoE weight conversions ----
    cudaStreamWaitEvent(s2, ev_root, 0);
    F2H(s2, qkv_w, hqkvw, 3*DD*DD);
    cudaEventRecord(ev_qkvw, s2);
    F2H(s2, attn_o_w, haow, DD*DD);
    cudaEventRecord(ev_aow, s2);
    cudaMemsetAsync(hbuf, 0, (size_t)EE*CAP*DD*sizeof(__half), s2);
    F2H(s2, moe_w1, hw1, EE*DD*FF);
    F2H(s2, moe_w2, hw2, EE*FF*DD);
    cudaEventRecord(ev_s2, s2);

    // ---- Block 1 ----
    rmsnorm_h<<<NTOK, 256>>>(x, norm1_w, hxn, nullptr);
    cudaStreamWaitEvent(0, ev_qkvw, 0);
    gemm_h<128,true,0,true><<<dim3(3*DD/128, NTOK/128, 1), 256, SMEM_HBT128>>>(
        hxn, hqkvw, hqkv, NTOK, 3*DD, DD, 0, 0, 0, nullptr, nullptr, nullptr);
    cudaStreamWaitEvent(0, ev_tab, 0);
    rope_hh<<<NTOK, 256>>>(hqkv);
    flash_attn_h<<<dim3(TT/128, BB*HH), 256, FLASHH_SMEM>>>(hqkv, hattn);
    cudaStreamWaitEvent(0, ev_aow, 0);
    gemm_h<128,true,4,false><<<dim3(DD/128, NTOK/128, 1), 256, SMEM_HBT128>>>(
        hattn, haow, gx, NTOK, DD, DD, 0, 0, 0, nullptr, x, nullptr);   // gx = x + proj

    // ---- Block 2: MoE ----
    rmsnorm_h<<<NTOK, 256>>>(gx, norm2_w, hxn, gxn);
    router_kernel<<<NTOK, 128>>>(gxn, router_w, glogits);
    top2_kernel<<<NTOK/128, 128>>>(glogits, gprobs, gtopi, gtopw);
    cudaEventRecord(ev_top2, 0);
    cudaStreamWaitEvent(s2, ev_top2, 0);
    pmean_kernel<<<EE, 256, 0, s2>>>(gprobs, gpmean);
    assign_kernel<<<EE, 256>>>(gtopi, gtopw, gslot, gkeep, gwcomb, gcounts);
    cudaEventRecord(ev_asn, 0);
    cudaStreamWaitEvent(s2, ev_asn, 0);
    aux_kernel<<<1, 32, 0, s2>>>(gcounts, gpmean, (float*)d_out, out_size);
    cudaStreamWaitEvent(0, ev_s2, 0);
    scatter_kernel<<<NFLAT, 256>>>(gtopi, gslot, gkeep, hxn, hbuf);
    gemm_h<128,false,2,true><<<dim3(FF/128, CAP/128, EE), 256, SMEM_HKN128>>>(
        hbuf, hw1, hh, CAP, FF, DD,
        (long long)CAP*DD, (long long)DD*FF, (long long)CAP*FF, nullptr, nullptr, gcounts);
    gemm_h<128,false,0,true><<<dim3(DD/128, CAP/128, EE), 256, SMEM_HKN128>>>(
        hh, hw2, hyb, CAP, DD, FF,
        (long long)CAP*FF, (long long)FF*DD, (long long)CAP*DD, nullptr, nullptr, gcounts);
    gather_kernel<<<NTOK, 256>>>(gtopi, gslot, gwcomb, hyb, gx);

    // ---- Block 3: ToU cross-attention ----
    rmsnorm_h<<<NTOK, 256>>>(gx, norm3_w, hxn, nullptr);
    cudaEventRecord(ev_n3, 0);
    cudaStreamWaitEvent(s2, ev_n3, 0);
    gate_kernel<<<NTOK, 256, 0, s2>>>(hxn, tou_gate_w, tou_gate_b, ggate);
    cudaEventRecord(ev_gate, s2);
    cudaStreamWaitEvent(0, ev_s1, 0);
    gemm_h<64,true,0,true><<<dim3(DP/128, NTOK/64, 1), 256, SMEM_HBT64>>>(
        hxn, htqw, htq, NTOK, DP, DD, 0, 0, 0, nullptr, nullptr, nullptr);
    gemm_h<64,true,0,false><<<dim3(NPRIM/128, NTOK/64, 1), 256, SMEM_HBT64>>>(
        htq, htk, gtl, NTOK, NPRIM, DP, 0, 0, 0, nullptr, nullptr, nullptr);
    softmax512_kernel<<<NTOK, 256>>>(gtl, htl);
    gemm_h<64,false,0,true><<<dim3(DP/128, NTOK/64, 1), 256, SMEM_HKN64>>>(
        htl, htv, htout, NTOK, DP, NPRIM, 0, 0, 0, nullptr, nullptr, nullptr);
    cudaStreamWaitEvent(0, ev_gate, 0);
    gemm_h<128,true,5,false><<<dim3(DD/128, NTOK/128, 1), 256, SMEM_HBT128>>>(
        htout, htow, (float*)d_out, NTOK, DD, DP, 0, 0, 0, ggate, gx, nullptr);
}